// round 11
// baseline (speedup 1.0000x reference)
#include <cuda_runtime.h>
#include <cuda_bf16.h>
#include <cuda_fp16.h>
#include <math.h>
#include <stdint.h>

// Problem dims (fixed)
#define BB 2
#define LL 2048
#define DD 1024
#define SS 16
#define EE 4
#define HH 2048
#define NN (BB*LL)   // 4096

typedef uint32_t u32;

// ---------------- scratch (device globals; no allocation allowed) ----------------
__device__ float g_delta[NN*DD];
__device__ float g_Bm[NN*SS];
__device__ float g_Cm[NN*SS];
__device__ float g_ssm[NN*DD];
__device__ int   g_cnt[EE];
__device__ int   g_list[EE*NN];
__device__ float g_cw[EE*NN];
__device__ int   g_loc[2*NN];            // token -> (e*NN + pos), two entries
__device__ u32   g_Gh[(size_t)EE*NN*HH/2];  // per-expert compact G (fp16 pairs)
__device__ u32   g_Uh[(size_t)EE*NN*HH/2];  // per-expert compact U (fp16 pairs)
__device__ float g_Dn[(size_t)EE*NN*DD]; // per-expert compact down output

// bf16x2 split operands for delta GEMM (packed: low16 = even k, high16 = odd k)
__device__ u32 g_xHi[NN*DD/2],   g_xLo[NN*DD/2];      // x           [NN][512]
__device__ u32 g_WdHi[DD*DD/2],  g_WdLo[DD*DD/2];     // W_delta^T   [D][512]
// fp16 single-precision MoE operands (pair-packed)
__device__ u32 g_sF[NN*DD/2];                         // ssm  (fp16 pairs)
__device__ u32 g_aF[(size_t)EE*NN*HH/2];              // act  (fp16 pairs, per-expert)
__device__ u32 g_WgF[EE*HH*DD/2];                     // Wg^T  [e][H][512]
__device__ u32 g_WuF[EE*HH*DD/2];                     // Wu^T  [e][H][512]
__device__ u32 g_WnF[EE*DD*HH/2];                     // Wd^T  [e][D][1024]

// ---------------- FMA-only transcendentals (no MUFU) ----------------
__device__ __forceinline__ float fexpf(float x) {
    x = fmaxf(x, -87.3f);                      // callers guarantee x <= ~20
    float t = fmaf(x, 1.4426950408889634f, 12582912.f);
    float n = t - 12582912.f;
    float r = fmaf(n, -0.693359375f, x);
    r = fmaf(n, 2.12194440e-4f, r);
    float z = r * r;
    float p =          1.9875691500E-4f;
    p = fmaf(p, r,     1.3981999507E-3f);
    p = fmaf(p, r,     8.3334519073E-3f);
    p = fmaf(p, r,     4.1665795894E-2f);
    p = fmaf(p, r,     1.6666665459E-1f);
    p = fmaf(p, r,     5.0000001201E-1f);
    float res = fmaf(p, z, r) + 1.f;
    int e = (int)n;
    return __int_as_float(__float_as_int(res) + (e << 23));
}

__device__ __forceinline__ float flogf(float u) {   // u >= 1
    int iu = __float_as_int(u);
    int e = ((iu >> 23) & 255) - 127;
    float m = __int_as_float((iu & 0x007FFFFF) | 0x3F800000);
    if (m > 1.41421356f) { m *= 0.5f; e += 1; }
    float f = m - 1.f;
    float z = f * f;
    float p =          7.0376836292E-2f;
    p = fmaf(p, f,    -1.1514610310E-1f);
    p = fmaf(p, f,     1.1676998740E-1f);
    p = fmaf(p, f,    -1.2420140846E-1f);
    p = fmaf(p, f,     1.4249322787E-1f);
    p = fmaf(p, f,    -1.6668057665E-1f);
    p = fmaf(p, f,     2.0000714765E-1f);
    p = fmaf(p, f,    -2.4999993993E-1f);
    p = fmaf(p, f,     3.3333331174E-1f);
    float y = fmaf(z * f, p, -0.5f * z);
    float res = f + y;
    return fmaf((float)e, 0.69314718056f, res);
}

__device__ __forceinline__ float softplusf(float z) {
    if (z > 20.f) return z;
    return flogf(1.f + fexpf(z));
}

// FMA-only reciprocal for d in (1, 2]
__device__ __forceinline__ float frecip12(float d) {
    float r = __int_as_float(0x7EF311C3 - __float_as_int(d));
    r = r * fmaf(-d, r, 2.f);
    r = r * fmaf(-d, r, 2.f);
    r = r * fmaf(-d, r, 2.f);
    return r;
}

__device__ __forceinline__ float fsilu(float g) {   // g * sigmoid(g)
    float e = fexpf(-fabsf(g));
    float r = frecip12(1.f + e);
    float num = (g >= 0.f) ? 1.f : e;
    return g * num * r;
}

__device__ __forceinline__ void split2(float a, float b, u32& hi, u32& lo) {
    __nv_bfloat16 ah = __float2bfloat16(a);
    __nv_bfloat16 bh = __float2bfloat16(b);
    float ra = a - __bfloat162float(ah);
    float rb = b - __bfloat162float(bh);
    __nv_bfloat16 al = __float2bfloat16(ra);
    __nv_bfloat16 bl = __float2bfloat16(rb);
    hi = ((u32)__bfloat16_as_ushort(bh) << 16) | __bfloat16_as_ushort(ah);
    lo = ((u32)__bfloat16_as_ushort(bl) << 16) | __bfloat16_as_ushort(al);
}

__device__ __forceinline__ u32 pack_h2(float a, float b) {
    __half2 h = __floats2half2_rn(a, b);
    return *reinterpret_cast<u32*>(&h);
}

// ---------------- zero counts ----------------
__global__ void zero_counts() {
    if (threadIdx.x < EE) g_cnt[threadIdx.x] = 0;
}

// ---------------- split x (bf16 pairs, row-major) ----------------
__global__ __launch_bounds__(256)
void split_x_kernel(const float* __restrict__ in, u32* __restrict__ oh,
                    u32* __restrict__ ol, int n2) {
    int i = blockIdx.x * blockDim.x + threadIdx.x;
    if (i < n2) {
        float2 v = ((const float2*)in)[i];
        u32 hi, lo; split2(v.x, v.y, hi, lo);
        oh[i] = hi; ol[i] = lo;
    }
}

// ---------------- split + transpose W_delta (bf16 pairs) ----------------
__global__ __launch_bounds__(256)
void split_w_kernel(const float* __restrict__ W, u32* __restrict__ oh,
                    u32* __restrict__ ol, int K, int N) {
    int K2 = K / 2;
    __shared__ u32 th[32][33], tl[32][33];
    int kp0 = blockIdx.x * 32, n0 = blockIdx.y * 32;
    int tx = threadIdx.x, ty = threadIdx.y;
#pragma unroll
    for (int r = 0; r < 4; r++) {
        int kp = kp0 + ty + r * 8;
        int n  = n0 + tx;
        float w0 = W[(size_t)(2 * kp) * N + n];
        float w1 = W[(size_t)(2 * kp + 1) * N + n];
        u32 hi, lo; split2(w0, w1, hi, lo);
        th[ty + r * 8][tx] = hi;
        tl[ty + r * 8][tx] = lo;
    }
    __syncthreads();
#pragma unroll
    for (int r = 0; r < 4; r++) {
        int n  = n0 + ty + r * 8;
        int kp = kp0 + tx;
        oh[(size_t)n * K2 + kp] = th[tx][ty + r * 8];
        ol[(size_t)n * K2 + kp] = tl[tx][ty + r * 8];
    }
}

// ---------------- convert + transpose MoE weight (single fp16 pairs) ----------
__global__ __launch_bounds__(256)
void split_w_h_kernel(const float* __restrict__ W, u32* __restrict__ o,
                      int K, int N) {
    int K2 = K / 2;
    size_t eoffW = (size_t)blockIdx.z * K * N;
    size_t eoffO = (size_t)blockIdx.z * N * K2;
    __shared__ u32 th[32][33];
    int kp0 = blockIdx.x * 32, n0 = blockIdx.y * 32;
    int tx = threadIdx.x, ty = threadIdx.y;
#pragma unroll
    for (int r = 0; r < 4; r++) {
        int kp = kp0 + ty + r * 8;
        int n  = n0 + tx;
        float w0 = W[eoffW + (size_t)(2 * kp) * N + n];
        float w1 = W[eoffW + (size_t)(2 * kp + 1) * N + n];
        th[ty + r * 8][tx] = pack_h2(w0, w1);
    }
    __syncthreads();
#pragma unroll
    for (int r = 0; r < 4; r++) {
        int n  = n0 + ty + r * 8;
        int kp = kp0 + tx;
        o[eoffO + (size_t)n * K2 + kp] = th[tx][ty + r * 8];
    }
}

// ---------------- cp.async helpers ----------------
__device__ __forceinline__ void cp_async16z(void* dst, const void* src, int sz) {
    u32 d = (u32)__cvta_generic_to_shared(dst);
    asm volatile("cp.async.ca.shared.global [%0], [%1], 16, %2;\n"
                 :: "r"(d), "l"(src), "r"(sz) : "memory");
}
__device__ __forceinline__ void cp_commit() {
    asm volatile("cp.async.commit_group;\n" ::: "memory");
}
template<int N> __device__ __forceinline__ void cp_wait() {
    asm volatile("cp.async.wait_group %0;\n" :: "n"(N) : "memory");
}

// ---------------- mma / ldmatrix ----------------
__device__ __forceinline__ void mma_bf16(float* d, const u32* a, const u32* b) {
    asm volatile(
        "mma.sync.aligned.m16n8k16.row.col.f32.bf16.bf16.f32 "
        "{%0,%1,%2,%3}, {%4,%5,%6,%7}, {%8,%9}, {%0,%1,%2,%3};\n"
        : "+f"(d[0]), "+f"(d[1]), "+f"(d[2]), "+f"(d[3])
        : "r"(a[0]), "r"(a[1]), "r"(a[2]), "r"(a[3]), "r"(b[0]), "r"(b[1]));
}
__device__ __forceinline__ void mma_f16(float* d, const u32* a, const u32* b) {
    asm volatile(
        "mma.sync.aligned.m16n8k16.row.col.f32.f16.f16.f32 "
        "{%0,%1,%2,%3}, {%4,%5,%6,%7}, {%8,%9}, {%0,%1,%2,%3};\n"
        : "+f"(d[0]), "+f"(d[1]), "+f"(d[2]), "+f"(d[3])
        : "r"(a[0]), "r"(a[1]), "r"(a[2]), "r"(a[3]), "r"(b[0]), "r"(b[1]));
}
__device__ __forceinline__ void ldsm_x4(u32& r0, u32& r1, u32& r2, u32& r3, u32 addr) {
    asm volatile("ldmatrix.sync.aligned.m8n8.x4.shared.b16 {%0,%1,%2,%3}, [%4];"
                 : "=r"(r0), "=r"(r1), "=r"(r2), "=r"(r3) : "r"(addr));
}

#define BM 128
#define BN 128
#define KP 16            // k-pairs per tile (32 elements)
#define STR 20           // smem row stride in u32 (16 used + 4 pad)
#define ABUF (128*STR)   // 2560 u32 per array per buffer
#define GEMM_SMEM_BYTES  (8*ABUF*4 + BM*4)
#define GEMMH_SMEM_BYTES (4*ABUF*4 + BM*4)

// ---------------- bf16x2 3-pass GEMM (delta projection) ----------
__global__ __launch_bounds__(256, 1)
void gemm_bf(const u32* __restrict__ Ahi, const u32* __restrict__ Alo,
             const u32* __restrict__ Bhi, const u32* __restrict__ Blo,
             float* __restrict__ C1, const float* __restrict__ bias,
             int M, int Ncols, int K)
{
    extern __shared__ u32 sm[];

    int mblk = blockIdx.y;
    int nblk = blockIdx.x;
    int n0 = nblk * BN;
    int K2 = K / 2;
    int tid = threadIdx.x;

    int crow = tid >> 1;
    int cseg = (tid & 1) * 8;
    size_t abase = (size_t)(mblk * BM + crow) * K2 + cseg;
    size_t bbase = (size_t)(n0 + crow) * K2 + cseg;

    int wid = tid >> 5, lane = tid & 31;
    int g = lane >> 2, tig = lane & 3;
    int wm = wid >> 2, wn = wid & 3;

    u32 aoffL = (u32)((wm * 64 + (lane & 15)) * STR + (lane >> 4) * 4);
    u32 boffL = (u32)((wn * 32 + ((lane >> 4) << 3) + (lane & 7)) * STR + ((lane >> 3) & 1) * 4);

    float acc[4][4][4];
#pragma unroll
    for (int i = 0; i < 4; i++)
#pragma unroll
        for (int j = 0; j < 4; j++)
#pragma unroll
            for (int k = 0; k < 4; k++) acc[i][j][k] = 0.f;

    int KT = K2 / KP;
    int buf = 0;
    u32 sdst = crow * STR + cseg;

    {
        u32* s0 = sm;
        cp_async16z(s0 + 0*ABUF + sdst,     Ahi + abase,     16);
        cp_async16z(s0 + 0*ABUF + sdst + 4, Ahi + abase + 4, 16);
        cp_async16z(s0 + 1*ABUF + sdst,     Alo + abase,     16);
        cp_async16z(s0 + 1*ABUF + sdst + 4, Alo + abase + 4, 16);
        cp_async16z(s0 + 2*ABUF + sdst,     Bhi + bbase,     16);
        cp_async16z(s0 + 2*ABUF + sdst + 4, Bhi + bbase + 4, 16);
        cp_async16z(s0 + 3*ABUF + sdst,     Blo + bbase,     16);
        cp_async16z(s0 + 3*ABUF + sdst + 4, Blo + bbase + 4, 16);
        cp_commit();
    }

    for (int kt = 0; kt < KT; kt++) {
        if (kt + 1 < KT) {
            u32* s1 = sm + (buf ^ 1) * 4 * ABUF;
            size_t ao = abase + (size_t)(kt + 1) * KP;
            size_t bo = bbase + (size_t)(kt + 1) * KP;
            cp_async16z(s1 + 0*ABUF + sdst,     Ahi + ao,     16);
            cp_async16z(s1 + 0*ABUF + sdst + 4, Ahi + ao + 4, 16);
            cp_async16z(s1 + 1*ABUF + sdst,     Alo + ao,     16);
            cp_async16z(s1 + 1*ABUF + sdst + 4, Alo + ao + 4, 16);
            cp_async16z(s1 + 2*ABUF + sdst,     Bhi + bo,     16);
            cp_async16z(s1 + 2*ABUF + sdst + 4, Bhi + bo + 4, 16);
            cp_async16z(s1 + 3*ABUF + sdst,     Blo + bo,     16);
            cp_async16z(s1 + 3*ABUF + sdst + 4, Blo + bo + 4, 16);
            cp_commit();
            cp_wait<1>();
        } else {
            cp_wait<0>();
        }
        __syncthreads();

        u32 aAh = (u32)__cvta_generic_to_shared(sm + buf * 4 * ABUF);
        u32 aAl = aAh + ABUF * 4;
        u32 aBh = aAh + 2 * ABUF * 4;
        u32 aBl = aAh + 3 * ABUF * 4;

#pragma unroll
        for (int ks = 0; ks < 2; ks++) {
            int kb = ks * 8;
            u32 ah[4][4], al[4][4];
#pragma unroll
            for (int mt = 0; mt < 4; mt++) {
                u32 off = (aoffL + mt * 16 * STR + kb) * 4;
                ldsm_x4(ah[mt][0], ah[mt][1], ah[mt][2], ah[mt][3], aAh + off);
                ldsm_x4(al[mt][0], al[mt][1], al[mt][2], al[mt][3], aAl + off);
            }
            u32 bh[4][2], bl[4][2];
#pragma unroll
            for (int np = 0; np < 2; np++) {
                u32 off = (boffL + np * 16 * STR + kb) * 4;
                ldsm_x4(bh[2*np][0], bh[2*np][1], bh[2*np+1][0], bh[2*np+1][1], aBh + off);
                ldsm_x4(bl[2*np][0], bl[2*np][1], bl[2*np+1][0], bl[2*np+1][1], aBl + off);
            }
#pragma unroll
            for (int mt = 0; mt < 4; mt++)
#pragma unroll
                for (int nt = 0; nt < 4; nt++) {
                    mma_bf16(acc[mt][nt], ah[mt], bh[nt]);
                    mma_bf16(acc[mt][nt], ah[mt], bl[nt]);
                    mma_bf16(acc[mt][nt], al[mt], bh[nt]);
                }
        }
        __syncthreads();
        buf ^= 1;
    }

#pragma unroll
    for (int mt = 0; mt < 4; mt++) {
#pragma unroll
        for (int half = 0; half < 2; half++) {
            int gr = mblk * BM + wm * 64 + mt * 16 + g + half * 8;
            float* orow = C1 + (size_t)gr * Ncols;
#pragma unroll
            for (int nt = 0; nt < 4; nt++) {
                int col = n0 + wn * 32 + nt * 8 + tig * 2;
                float v0 = softplusf(acc[mt][nt][half*2+0] + bias[col]);
                float v1 = softplusf(acc[mt][nt][half*2+1] + bias[col+1]);
                *(float2*)(orow + col) = make_float2(v0, v1);
            }
        }
    }
}

// ---------------- fp16 single-pass GEMM (MoE up/down), expert-batched ----------
// blockIdx.z = expert.
// MODE 1: A (g_sF) gathered via g_list; nblk<16 -> g_Gh, else g_Uh (fp16 pair stores)
// MODE 2: A compact per-expert rows; C1[(e*NN+gr),:] = acc (float store)
template<int MODE>
__global__ __launch_bounds__(256, 2)
void gemm_hf(const u32* __restrict__ A,
             const u32* __restrict__ B1, const u32* __restrict__ B2,
             float* __restrict__ Cf, u32* __restrict__ Ch1, u32* __restrict__ Ch2,
             int Ncols, int K)
{
    extern __shared__ u32 sm[];
    int* sidx = (int*)(sm + 4 * ABUF);

    int e = blockIdx.z;
    int M = g_cnt[e];
    int mblk = blockIdx.y;
    if (mblk * BM >= M) return;
    int nblk = blockIdx.x;
    int K2 = K / 2;

    const u32* Bp = B1 + (size_t)e * Ncols * K2;
    u32* Chout = Ch1;
    int nb = nblk;
    if (MODE == 1 && nblk >= 16) {
        Bp = B2 + (size_t)e * Ncols * K2;
        Chout = Ch2; nb = nblk - 16;
    }
    int n0 = nb * BN;
    int tid = threadIdx.x;

    if (MODE == 1) {
        const int* rowidx = g_list + (size_t)e * NN;
        for (int i = tid; i < BM; i += 256) {
            int gr = mblk * BM + i;
            sidx[i] = (gr < M) ? rowidx[gr] : -1;
        }
        __syncthreads();
    }

    int crow = tid >> 1;
    int cseg = (tid & 1) * 8;
    int asz;
    size_t abase;
    if (MODE == 1) {
        int s = sidx[crow];
        asz = (s >= 0) ? 16 : 0;
        abase = (size_t)(s >= 0 ? s : 0) * K2 + cseg;
    } else {
        int gr = mblk * BM + crow;
        asz = (gr < M) ? 16 : 0;
        abase = ((size_t)e * NN + (gr < M ? gr : 0)) * K2 + cseg;
    }
    size_t bbase = (size_t)(n0 + crow) * K2 + cseg;

    int wid = tid >> 5, lane = tid & 31;
    int g = lane >> 2, tig = lane & 3;
    int wm = wid >> 2, wn = wid & 3;

    u32 aoffL = (u32)((wm * 64 + (lane & 15)) * STR + (lane >> 4) * 4);
    u32 boffL = (u32)((wn * 32 + ((lane >> 4) << 3) + (lane & 7)) * STR + ((lane >> 3) & 1) * 4);

    float acc[4][4][4];
#pragma unroll
    for (int i = 0; i < 4; i++)
#pragma unroll
        for (int j = 0; j < 4; j++)
#pragma unroll
            for (int k = 0; k < 4; k++) acc[i][j][k] = 0.f;

    int KT = K2 / KP;
    int buf = 0;
    u32 sdst = crow * STR + cseg;

    {
        u32* s0 = sm;
        cp_async16z(s0 + 0*ABUF + sdst,     A + abase,      asz);
        cp_async16z(s0 + 0*ABUF + sdst + 4, A + abase + 4,  asz);
        cp_async16z(s0 + 1*ABUF + sdst,     Bp + bbase,     16);
        cp_async16z(s0 + 1*ABUF + sdst + 4, Bp + bbase + 4, 16);
        cp_commit();
    }

    for (int kt = 0; kt < KT; kt++) {
        if (kt + 1 < KT) {
            u32* s1 = sm + (buf ^ 1) * 2 * ABUF;
            size_t ao = abase + (size_t)(kt + 1) * KP;
            size_t bo = bbase + (size_t)(kt + 1) * KP;
            cp_async16z(s1 + 0*ABUF + sdst,     A + ao,      asz);
            cp_async16z(s1 + 0*ABUF + sdst + 4, A + ao + 4,  asz);
            cp_async16z(s1 + 1*ABUF + sdst,     Bp + bo,     16);
            cp_async16z(s1 + 1*ABUF + sdst + 4, Bp + bo + 4, 16);
            cp_commit();
            cp_wait<1>();
        } else {
            cp_wait<0>();
        }
        __syncthreads();

        u32 aA = (u32)__cvta_generic_to_shared(sm + buf * 2 * ABUF);
        u32 aB = aA + ABUF * 4;

#pragma unroll
        for (int ks = 0; ks < 2; ks++) {
            int kb = ks * 8;
            u32 ah[4][4];
#pragma unroll
            for (int mt = 0; mt < 4; mt++) {
                u32 off = (aoffL + mt * 16 * STR + kb) * 4;
                ldsm_x4(ah[mt][0], ah[mt][1], ah[mt][2], ah[mt][3], aA + off);
            }
            u32 bh[4][2];
#pragma unroll
            for (int np = 0; np < 2; np++) {
                u32 off = (boffL + np * 16 * STR + kb) * 4;
                ldsm_x4(bh[2*np][0], bh[2*np][1], bh[2*np+1][0], bh[2*np+1][1], aB + off);
            }
#pragma unroll
            for (int mt = 0; mt < 4; mt++)
#pragma unroll
                for (int nt = 0; nt < 4; nt++)
                    mma_f16(acc[mt][nt], ah[mt], bh[nt]);
        }
        __syncthreads();
        buf ^= 1;
    }

#pragma unroll
    for (int mt = 0; mt < 4; mt++) {
#pragma unroll
        for (int half = 0; half < 2; half++) {
            int lr = wm * 64 + mt * 16 + g + half * 8;
            int gr = mblk * BM + lr;
            if (gr >= M) continue;
            if (MODE == 1) {
                u32* orow = Chout + ((size_t)e * NN + gr) * (Ncols / 2);
#pragma unroll
                for (int nt = 0; nt < 4; nt++) {
                    int col = n0 + wn * 32 + nt * 8 + tig * 2;
                    orow[col >> 1] = pack_h2(acc[mt][nt][half*2+0], acc[mt][nt][half*2+1]);
                }
            } else {
                float* orow = Cf + ((size_t)e * NN + gr) * Ncols;
#pragma unroll
                for (int nt = 0; nt < 4; nt++) {
                    int col = n0 + wn * 32 + nt * 8 + tig * 2;
                    *(float2*)(orow + col) =
                        make_float2(acc[mt][nt][half*2+0], acc[mt][nt][half*2+1]);
                }
            }
        }
    }
}

// ---------------- small projections: Bm, Cm (from x) ----------------
__global__ __launch_bounds__(128)
void proj_small(const float* __restrict__ x, const float* __restrict__ WB,
                const float* __restrict__ WC)
{
    int n = blockIdx.x;
    __shared__ float xs[DD];
    const float* xr = x + (size_t)n * DD;
    for (int i = threadIdx.x; i < DD; i += 128) xs[i] = xr[i];
    __syncthreads();
    int warp = threadIdx.x >> 5, lane = threadIdx.x & 31;
    for (int c = warp; c < 32; c += 4) {
        const float* W; int col; float* out;
        if (c < 16) { W = WB; col = c;      out = g_Bm + (size_t)n * SS + col; }
        else        { W = WC; col = c - 16; out = g_Cm + (size_t)n * SS + col; }
        float s = 0.f;
        for (int k = lane; k < DD; k += 32)
            s = fmaf(xs[k], W[(size_t)k * SS + col], s);
        s += __shfl_xor_sync(~0u, s, 16);
        s += __shfl_xor_sync(~0u, s, 8);
        s += __shfl_xor_sync(~0u, s, 4);
        s += __shfl_xor_sync(~0u, s, 2);
        s += __shfl_xor_sync(~0u, s, 1);
        if (lane == 0) *out = s;
    }
}

// ---------------- selective scan (FMA-only exp) -------------
__global__ __launch_bounds__(256)
void scan_kernel(const float* __restrict__ x, const float* __restrict__ A_log,
                 const float* __restrict__ D_param)
{
    int b = blockIdx.x >> 6;
    int dchunk = blockIdx.x & 63;
    int dl = threadIdx.x >> 4;      // d-local 0..15
    int s  = threadIdx.x & 15;      // state index
    int d = dchunk * 16 + dl;

    float A_ds = -__expf(A_log[d * SS + s]);

    __shared__ float sx[16][16], sd[16][16];
    __shared__ float sB[16][17], sC[16][17];
    __shared__ float sp[16 * 272];  // [q][s*17 + dl]
    __shared__ float sDp[16];

    int tt = threadIdx.x >> 4;
    int cc = threadIdx.x & 15;
    const int base_bt = b * LL;

    if (threadIdx.x < 16) sDp[threadIdx.x] = D_param[dchunk * 16 + threadIdx.x];

    size_t xoff = ((size_t)(base_bt + tt)) * DD + dchunk * 16 + cc;
    float rx = x[xoff];
    float rd = g_delta[xoff];
    size_t boff = ((size_t)(base_bt + tt)) * SS + cc;
    float rB = g_Bm[boff];
    float rC = g_Cm[boff];

    float h = 0.f;
    for (int t0 = 0; t0 < LL; t0 += 16) {
        __syncthreads();
        sx[tt][cc] = rx; sd[tt][cc] = rd; sB[tt][cc] = rB; sC[tt][cc] = rC;
        __syncthreads();
        if (t0 + 16 < LL) {
            size_t xo = ((size_t)(base_bt + t0 + 16 + tt)) * DD + dchunk * 16 + cc;
            rx = x[xo]; rd = g_delta[xo];
            size_t bo = ((size_t)(base_bt + t0 + 16 + tt)) * SS + cc;
            rB = g_Bm[bo]; rC = g_Cm[bo];
        }
        float p[16];
#pragma unroll
        for (int q = 0; q < 16; q++) {
            float xv = sx[q][dl], dv = sd[q][dl];
            float Bv = sB[q][s],  Cv = sC[q][s];
            float a  = fexpf(fminf(dv * A_ds, 10.f));
            float bBc = fminf(fmaxf(dv * Bv, -10.f), 10.f);
            h = fminf(fmaxf(fmaf(a, h, bBc * xv), -10000.f), 10000.f);
            p[q] = h * Cv;
        }
#pragma unroll
        for (int q = 0; q < 16; q++)
            sp[q * 272 + s * 17 + dl] = p[q];
        __syncthreads();
        // reduction role: (q2 = tt, d2 = cc)
        float ysum = 0.f;
#pragma unroll
        for (int s2 = 0; s2 < 16; s2++)
            ysum += sp[tt * 272 + s2 * 17 + cc];
        float y = fmaf(sx[tt][cc], sDp[cc], ysum);
        size_t yo = ((size_t)(base_bt + t0 + tt)) * DD + dchunk * 16 + cc;
        g_ssm[yo] = y;
        float yn = __shfl_down_sync(~0u, y, 1);
        if (!(cc & 1)) {
            float ya = fminf(fmaxf(y,  -60000.f), 60000.f);
            float yb = fminf(fmaxf(yn, -60000.f), 60000.f);
            size_t po = ((size_t)(base_bt + t0 + tt)) * (DD/2) + dchunk * 8 + (cc >> 1);
            g_sF[po] = pack_h2(ya, yb);
        }
    }
}

// ---------------- router on SSM output: softmax, top-2, expert lists ----------
__global__ __launch_bounds__(128)
void router_kernel(const float* __restrict__ WR)
{
    int n = blockIdx.x;
    __shared__ float xs[DD];
    __shared__ float logits[EE];
    const float* xr = g_ssm + (size_t)n * DD;
    for (int i = threadIdx.x; i < DD; i += 128) xs[i] = xr[i];
    __syncthreads();
    int warp = threadIdx.x >> 5, lane = threadIdx.x & 31;
    {
        float s = 0.f;
        for (int k = lane; k < DD; k += 32)
            s = fmaf(xs[k], WR[(size_t)k * EE + warp], s);
        s += __shfl_xor_sync(~0u, s, 16);
        s += __shfl_xor_sync(~0u, s, 8);
        s += __shfl_xor_sync(~0u, s, 4);
        s += __shfl_xor_sync(~0u, s, 2);
        s += __shfl_xor_sync(~0u, s, 1);
        if (lane == 0) logits[warp] = s;
    }
    __syncthreads();
    if (threadIdx.x == 0) {
        float l[4] = {logits[0], logits[1], logits[2], logits[3]};
        float m = fmaxf(fmaxf(l[0], l[1]), fmaxf(l[2], l[3]));
        float e[4], sum = 0.f;
#pragma unroll
        for (int i = 0; i < 4; i++) { e[i] = __expf(l[i] - m); sum += e[i]; }
        float p[4];
#pragma unroll
        for (int i = 0; i < 4; i++) p[i] = e[i] / sum;
        int i0 = 0;
#pragma unroll
        for (int i = 1; i < 4; i++) if (p[i] > p[i0]) i0 = i;
        int i1 = -1;
#pragma unroll
        for (int i = 0; i < 4; i++) {
            if (i == i0) continue;
            if (i1 < 0 || p[i] > p[i1]) i1 = i;
        }
        float w0 = p[i0], w1 = p[i1];
        float sw = w0 + w1 + 1e-9f;
        w0 /= sw; w1 /= sw;
        int pos = atomicAdd(&g_cnt[i0], 1);
        g_list[i0*NN + pos] = n; g_cw[i0*NN + pos] = w0;
        g_loc[n] = i0 * NN + pos;
        pos = atomicAdd(&g_cnt[i1], 1);
        g_list[i1*NN + pos] = n; g_cw[i1*NN + pos] = w1;
        g_loc[NN + n] = i1 * NN + pos;
    }
}

// ---------------- silu(G)*U -> rmsnorm(wn) -> * cw (FMA-only, fp16 I/O) -------
__global__ __launch_bounds__(256)
void act_norm(const float* __restrict__ wn_all)
{
    int i = blockIdx.x;
    int e = blockIdx.y;
    if (i >= g_cnt[e]) return;
    size_t row = (size_t)e * NN + i;
    const float* wn = wn_all + (size_t)e * HH;
    __shared__ float buf[HH];
    __shared__ float red[8];
    float ss = 0.f;
    for (int j2 = threadIdx.x; j2 < HH / 2; j2 += 256) {
        float2 gg = __half22float2(*(const __half2*)&g_Gh[row * (HH/2) + j2]);
        float2 uu = __half22float2(*(const __half2*)&g_Uh[row * (HH/2) + j2]);
        float v0 = fsilu(gg.x) * uu.x;
        float v1 = fsilu(gg.y) * uu.y;
        buf[2*j2]   = v0;
        buf[2*j2+1] = v1;
        ss = fmaf(v0, v0, fmaf(v1, v1, ss));
    }
    ss += __shfl_xor_sync(~0u, ss, 16);
    ss += __shfl_xor_sync(~0u, ss, 8);
    ss += __shfl_xor_sync(~0u, ss, 4);
    ss += __shfl_xor_sync(~0u, ss, 2);
    ss += __shfl_xor_sync(~0u, ss, 1);
    if ((threadIdx.x & 31) == 0) red[threadIdx.x >> 5] = ss;
    __syncthreads();
    if (threadIdx.x < 32) {
        float v = (threadIdx.x < 8) ? red[threadIdx.x] : 0.f;
        v += __shfl_xor_sync(~0u, v, 4);
        v += __shfl_xor_sync(~0u, v, 2);
        v += __shfl_xor_sync(~0u, v, 1);
        if (threadIdx.x == 0) red[0] = v;
    }
    __syncthreads();
    float scale = g_cw[(size_t)e * NN + i] * rsqrtf(red[0] / (float)HH + 1e-6f);
    for (int j2 = threadIdx.x; j2 < HH / 2; j2 += 256) {
        float v0 = wn[2 * j2]     * buf[2 * j2]     * scale;
        float v1 = wn[2 * j2 + 1] * buf[2 * j2 + 1] * scale;
        g_aF[row * (HH/2) + j2] = pack_h2(v0, v1);
    }
}

// ---------------- final rmsnorm over (ssm + Dn[loc0] + Dn[loc1]) --------------
__global__ __launch_bounds__(256)
void final_norm(const float* __restrict__ norm_w, float* __restrict__ out)
{
    int n = blockIdx.x;
    __shared__ float red[8];
    __shared__ float buf[DD];
    int l0 = g_loc[n], l1 = g_loc[NN + n];
    const float* r0 = g_Dn + (size_t)l0 * DD;
    const float* r1 = g_Dn + (size_t)l1 * DD;
    const float* rs = g_ssm + (size_t)n * DD;
    float ss = 0.f;
    for (int j = threadIdx.x; j < DD; j += 256) {
        float v = rs[j] + r0[j] + r1[j];
        buf[j] = v;
        ss = fmaf(v, v, ss);
    }
    ss += __shfl_xor_sync(~0u, ss, 16);
    ss += __shfl_xor_sync(~0u, ss, 8);
    ss += __shfl_xor_sync(~0u, ss, 4);
    ss += __shfl_xor_sync(~0u, ss, 2);
    ss += __shfl_xor_sync(~0u, ss, 1);
    if ((threadIdx.x & 31) == 0) red[threadIdx.x >> 5] = ss;
    __syncthreads();
    if (threadIdx.x < 32) {
        float v = (threadIdx.x < 8) ? red[threadIdx.x] : 0.f;
        v += __shfl_xor_sync(~0u, v, 4);
        v += __shfl_xor_sync(~0u, v, 2);
        v += __shfl_xor_sync(~0u, v, 1);
        if (threadIdx.x == 0) red[0] = v;
    }
    __syncthreads();
    float inv = rsqrtf(red[0] / (float)DD + 1e-6f);
    for (int j = threadIdx.x; j < DD; j += 256)
        out[(size_t)n * DD + j] = norm_w[j] * buf[j] * inv;
}

// ---------------- launch ----------------
extern "C" void kernel_launch(void* const* d_in, const int* in_sizes, int n_in,
                              void* d_out, int out_size)
{
    const float* x        = (const float*)d_in[0];
    const float* A_log    = (const float*)d_in[1];
    const float* D_param  = (const float*)d_in[2];
    const float* W_delta  = (const float*)d_in[3];
    const float* b_delta  = (const float*)d_in[4];
    const float* W_B      = (const float*)d_in[5];
    const float* W_C      = (const float*)d_in[6];
    const float* W_router = (const float*)d_in[7];
    const float* Wg       = (const float*)d_in[8];
    const float* Wu       = (const float*)d_in[9];
    const float* Wd       = (const float*)d_in[10];
    const float* wn_exp   = (const float*)d_in[11];
    const float* norm_w   = (const float*)d_in[12];
    float* out = (float*)d_out;

    float *p_delta, *p_Dn;
    u32 *p_xHi, *p_xLo, *p_sF, *p_aF, *p_Gh, *p_Uh;
    u32 *p_WdHi, *p_WdLo, *p_WgF, *p_WuF, *p_WnF;
    cudaGetSymbolAddress((void**)&p_delta, g_delta);
    cudaGetSymbolAddress((void**)&p_Gh,    g_Gh);
    cudaGetSymbolAddress((void**)&p_Uh,    g_Uh);
    cudaGetSymbolAddress((void**)&p_Dn,    g_Dn);
    cudaGetSymbolAddress((void**)&p_xHi,   g_xHi);
    cudaGetSymbolAddress((void**)&p_xLo,   g_xLo);
    cudaGetSymbolAddress((void**)&p_sF,    g_sF);
    cudaGetSymbolAddress((void**)&p_aF,    g_aF);
    cudaGetSymbolAddress((void**)&p_WdHi,  g_WdHi);
    cudaGetSymbolAddress((void**)&p_WdLo,  g_WdLo);
    cudaGetSymbolAddress((void**)&p_WgF,   g_WgF);
    cudaGetSymbolAddress((void**)&p_WuF,   g_WuF);
    cudaGetSymbolAddress((void**)&p_WnF,   g_WnF);

    cudaFuncSetAttribute(gemm_bf,    cudaFuncAttributeMaxDynamicSharedMemorySize, GEMM_SMEM_BYTES);
    cudaFuncSetAttribute(gemm_hf<1>, cudaFuncAttributeMaxDynamicSharedMemorySize, GEMMH_SMEM_BYTES);
    cudaFuncSetAttribute(gemm_hf<2>, cudaFuncAttributeMaxDynamicSharedMemorySize, GEMMH_SMEM_BYTES);

    zero_counts<<<1, 32>>>();

    // operand pre-conversion
    {
        int n2 = NN * DD / 2;
        split_x_kernel<<<(n2 + 255) / 256, 256>>>(x, p_xHi, p_xLo, n2);
    }
    {
        dim3 blk(32, 8);
        dim3 gWdel(DD/2/32, DD/32, 1);
        split_w_kernel<<<gWdel, blk>>>(W_delta, p_WdHi, p_WdLo, DD, DD);
        dim3 gUp(DD/2/32, HH/32, EE);
        split_w_h_kernel<<<gUp, blk>>>(Wg, p_WgF, DD, HH);
        split_w_h_kernel<<<gUp, blk>>>(Wu, p_WuF, DD, HH);
        dim3 gDn(HH/2/32, DD/32, EE);
        split_w_h_kernel<<<gDn, blk>>>(Wd, p_WnF, HH, DD);
    }

    // delta = softplus(x @ W_delta + b)   [bf16x2 3-pass]
    {
        dim3 grid(DD / BN, NN / BM);
        gemm_bf<<<grid, 256, GEMM_SMEM_BYTES>>>(
            p_xHi, p_xLo, p_WdHi, p_WdLo, p_delta, b_delta, NN, DD, DD);
    }

    // Bm, Cm from x
    proj_small<<<NN, 128>>>(x, W_B, W_C);

    // selective scan -> g_ssm / fp16 ssm
    scan_kernel<<<BB * (DD / 16), 256>>>(x, A_log, D_param);

    // router on SSM output
    router_kernel<<<NN, 128>>>(W_router);

    // MoE, all experts batched:
    // G/U = gather(ssm) @ {Wg,Wu}   [fp16 single-pass, z = expert, fp16 out]
    gemm_hf<1><<<dim3(2 * HH / BN, NN / BM, EE), 256, GEMMH_SMEM_BYTES>>>(
        p_sF, p_WgF, p_WuF, nullptr, p_Gh, p_Uh, HH, DD);
    // act = wn * rmsnorm(silu(G)*U) * cw  (fp16 output)
    act_norm<<<dim3(NN, EE), 256>>>(wn_exp);
    // Dn[e][i] = act @ Wd_e   [fp16 single-pass, compact store]
    gemm_hf<2><<<dim3(DD / BN, NN / BM, EE), 256, GEMMH_SMEM_BYTES>>>(
        p_aF, p_WnF, nullptr, p_Dn, nullptr, nullptr, DD, HH);

    // out = rmsnorm(ssm + Dn[loc0] + Dn[loc1], norm_w)
    final_norm<<<NN, 256>>>(norm_w, out);
}

// round 12
// speedup vs baseline: 1.0547x; 1.0547x over previous
#include <cuda_runtime.h>
#include <cuda_bf16.h>
#include <cuda_fp16.h>
#include <math.h>
#include <stdint.h>

// Problem dims (fixed)
#define BB 2
#define LL 2048
#define DD 1024
#define SS 16
#define EE 4
#define HH 2048
#define NN (BB*LL)   // 4096

typedef uint32_t u32;

// ---------------- scratch (device globals; no allocation allowed) ----------------
__device__ float g_delta[NN*DD];
__device__ float g_Bm[NN*SS];
__device__ float g_Cm[NN*SS];
__device__ float g_ssm[NN*DD];
__device__ int   g_cnt[EE];
__device__ int   g_list[EE*NN];
__device__ float g_cw[EE*NN];
__device__ int   g_loc[2*NN];            // token -> (e*NN + pos), two entries
__device__ u32   g_Gh[(size_t)EE*NN*HH/2];  // per-expert compact G (fp16 pairs)
__device__ u32   g_Uh[(size_t)EE*NN*HH/2];  // per-expert compact U (fp16 pairs)
__device__ float g_Dn[(size_t)EE*NN*DD]; // per-expert compact down output

// bf16x2 split operands for delta GEMM (packed: low16 = even k, high16 = odd k)
__device__ u32 g_xHi[NN*DD/2],   g_xLo[NN*DD/2];      // x           [NN][512]
__device__ u32 g_WdHi[DD*DD/2],  g_WdLo[DD*DD/2];     // W_delta^T   [D][512]
// fp16 single-precision MoE operands (pair-packed)
__device__ u32 g_sF[NN*DD/2];                         // ssm  (fp16 pairs)
__device__ u32 g_aF[(size_t)EE*NN*HH/2];              // act  (fp16 pairs, per-expert)
__device__ u32 g_WgF[EE*HH*DD/2];                     // Wg^T  [e][H][512]
__device__ u32 g_WuF[EE*HH*DD/2];                     // Wu^T  [e][H][512]
__device__ u32 g_WnF[EE*DD*HH/2];                     // Wd^T  [e][D][1024]

// ---------------- FMA-only helpers (throughput-bound sites only) ----------------
__device__ __forceinline__ float fexpf(float x) {
    x = fmaxf(x, -87.3f);
    float t = fmaf(x, 1.4426950408889634f, 12582912.f);
    float n = t - 12582912.f;
    float r = fmaf(n, -0.693359375f, x);
    r = fmaf(n, 2.12194440e-4f, r);
    float z = r * r;
    float p =          1.9875691500E-4f;
    p = fmaf(p, r,     1.3981999507E-3f);
    p = fmaf(p, r,     8.3334519073E-3f);
    p = fmaf(p, r,     4.1665795894E-2f);
    p = fmaf(p, r,     1.6666665459E-1f);
    p = fmaf(p, r,     5.0000001201E-1f);
    float res = fmaf(p, z, r) + 1.f;
    int e = (int)n;
    return __int_as_float(__float_as_int(res) + (e << 23));
}

__device__ __forceinline__ float flogf(float u) {   // u >= 1
    int iu = __float_as_int(u);
    int e = ((iu >> 23) & 255) - 127;
    float m = __int_as_float((iu & 0x007FFFFF) | 0x3F800000);
    if (m > 1.41421356f) { m *= 0.5f; e += 1; }
    float f = m - 1.f;
    float z = f * f;
    float p =          7.0376836292E-2f;
    p = fmaf(p, f,    -1.1514610310E-1f);
    p = fmaf(p, f,     1.1676998740E-1f);
    p = fmaf(p, f,    -1.2420140846E-1f);
    p = fmaf(p, f,     1.4249322787E-1f);
    p = fmaf(p, f,    -1.6668057665E-1f);
    p = fmaf(p, f,     2.0000714765E-1f);
    p = fmaf(p, f,    -2.4999993993E-1f);
    p = fmaf(p, f,     3.3333331174E-1f);
    float y = fmaf(z * f, p, -0.5f * z);
    float res = f + y;
    return fmaf((float)e, 0.69314718056f, res);
}

__device__ __forceinline__ float softplusf(float z) {
    if (z > 20.f) return z;
    return flogf(1.f + fexpf(z));
}

__device__ __forceinline__ float frecip12(float d) {  // d in (1, 2]
    float r = __int_as_float(0x7EF311C3 - __float_as_int(d));
    r = r * fmaf(-d, r, 2.f);
    r = r * fmaf(-d, r, 2.f);
    r = r * fmaf(-d, r, 2.f);
    return r;
}

__device__ __forceinline__ float fsilu(float g) {   // g * sigmoid(g)
    float e = fexpf(-fabsf(g));
    float r = frecip12(1.f + e);
    float num = (g >= 0.f) ? 1.f : e;
    return g * num * r;
}

__device__ __forceinline__ void split2(float a, float b, u32& hi, u32& lo) {
    __nv_bfloat16 ah = __float2bfloat16(a);
    __nv_bfloat16 bh = __float2bfloat16(b);
    float ra = a - __bfloat162float(ah);
    float rb = b - __bfloat162float(bh);
    __nv_bfloat16 al = __float2bfloat16(ra);
    __nv_bfloat16 bl = __float2bfloat16(rb);
    hi = ((u32)__bfloat16_as_ushort(bh) << 16) | __bfloat16_as_ushort(ah);
    lo = ((u32)__bfloat16_as_ushort(bl) << 16) | __bfloat16_as_ushort(al);
}

__device__ __forceinline__ u32 pack_h2(float a, float b) {
    __half2 h = __floats2half2_rn(a, b);
    return *reinterpret_cast<u32*>(&h);
}

// ---------------- zero counts ----------------
__global__ void zero_counts() {
    if (threadIdx.x < EE) g_cnt[threadIdx.x] = 0;
}

// ---------------- split x (bf16 pairs, row-major) ----------------
__global__ __launch_bounds__(256)
void split_x_kernel(const float* __restrict__ in, u32* __restrict__ oh,
                    u32* __restrict__ ol, int n2) {
    int i = blockIdx.x * blockDim.x + threadIdx.x;
    if (i < n2) {
        float2 v = ((const float2*)in)[i];
        u32 hi, lo; split2(v.x, v.y, hi, lo);
        oh[i] = hi; ol[i] = lo;
    }
}

// ---------------- split + transpose W_delta (bf16 pairs) ----------------
__global__ __launch_bounds__(256)
void split_w_kernel(const float* __restrict__ W, u32* __restrict__ oh,
                    u32* __restrict__ ol, int K, int N) {
    int K2 = K / 2;
    __shared__ u32 th[32][33], tl[32][33];
    int kp0 = blockIdx.x * 32, n0 = blockIdx.y * 32;
    int tx = threadIdx.x, ty = threadIdx.y;
#pragma unroll
    for (int r = 0; r < 4; r++) {
        int kp = kp0 + ty + r * 8;
        int n  = n0 + tx;
        float w0 = W[(size_t)(2 * kp) * N + n];
        float w1 = W[(size_t)(2 * kp + 1) * N + n];
        u32 hi, lo; split2(w0, w1, hi, lo);
        th[ty + r * 8][tx] = hi;
        tl[ty + r * 8][tx] = lo;
    }
    __syncthreads();
#pragma unroll
    for (int r = 0; r < 4; r++) {
        int n  = n0 + ty + r * 8;
        int kp = kp0 + tx;
        oh[(size_t)n * K2 + kp] = th[tx][ty + r * 8];
        ol[(size_t)n * K2 + kp] = tl[tx][ty + r * 8];
    }
}

// ---------------- convert + transpose MoE weight (single fp16 pairs) ----------
__global__ __launch_bounds__(256)
void split_w_h_kernel(const float* __restrict__ W, u32* __restrict__ o,
                      int K, int N) {
    int K2 = K / 2;
    size_t eoffW = (size_t)blockIdx.z * K * N;
    size_t eoffO = (size_t)blockIdx.z * N * K2;
    __shared__ u32 th[32][33];
    int kp0 = blockIdx.x * 32, n0 = blockIdx.y * 32;
    int tx = threadIdx.x, ty = threadIdx.y;
#pragma unroll
    for (int r = 0; r < 4; r++) {
        int kp = kp0 + ty + r * 8;
        int n  = n0 + tx;
        float w0 = W[eoffW + (size_t)(2 * kp) * N + n];
        float w1 = W[eoffW + (size_t)(2 * kp + 1) * N + n];
        th[ty + r * 8][tx] = pack_h2(w0, w1);
    }
    __syncthreads();
#pragma unroll
    for (int r = 0; r < 4; r++) {
        int n  = n0 + ty + r * 8;
        int kp = kp0 + tx;
        o[eoffO + (size_t)n * K2 + kp] = th[tx][ty + r * 8];
    }
}

// ---------------- cp.async helpers ----------------
__device__ __forceinline__ void cp_async16z(void* dst, const void* src, int sz) {
    u32 d = (u32)__cvta_generic_to_shared(dst);
    asm volatile("cp.async.ca.shared.global [%0], [%1], 16, %2;\n"
                 :: "r"(d), "l"(src), "r"(sz) : "memory");
}
__device__ __forceinline__ void cp_commit() {
    asm volatile("cp.async.commit_group;\n" ::: "memory");
}
template<int N> __device__ __forceinline__ void cp_wait() {
    asm volatile("cp.async.wait_group %0;\n" :: "n"(N) : "memory");
}

// ---------------- mma / ldmatrix ----------------
__device__ __forceinline__ void mma_bf16(float* d, const u32* a, const u32* b) {
    asm volatile(
        "mma.sync.aligned.m16n8k16.row.col.f32.bf16.bf16.f32 "
        "{%0,%1,%2,%3}, {%4,%5,%6,%7}, {%8,%9}, {%0,%1,%2,%3};\n"
        : "+f"(d[0]), "+f"(d[1]), "+f"(d[2]), "+f"(d[3])
        : "r"(a[0]), "r"(a[1]), "r"(a[2]), "r"(a[3]), "r"(b[0]), "r"(b[1]));
}
__device__ __forceinline__ void mma_f16(float* d, const u32* a, const u32* b) {
    asm volatile(
        "mma.sync.aligned.m16n8k16.row.col.f32.f16.f16.f32 "
        "{%0,%1,%2,%3}, {%4,%5,%6,%7}, {%8,%9}, {%0,%1,%2,%3};\n"
        : "+f"(d[0]), "+f"(d[1]), "+f"(d[2]), "+f"(d[3])
        : "r"(a[0]), "r"(a[1]), "r"(a[2]), "r"(a[3]), "r"(b[0]), "r"(b[1]));
}
__device__ __forceinline__ void ldsm_x4(u32& r0, u32& r1, u32& r2, u32& r3, u32 addr) {
    asm volatile("ldmatrix.sync.aligned.m8n8.x4.shared.b16 {%0,%1,%2,%3}, [%4];"
                 : "=r"(r0), "=r"(r1), "=r"(r2), "=r"(r3) : "r"(addr));
}

#define BM 128
#define BN 128
#define KP 16            // k-pairs per tile (32 elements)
#define STR 20           // smem row stride in u32 (16 used + 4 pad)
#define ABUF (128*STR)   // 2560 u32 per array per buffer
#define GEMM_SMEM_BYTES  (8*ABUF*4 + BM*4)
#define GEMMH_SMEM_BYTES (4*ABUF*4 + BM*4)

// ---------------- bf16x2 3-pass GEMM (delta projection) ----------
__global__ __launch_bounds__(256, 1)
void gemm_bf(const u32* __restrict__ Ahi, const u32* __restrict__ Alo,
             const u32* __restrict__ Bhi, const u32* __restrict__ Blo,
             float* __restrict__ C1, const float* __restrict__ bias,
             int M, int Ncols, int K)
{
    extern __shared__ u32 sm[];

    int mblk = blockIdx.y;
    int nblk = blockIdx.x;
    int n0 = nblk * BN;
    int K2 = K / 2;
    int tid = threadIdx.x;

    int crow = tid >> 1;
    int cseg = (tid & 1) * 8;
    size_t abase = (size_t)(mblk * BM + crow) * K2 + cseg;
    size_t bbase = (size_t)(n0 + crow) * K2 + cseg;

    int wid = tid >> 5, lane = tid & 31;
    int g = lane >> 2, tig = lane & 3;
    int wm = wid >> 2, wn = wid & 3;

    u32 aoffL = (u32)((wm * 64 + (lane & 15)) * STR + (lane >> 4) * 4);
    u32 boffL = (u32)((wn * 32 + ((lane >> 4) << 3) + (lane & 7)) * STR + ((lane >> 3) & 1) * 4);

    float acc[4][4][4];
#pragma unroll
    for (int i = 0; i < 4; i++)
#pragma unroll
        for (int j = 0; j < 4; j++)
#pragma unroll
            for (int k = 0; k < 4; k++) acc[i][j][k] = 0.f;

    int KT = K2 / KP;
    int buf = 0;
    u32 sdst = crow * STR + cseg;

    {
        u32* s0 = sm;
        cp_async16z(s0 + 0*ABUF + sdst,     Ahi + abase,     16);
        cp_async16z(s0 + 0*ABUF + sdst + 4, Ahi + abase + 4, 16);
        cp_async16z(s0 + 1*ABUF + sdst,     Alo + abase,     16);
        cp_async16z(s0 + 1*ABUF + sdst + 4, Alo + abase + 4, 16);
        cp_async16z(s0 + 2*ABUF + sdst,     Bhi + bbase,     16);
        cp_async16z(s0 + 2*ABUF + sdst + 4, Bhi + bbase + 4, 16);
        cp_async16z(s0 + 3*ABUF + sdst,     Blo + bbase,     16);
        cp_async16z(s0 + 3*ABUF + sdst + 4, Blo + bbase + 4, 16);
        cp_commit();
    }

    for (int kt = 0; kt < KT; kt++) {
        if (kt + 1 < KT) {
            u32* s1 = sm + (buf ^ 1) * 4 * ABUF;
            size_t ao = abase + (size_t)(kt + 1) * KP;
            size_t bo = bbase + (size_t)(kt + 1) * KP;
            cp_async16z(s1 + 0*ABUF + sdst,     Ahi + ao,     16);
            cp_async16z(s1 + 0*ABUF + sdst + 4, Ahi + ao + 4, 16);
            cp_async16z(s1 + 1*ABUF + sdst,     Alo + ao,     16);
            cp_async16z(s1 + 1*ABUF + sdst + 4, Alo + ao + 4, 16);
            cp_async16z(s1 + 2*ABUF + sdst,     Bhi + bo,     16);
            cp_async16z(s1 + 2*ABUF + sdst + 4, Bhi + bo + 4, 16);
            cp_async16z(s1 + 3*ABUF + sdst,     Blo + bo,     16);
            cp_async16z(s1 + 3*ABUF + sdst + 4, Blo + bo + 4, 16);
            cp_commit();
            cp_wait<1>();
        } else {
            cp_wait<0>();
        }
        __syncthreads();

        u32 aAh = (u32)__cvta_generic_to_shared(sm + buf * 4 * ABUF);
        u32 aAl = aAh + ABUF * 4;
        u32 aBh = aAh + 2 * ABUF * 4;
        u32 aBl = aAh + 3 * ABUF * 4;

#pragma unroll
        for (int ks = 0; ks < 2; ks++) {
            int kb = ks * 8;
            u32 ah[4][4], al[4][4];
#pragma unroll
            for (int mt = 0; mt < 4; mt++) {
                u32 off = (aoffL + mt * 16 * STR + kb) * 4;
                ldsm_x4(ah[mt][0], ah[mt][1], ah[mt][2], ah[mt][3], aAh + off);
                ldsm_x4(al[mt][0], al[mt][1], al[mt][2], al[mt][3], aAl + off);
            }
            u32 bh[4][2], bl[4][2];
#pragma unroll
            for (int np = 0; np < 2; np++) {
                u32 off = (boffL + np * 16 * STR + kb) * 4;
                ldsm_x4(bh[2*np][0], bh[2*np][1], bh[2*np+1][0], bh[2*np+1][1], aBh + off);
                ldsm_x4(bl[2*np][0], bl[2*np][1], bl[2*np+1][0], bl[2*np+1][1], aBl + off);
            }
#pragma unroll
            for (int mt = 0; mt < 4; mt++)
#pragma unroll
                for (int nt = 0; nt < 4; nt++) {
                    mma_bf16(acc[mt][nt], ah[mt], bh[nt]);
                    mma_bf16(acc[mt][nt], ah[mt], bl[nt]);
                    mma_bf16(acc[mt][nt], al[mt], bh[nt]);
                }
        }
        __syncthreads();
        buf ^= 1;
    }

#pragma unroll
    for (int mt = 0; mt < 4; mt++) {
#pragma unroll
        for (int half = 0; half < 2; half++) {
            int gr = mblk * BM + wm * 64 + mt * 16 + g + half * 8;
            float* orow = C1 + (size_t)gr * Ncols;
#pragma unroll
            for (int nt = 0; nt < 4; nt++) {
                int col = n0 + wn * 32 + nt * 8 + tig * 2;
                float v0 = softplusf(acc[mt][nt][half*2+0] + bias[col]);
                float v1 = softplusf(acc[mt][nt][half*2+1] + bias[col+1]);
                *(float2*)(orow + col) = make_float2(v0, v1);
            }
        }
    }
}

// ---------------- fp16 single-pass GEMM (MoE up/down), expert-batched ----------
// blockIdx.z = expert.
// MODE 1: A (g_sF) gathered via g_list; nblk<16 -> g_Gh, else g_Uh (fp16 pair stores)
// MODE 2: A compact per-expert rows; Cf[(e*NN+gr),:] = acc (float store)
template<int MODE>
__global__ __launch_bounds__(256, 2)
void gemm_hf(const u32* __restrict__ A,
             const u32* __restrict__ B1, const u32* __restrict__ B2,
             float* __restrict__ Cf, u32* __restrict__ Ch1, u32* __restrict__ Ch2,
             int Ncols, int K)
{
    extern __shared__ u32 sm[];
    int* sidx = (int*)(sm + 4 * ABUF);

    int e = blockIdx.z;
    int M = g_cnt[e];
    int mblk = blockIdx.y;
    if (mblk * BM >= M) return;
    int nblk = blockIdx.x;
    int K2 = K / 2;

    const u32* Bp = B1 + (size_t)e * Ncols * K2;
    u32* Chout = Ch1;
    int nb = nblk;
    if (MODE == 1 && nblk >= 16) {
        Bp = B2 + (size_t)e * Ncols * K2;
        Chout = Ch2; nb = nblk - 16;
    }
    int n0 = nb * BN;
    int tid = threadIdx.x;

    if (MODE == 1) {
        const int* rowidx = g_list + (size_t)e * NN;
        for (int i = tid; i < BM; i += 256) {
            int gr = mblk * BM + i;
            sidx[i] = (gr < M) ? rowidx[gr] : -1;
        }
        __syncthreads();
    }

    int crow = tid >> 1;
    int cseg = (tid & 1) * 8;
    int asz;
    size_t abase;
    if (MODE == 1) {
        int s = sidx[crow];
        asz = (s >= 0) ? 16 : 0;
        abase = (size_t)(s >= 0 ? s : 0) * K2 + cseg;
    } else {
        int gr = mblk * BM + crow;
        asz = (gr < M) ? 16 : 0;
        abase = ((size_t)e * NN + (gr < M ? gr : 0)) * K2 + cseg;
    }
    size_t bbase = (size_t)(n0 + crow) * K2 + cseg;

    int wid = tid >> 5, lane = tid & 31;
    int g = lane >> 2, tig = lane & 3;
    int wm = wid >> 2, wn = wid & 3;

    u32 aoffL = (u32)((wm * 64 + (lane & 15)) * STR + (lane >> 4) * 4);
    u32 boffL = (u32)((wn * 32 + ((lane >> 4) << 3) + (lane & 7)) * STR + ((lane >> 3) & 1) * 4);

    float acc[4][4][4];
#pragma unroll
    for (int i = 0; i < 4; i++)
#pragma unroll
        for (int j = 0; j < 4; j++)
#pragma unroll
            for (int k = 0; k < 4; k++) acc[i][j][k] = 0.f;

    int KT = K2 / KP;
    int buf = 0;
    u32 sdst = crow * STR + cseg;

    {
        u32* s0 = sm;
        cp_async16z(s0 + 0*ABUF + sdst,     A + abase,      asz);
        cp_async16z(s0 + 0*ABUF + sdst + 4, A + abase + 4,  asz);
        cp_async16z(s0 + 1*ABUF + sdst,     Bp + bbase,     16);
        cp_async16z(s0 + 1*ABUF + sdst + 4, Bp + bbase + 4, 16);
        cp_commit();
    }

    for (int kt = 0; kt < KT; kt++) {
        if (kt + 1 < KT) {
            u32* s1 = sm + (buf ^ 1) * 2 * ABUF;
            size_t ao = abase + (size_t)(kt + 1) * KP;
            size_t bo = bbase + (size_t)(kt + 1) * KP;
            cp_async16z(s1 + 0*ABUF + sdst,     A + ao,      asz);
            cp_async16z(s1 + 0*ABUF + sdst + 4, A + ao + 4,  asz);
            cp_async16z(s1 + 1*ABUF + sdst,     Bp + bo,     16);
            cp_async16z(s1 + 1*ABUF + sdst + 4, Bp + bo + 4, 16);
            cp_commit();
            cp_wait<1>();
        } else {
            cp_wait<0>();
        }
        __syncthreads();

        u32 aA = (u32)__cvta_generic_to_shared(sm + buf * 2 * ABUF);
        u32 aB = aA + ABUF * 4;

#pragma unroll
        for (int ks = 0; ks < 2; ks++) {
            int kb = ks * 8;
            u32 ah[4][4];
#pragma unroll
            for (int mt = 0; mt < 4; mt++) {
                u32 off = (aoffL + mt * 16 * STR + kb) * 4;
                ldsm_x4(ah[mt][0], ah[mt][1], ah[mt][2], ah[mt][3], aA + off);
            }
            u32 bh[4][2];
#pragma unroll
            for (int np = 0; np < 2; np++) {
                u32 off = (boffL + np * 16 * STR + kb) * 4;
                ldsm_x4(bh[2*np][0], bh[2*np][1], bh[2*np+1][0], bh[2*np+1][1], aB + off);
            }
#pragma unroll
            for (int mt = 0; mt < 4; mt++)
#pragma unroll
                for (int nt = 0; nt < 4; nt++)
                    mma_f16(acc[mt][nt], ah[mt], bh[nt]);
        }
        __syncthreads();
        buf ^= 1;
    }

#pragma unroll
    for (int mt = 0; mt < 4; mt++) {
#pragma unroll
        for (int half = 0; half < 2; half++) {
            int lr = wm * 64 + mt * 16 + g + half * 8;
            int gr = mblk * BM + lr;
            if (gr >= M) continue;
            if (MODE == 1) {
                u32* orow = Chout + ((size_t)e * NN + gr) * (Ncols / 2);
#pragma unroll
                for (int nt = 0; nt < 4; nt++) {
                    int col = n0 + wn * 32 + nt * 8 + tig * 2;
                    orow[col >> 1] = pack_h2(acc[mt][nt][half*2+0], acc[mt][nt][half*2+1]);
                }
            } else {
                float* orow = Cf + ((size_t)e * NN + gr) * Ncols;
#pragma unroll
                for (int nt = 0; nt < 4; nt++) {
                    int col = n0 + wn * 32 + nt * 8 + tig * 2;
                    *(float2*)(orow + col) =
                        make_float2(acc[mt][nt][half*2+0], acc[mt][nt][half*2+1]);
                }
            }
        }
    }
}

// ---------------- small projections: Bm, Cm (from x) ----------------
__global__ __launch_bounds__(128)
void proj_small(const float* __restrict__ x, const float* __restrict__ WB,
                const float* __restrict__ WC)
{
    int n = blockIdx.x;
    __shared__ float xs[DD];
    const float* xr = x + (size_t)n * DD;
    for (int i = threadIdx.x; i < DD; i += 128) xs[i] = xr[i];
    __syncthreads();
    int warp = threadIdx.x >> 5, lane = threadIdx.x & 31;
    for (int c = warp; c < 32; c += 4) {
        const float* W; int col; float* out;
        if (c < 16) { W = WB; col = c;      out = g_Bm + (size_t)n * SS + col; }
        else        { W = WC; col = c - 16; out = g_Cm + (size_t)n * SS + col; }
        float s = 0.f;
        for (int k = lane; k < DD; k += 32)
            s = fmaf(xs[k], W[(size_t)k * SS + col], s);
        s += __shfl_xor_sync(~0u, s, 16);
        s += __shfl_xor_sync(~0u, s, 8);
        s += __shfl_xor_sync(~0u, s, 4);
        s += __shfl_xor_sync(~0u, s, 2);
        s += __shfl_xor_sync(~0u, s, 1);
        if (lane == 0) *out = s;
    }
}

// ---------------- selective scan: hoisted coefficients, short chain ------------
// block 128 = (8 d) x (16 s); grid = BB * DD/8 = 256
#define SPQ 168   // q-stride in sp (== 8 mod 32 for conflict-free reads)
__global__ __launch_bounds__(128)
void scan_kernel(const float* __restrict__ x, const float* __restrict__ A_log,
                 const float* __restrict__ D_param)
{
    int b = blockIdx.x >> 7;
    int dchunk = blockIdx.x & 127;    // 8 d's per chunk
    int dl = threadIdx.x >> 4;        // 0..7
    int s  = threadIdx.x & 15;        // state
    int d = dchunk * 8 + dl;

    float A_ds = -__expf(A_log[d * SS + s]);

    __shared__ float sx[16][8], sd[16][8];
    __shared__ float sB[16][17], sC[16][17];
    __shared__ float sp[16 * SPQ];    // [q][s*10 + dl]
    __shared__ float sDp[8];

    int tt = threadIdx.x >> 3;        // 0..15 (x/delta loader row)
    int cc = threadIdx.x & 7;         // 0..7
    int t2 = threadIdx.x >> 4;        // 0..7  (B/C loader rows t2, t2+8)
    int c16 = threadIdx.x & 15;
    const int base_bt = b * LL;

    if (threadIdx.x < 8) sDp[threadIdx.x] = D_param[dchunk * 8 + threadIdx.x];

    size_t xoff = ((size_t)(base_bt + tt)) * DD + dchunk * 8 + cc;
    float rx = x[xoff];
    float rd = g_delta[xoff];
    size_t boff0 = ((size_t)(base_bt + t2)) * SS + c16;
    size_t boff1 = ((size_t)(base_bt + t2 + 8)) * SS + c16;
    float rB0 = g_Bm[boff0], rB1 = g_Bm[boff1];
    float rC0 = g_Cm[boff0], rC1 = g_Cm[boff1];

    float h = 0.f;
    for (int t0 = 0; t0 < LL; t0 += 16) {
        __syncthreads();
        sx[tt][cc] = rx; sd[tt][cc] = rd;
        sB[t2][c16] = rB0; sB[t2 + 8][c16] = rB1;
        sC[t2][c16] = rC0; sC[t2 + 8][c16] = rC1;
        __syncthreads();
        if (t0 + 16 < LL) {
            size_t xo = ((size_t)(base_bt + t0 + 16 + tt)) * DD + dchunk * 8 + cc;
            rx = x[xo]; rd = g_delta[xo];
            size_t bo0 = ((size_t)(base_bt + t0 + 16 + t2)) * SS + c16;
            size_t bo1 = ((size_t)(base_bt + t0 + 24 + t2)) * SS + c16;
            rB0 = g_Bm[bo0]; rB1 = g_Bm[bo1];
            rC0 = g_Cm[bo0]; rC1 = g_Cm[bo1];
        }
        // hoisted, h-independent coefficients (ILP-rich)
        float av[16], bx[16];
#pragma unroll
        for (int q = 0; q < 16; q++) {
            float dv = sd[q][dl];
            av[q] = __expf(fminf(dv * A_ds, 10.f));
            bx[q] = fminf(fmaxf(dv * sB[q][s], -10.f), 10.f) * sx[q][dl];
        }
        // short serial chain: fma + clamp only
        float p[16];
#pragma unroll
        for (int q = 0; q < 16; q++) {
            h = fminf(fmaxf(fmaf(av[q], h, bx[q]), -10000.f), 10000.f);
            p[q] = h * sC[q][s];
        }
#pragma unroll
        for (int q = 0; q < 16; q++)
            sp[q * SPQ + s * 10 + dl] = p[q];
        __syncthreads();
        // reduction role: (q2 = tid>>3, d2 = tid&7)
        int q2 = tt, d2 = cc;
        float ysum = 0.f;
#pragma unroll
        for (int s2 = 0; s2 < 16; s2++)
            ysum += sp[q2 * SPQ + s2 * 10 + d2];
        float y = fmaf(sx[q2][d2], sDp[d2], ysum);
        size_t yo = ((size_t)(base_bt + t0 + q2)) * DD + dchunk * 8 + d2;
        g_ssm[yo] = y;
        float yn = __shfl_down_sync(~0u, y, 1);
        if (!(d2 & 1)) {
            float ya = fminf(fmaxf(y,  -60000.f), 60000.f);
            float yb = fminf(fmaxf(yn, -60000.f), 60000.f);
            size_t po = ((size_t)(base_bt + t0 + q2)) * (DD/2) + dchunk * 4 + (d2 >> 1);
            g_sF[po] = pack_h2(ya, yb);
        }
    }
}

// ---------------- router on SSM output: softmax, top-2, expert lists ----------
__global__ __launch_bounds__(128)
void router_kernel(const float* __restrict__ WR)
{
    int n = blockIdx.x;
    __shared__ float xs[DD];
    __shared__ float logits[EE];
    const float* xr = g_ssm + (size_t)n * DD;
    for (int i = threadIdx.x; i < DD; i += 128) xs[i] = xr[i];
    __syncthreads();
    int warp = threadIdx.x >> 5, lane = threadIdx.x & 31;
    {
        float s = 0.f;
        for (int k = lane; k < DD; k += 32)
            s = fmaf(xs[k], WR[(size_t)k * EE + warp], s);
        s += __shfl_xor_sync(~0u, s, 16);
        s += __shfl_xor_sync(~0u, s, 8);
        s += __shfl_xor_sync(~0u, s, 4);
        s += __shfl_xor_sync(~0u, s, 2);
        s += __shfl_xor_sync(~0u, s, 1);
        if (lane == 0) logits[warp] = s;
    }
    __syncthreads();
    if (threadIdx.x == 0) {
        float l[4] = {logits[0], logits[1], logits[2], logits[3]};
        float m = fmaxf(fmaxf(l[0], l[1]), fmaxf(l[2], l[3]));
        float e[4], sum = 0.f;
#pragma unroll
        for (int i = 0; i < 4; i++) { e[i] = __expf(l[i] - m); sum += e[i]; }
        float p[4];
#pragma unroll
        for (int i = 0; i < 4; i++) p[i] = e[i] / sum;
        int i0 = 0;
#pragma unroll
        for (int i = 1; i < 4; i++) if (p[i] > p[i0]) i0 = i;
        int i1 = -1;
#pragma unroll
        for (int i = 0; i < 4; i++) {
            if (i == i0) continue;
            if (i1 < 0 || p[i] > p[i1]) i1 = i;
        }
        float w0 = p[i0], w1 = p[i1];
        float sw = w0 + w1 + 1e-9f;
        w0 /= sw; w1 /= sw;
        int pos = atomicAdd(&g_cnt[i0], 1);
        g_list[i0*NN + pos] = n; g_cw[i0*NN + pos] = w0;
        g_loc[n] = i0 * NN + pos;
        pos = atomicAdd(&g_cnt[i1], 1);
        g_list[i1*NN + pos] = n; g_cw[i1*NN + pos] = w1;
        g_loc[NN + n] = i1 * NN + pos;
    }
}

// ---------------- silu(G)*U -> rmsnorm(wn) -> * cw (FMA-only, fp16 I/O) -------
__global__ __launch_bounds__(256)
void act_norm(const float* __restrict__ wn_all)
{
    int i = blockIdx.x;
    int e = blockIdx.y;
    if (i >= g_cnt[e]) return;
    size_t row = (size_t)e * NN + i;
    const float* wn = wn_all + (size_t)e * HH;
    __shared__ float buf[HH];
    __shared__ float red[8];
    float ss = 0.f;
    for (int j2 = threadIdx.x; j2 < HH / 2; j2 += 256) {
        float2 gg = __half22float2(*(const __half2*)&g_Gh[row * (HH/2) + j2]);
        float2 uu = __half22float2(*(const __half2*)&g_Uh[row * (HH/2) + j2]);
        float v0 = fsilu(gg.x) * uu.x;
        float v1 = fsilu(gg.y) * uu.y;
        buf[2*j2]   = v0;
        buf[2*j2+1] = v1;
        ss = fmaf(v0, v0, fmaf(v1, v1, ss));
    }
    ss += __shfl_xor_sync(~0u, ss, 16);
    ss += __shfl_xor_sync(~0u, ss, 8);
    ss += __shfl_xor_sync(~0u, ss, 4);
    ss += __shfl_xor_sync(~0u, ss, 2);
    ss += __shfl_xor_sync(~0u, ss, 1);
    if ((threadIdx.x & 31) == 0) red[threadIdx.x >> 5] = ss;
    __syncthreads();
    if (threadIdx.x < 32) {
        float v = (threadIdx.x < 8) ? red[threadIdx.x] : 0.f;
        v += __shfl_xor_sync(~0u, v, 4);
        v += __shfl_xor_sync(~0u, v, 2);
        v += __shfl_xor_sync(~0u, v, 1);
        if (threadIdx.x == 0) red[0] = v;
    }
    __syncthreads();
    float scale = g_cw[(size_t)e * NN + i] * rsqrtf(red[0] / (float)HH + 1e-6f);
    for (int j2 = threadIdx.x; j2 < HH / 2; j2 += 256) {
        float v0 = wn[2 * j2]     * buf[2 * j2]     * scale;
        float v1 = wn[2 * j2 + 1] * buf[2 * j2 + 1] * scale;
        g_aF[row * (HH/2) + j2] = pack_h2(v0, v1);
    }
}

// ---------------- final rmsnorm over (ssm + Dn[loc0] + Dn[loc1]) --------------
__global__ __launch_bounds__(256)
void final_norm(const float* __restrict__ norm_w, float* __restrict__ out)
{
    int n = blockIdx.x;
    __shared__ float red[8];
    __shared__ float buf[DD];
    int l0 = g_loc[n], l1 = g_loc[NN + n];
    const float* r0 = g_Dn + (size_t)l0 * DD;
    const float* r1 = g_Dn + (size_t)l1 * DD;
    const float* rs = g_ssm + (size_t)n * DD;
    float ss = 0.f;
    for (int j = threadIdx.x; j < DD; j += 256) {
        float v = rs[j] + r0[j] + r1[j];
        buf[j] = v;
        ss = fmaf(v, v, ss);
    }
    ss += __shfl_xor_sync(~0u, ss, 16);
    ss += __shfl_xor_sync(~0u, ss, 8);
    ss += __shfl_xor_sync(~0u, ss, 4);
    ss += __shfl_xor_sync(~0u, ss, 2);
    ss += __shfl_xor_sync(~0u, ss, 1);
    if ((threadIdx.x & 31) == 0) red[threadIdx.x >> 5] = ss;
    __syncthreads();
    if (threadIdx.x < 32) {
        float v = (threadIdx.x < 8) ? red[threadIdx.x] : 0.f;
        v += __shfl_xor_sync(~0u, v, 4);
        v += __shfl_xor_sync(~0u, v, 2);
        v += __shfl_xor_sync(~0u, v, 1);
        if (threadIdx.x == 0) red[0] = v;
    }
    __syncthreads();
    float inv = rsqrtf(red[0] / (float)DD + 1e-6f);
    for (int j = threadIdx.x; j < DD; j += 256)
        out[(size_t)n * DD + j] = norm_w[j] * buf[j] * inv;
}

// ---------------- launch ----------------
extern "C" void kernel_launch(void* const* d_in, const int* in_sizes, int n_in,
                              void* d_out, int out_size)
{
    const float* x        = (const float*)d_in[0];
    const float* A_log    = (const float*)d_in[1];
    const float* D_param  = (const float*)d_in[2];
    const float* W_delta  = (const float*)d_in[3];
    const float* b_delta  = (const float*)d_in[4];
    const float* W_B      = (const float*)d_in[5];
    const float* W_C      = (const float*)d_in[6];
    const float* W_router = (const float*)d_in[7];
    const float* Wg       = (const float*)d_in[8];
    const float* Wu       = (const float*)d_in[9];
    const float* Wd       = (const float*)d_in[10];
    const float* wn_exp   = (const float*)d_in[11];
    const float* norm_w   = (const float*)d_in[12];
    float* out = (float*)d_out;

    float *p_delta, *p_Dn;
    u32 *p_xHi, *p_xLo, *p_sF, *p_aF, *p_Gh, *p_Uh;
    u32 *p_WdHi, *p_WdLo, *p_WgF, *p_WuF, *p_WnF;
    cudaGetSymbolAddress((void**)&p_delta, g_delta);
    cudaGetSymbolAddress((void**)&p_Gh,    g_Gh);
    cudaGetSymbolAddress((void**)&p_Uh,    g_Uh);
    cudaGetSymbolAddress((void**)&p_Dn,    g_Dn);
    cudaGetSymbolAddress((void**)&p_xHi,   g_xHi);
    cudaGetSymbolAddress((void**)&p_xLo,   g_xLo);
    cudaGetSymbolAddress((void**)&p_sF,    g_sF);
    cudaGetSymbolAddress((void**)&p_aF,    g_aF);
    cudaGetSymbolAddress((void**)&p_WdHi,  g_WdHi);
    cudaGetSymbolAddress((void**)&p_WdLo,  g_WdLo);
    cudaGetSymbolAddress((void**)&p_WgF,   g_WgF);
    cudaGetSymbolAddress((void**)&p_WuF,   g_WuF);
    cudaGetSymbolAddress((void**)&p_WnF,   g_WnF);

    cudaFuncSetAttribute(gemm_bf,    cudaFuncAttributeMaxDynamicSharedMemorySize, GEMM_SMEM_BYTES);
    cudaFuncSetAttribute(gemm_hf<1>, cudaFuncAttributeMaxDynamicSharedMemorySize, GEMMH_SMEM_BYTES);
    cudaFuncSetAttribute(gemm_hf<2>, cudaFuncAttributeMaxDynamicSharedMemorySize, GEMMH_SMEM_BYTES);

    zero_counts<<<1, 32>>>();

    // operand pre-conversion
    {
        int n2 = NN * DD / 2;
        split_x_kernel<<<(n2 + 255) / 256, 256>>>(x, p_xHi, p_xLo, n2);
    }
    {
        dim3 blk(32, 8);
        dim3 gWdel(DD/2/32, DD/32, 1);
        split_w_kernel<<<gWdel, blk>>>(W_delta, p_WdHi, p_WdLo, DD, DD);
        dim3 gUp(DD/2/32, HH/32, EE);
        split_w_h_kernel<<<gUp, blk>>>(Wg, p_WgF, DD, HH);
        split_w_h_kernel<<<gUp, blk>>>(Wu, p_WuF, DD, HH);
        dim3 gDn(HH/2/32, DD/32, EE);
        split_w_h_kernel<<<gDn, blk>>>(Wd, p_WnF, HH, DD);
    }

    // delta = softplus(x @ W_delta + b)   [bf16x2 3-pass]
    {
        dim3 grid(DD / BN, NN / BM);
        gemm_bf<<<grid, 256, GEMM_SMEM_BYTES>>>(
            p_xHi, p_xLo, p_WdHi, p_WdLo, p_delta, b_delta, NN, DD, DD);
    }

    // Bm, Cm from x
    proj_small<<<NN, 128>>>(x, W_B, W_C);

    // selective scan -> g_ssm / fp16 ssm
    scan_kernel<<<BB * (DD / 8), 128>>>(x, A_log, D_param);

    // router on SSM output
    router_kernel<<<NN, 128>>>(W_router);

    // MoE, all experts batched:
    gemm_hf<1><<<dim3(2 * HH / BN, NN / BM, EE), 256, GEMMH_SMEM_BYTES>>>(
        p_sF, p_WgF, p_WuF, nullptr, p_Gh, p_Uh, HH, DD);
    act_norm<<<dim3(NN, EE), 256>>>(wn_exp);
    gemm_hf<2><<<dim3(DD / BN, NN / BM, EE), 256, GEMMH_SMEM_BYTES>>>(
        p_aF, p_WnF, nullptr, p_Dn, nullptr, nullptr, DD, HH);

    // out = rmsnorm(ssm + Dn[loc0] + Dn[loc1], norm_w)
    final_norm<<<NN, 256>>>(norm_w, out);
}

// round 13
// speedup vs baseline: 1.0609x; 1.0060x over previous
#include <cuda_runtime.h>
#include <cuda_bf16.h>
#include <cuda_fp16.h>
#include <math.h>
#include <stdint.h>

// Problem dims (fixed)
#define BB 2
#define LL 2048
#define DD 1024
#define SS 16
#define EE 4
#define HH 2048
#define NN (BB*LL)   // 4096

typedef uint32_t u32;

// ---------------- scratch (device globals; no allocation allowed) ----------------
__device__ float g_delta[NN*DD];
__device__ float g_Bm[NN*SS];
__device__ float g_Cm[NN*SS];
__device__ float g_ssm[NN*DD];
__device__ int   g_cnt[EE];
__device__ int   g_list[EE*NN];
__device__ float g_cw[EE*NN];
__device__ float g_rs[EE*NN];            // per compact row: cw * rsqrt(mean(v^2)+eps)
__device__ int   g_loc[2*NN];            // token -> (e*NN + pos), two entries
__device__ u32   g_Gh[(size_t)EE*NN*HH/2];  // per-expert compact G (fp16 pairs)
__device__ u32   g_Uh[(size_t)EE*NN*HH/2];  // per-expert compact U (fp16 pairs)
__device__ float g_Dn[(size_t)EE*NN*DD]; // per-expert compact down output

// bf16x2 split operands for delta GEMM (packed: low16 = even k, high16 = odd k)
__device__ u32 g_xHi[NN*DD/2],   g_xLo[NN*DD/2];      // x           [NN][512]
__device__ u32 g_WdHi[DD*DD/2],  g_WdLo[DD*DD/2];     // W_delta^T   [D][512]
// fp16 single-precision MoE operands (pair-packed)
__device__ u32 g_sF[NN*DD/2];                         // ssm  (fp16 pairs)
__device__ u32 g_aF[(size_t)EE*NN*HH/2];              // act v (fp16 pairs, per-expert)
__device__ u32 g_WgF[EE*HH*DD/2];                     // Wg^T  [e][H][512]
__device__ u32 g_WuF[EE*HH*DD/2];                     // Wu^T  [e][H][512]
__device__ u32 g_WnF[EE*DD*HH/2];                     // (wn*Wd)^T  [e][D][1024]

// ---------------- FMA-only helpers ----------------
__device__ __forceinline__ float fexpf(float x) {
    x = fmaxf(x, -87.3f);
    float t = fmaf(x, 1.4426950408889634f, 12582912.f);
    float n = t - 12582912.f;
    float r = fmaf(n, -0.693359375f, x);
    r = fmaf(n, 2.12194440e-4f, r);
    float z = r * r;
    float p =          1.9875691500E-4f;
    p = fmaf(p, r,     1.3981999507E-3f);
    p = fmaf(p, r,     8.3334519073E-3f);
    p = fmaf(p, r,     4.1665795894E-2f);
    p = fmaf(p, r,     1.6666665459E-1f);
    p = fmaf(p, r,     5.0000001201E-1f);
    float res = fmaf(p, z, r) + 1.f;
    int e = (int)n;
    return __int_as_float(__float_as_int(res) + (e << 23));
}

__device__ __forceinline__ float flogf(float u) {   // u >= 1
    int iu = __float_as_int(u);
    int e = ((iu >> 23) & 255) - 127;
    float m = __int_as_float((iu & 0x007FFFFF) | 0x3F800000);
    if (m > 1.41421356f) { m *= 0.5f; e += 1; }
    float f = m - 1.f;
    float z = f * f;
    float p =          7.0376836292E-2f;
    p = fmaf(p, f,    -1.1514610310E-1f);
    p = fmaf(p, f,     1.1676998740E-1f);
    p = fmaf(p, f,    -1.2420140846E-1f);
    p = fmaf(p, f,     1.4249322787E-1f);
    p = fmaf(p, f,    -1.6668057665E-1f);
    p = fmaf(p, f,     2.0000714765E-1f);
    p = fmaf(p, f,    -2.4999993993E-1f);
    p = fmaf(p, f,     3.3333331174E-1f);
    float y = fmaf(z * f, p, -0.5f * z);
    float res = f + y;
    return fmaf((float)e, 0.69314718056f, res);
}

__device__ __forceinline__ float softplusf(float z) {
    if (z > 20.f) return z;
    return flogf(1.f + fexpf(z));
}

__device__ __forceinline__ float frecip12(float d) {  // d in (1, 2]
    float r = __int_as_float(0x7EF311C3 - __float_as_int(d));
    r = r * fmaf(-d, r, 2.f);
    r = r * fmaf(-d, r, 2.f);
    return r;
}

__device__ __forceinline__ float fsilu(float g) {   // g * sigmoid(g)
    float e = fexpf(-fabsf(g));
    float r = frecip12(1.f + e);
    float num = (g >= 0.f) ? 1.f : e;
    return g * num * r;
}

__device__ __forceinline__ void split2(float a, float b, u32& hi, u32& lo) {
    __nv_bfloat16 ah = __float2bfloat16(a);
    __nv_bfloat16 bh = __float2bfloat16(b);
    float ra = a - __bfloat162float(ah);
    float rb = b - __bfloat162float(bh);
    __nv_bfloat16 al = __float2bfloat16(ra);
    __nv_bfloat16 bl = __float2bfloat16(rb);
    hi = ((u32)__bfloat16_as_ushort(bh) << 16) | __bfloat16_as_ushort(ah);
    lo = ((u32)__bfloat16_as_ushort(bl) << 16) | __bfloat16_as_ushort(al);
}

__device__ __forceinline__ u32 pack_h2(float a, float b) {
    __half2 h = __floats2half2_rn(a, b);
    return *reinterpret_cast<u32*>(&h);
}

// ---------------- zero counts ----------------
__global__ void zero_counts() {
    if (threadIdx.x < EE) g_cnt[threadIdx.x] = 0;
}

// ---------------- split x (bf16 pairs, row-major) ----------------
__global__ __launch_bounds__(256)
void split_x_kernel(const float* __restrict__ in, u32* __restrict__ oh,
                    u32* __restrict__ ol, int n2) {
    int i = blockIdx.x * blockDim.x + threadIdx.x;
    if (i < n2) {
        float2 v = ((const float2*)in)[i];
        u32 hi, lo; split2(v.x, v.y, hi, lo);
        oh[i] = hi; ol[i] = lo;
    }
}

// ---------------- split + transpose W_delta (bf16 pairs) ----------------
__global__ __launch_bounds__(256)
void split_w_kernel(const float* __restrict__ W, u32* __restrict__ oh,
                    u32* __restrict__ ol, int K, int N) {
    int K2 = K / 2;
    __shared__ u32 th[32][33], tl[32][33];
    int kp0 = blockIdx.x * 32, n0 = blockIdx.y * 32;
    int tx = threadIdx.x, ty = threadIdx.y;
#pragma unroll
    for (int r = 0; r < 4; r++) {
        int kp = kp0 + ty + r * 8;
        int n  = n0 + tx;
        float w0 = W[(size_t)(2 * kp) * N + n];
        float w1 = W[(size_t)(2 * kp + 1) * N + n];
        u32 hi, lo; split2(w0, w1, hi, lo);
        th[ty + r * 8][tx] = hi;
        tl[ty + r * 8][tx] = lo;
    }
    __syncthreads();
#pragma unroll
    for (int r = 0; r < 4; r++) {
        int n  = n0 + ty + r * 8;
        int kp = kp0 + tx;
        oh[(size_t)n * K2 + kp] = th[tx][ty + r * 8];
        ol[(size_t)n * K2 + kp] = tl[tx][ty + r * 8];
    }
}

// ---------------- convert + transpose MoE weight (single fp16 pairs) ----------
// wn != nullptr: multiply row k by wn[e][k] (folds rmsnorm weight into W_down)
__global__ __launch_bounds__(256)
void split_w_h_kernel(const float* __restrict__ W, u32* __restrict__ o,
                      int K, int N, const float* __restrict__ wn) {
    int K2 = K / 2;
    size_t eoffW = (size_t)blockIdx.z * K * N;
    size_t eoffO = (size_t)blockIdx.z * N * K2;
    const float* wne = wn ? (wn + (size_t)blockIdx.z * K) : nullptr;
    __shared__ u32 th[32][33];
    int kp0 = blockIdx.x * 32, n0 = blockIdx.y * 32;
    int tx = threadIdx.x, ty = threadIdx.y;
#pragma unroll
    for (int r = 0; r < 4; r++) {
        int kp = kp0 + ty + r * 8;
        int n  = n0 + tx;
        float w0 = W[eoffW + (size_t)(2 * kp) * N + n];
        float w1 = W[eoffW + (size_t)(2 * kp + 1) * N + n];
        if (wne) { w0 *= wne[2 * kp]; w1 *= wne[2 * kp + 1]; }
        th[ty + r * 8][tx] = pack_h2(w0, w1);
    }
    __syncthreads();
#pragma unroll
    for (int r = 0; r < 4; r++) {
        int n  = n0 + ty + r * 8;
        int kp = kp0 + tx;
        o[eoffO + (size_t)n * K2 + kp] = th[tx][ty + r * 8];
    }
}

// ---------------- cp.async helpers ----------------
__device__ __forceinline__ void cp_async16z(void* dst, const void* src, int sz) {
    u32 d = (u32)__cvta_generic_to_shared(dst);
    asm volatile("cp.async.ca.shared.global [%0], [%1], 16, %2;\n"
                 :: "r"(d), "l"(src), "r"(sz) : "memory");
}
__device__ __forceinline__ void cp_commit() {
    asm volatile("cp.async.commit_group;\n" ::: "memory");
}
template<int N> __device__ __forceinline__ void cp_wait() {
    asm volatile("cp.async.wait_group %0;\n" :: "n"(N) : "memory");
}

// ---------------- mma / ldmatrix ----------------
__device__ __forceinline__ void mma_bf16(float* d, const u32* a, const u32* b) {
    asm volatile(
        "mma.sync.aligned.m16n8k16.row.col.f32.bf16.bf16.f32 "
        "{%0,%1,%2,%3}, {%4,%5,%6,%7}, {%8,%9}, {%0,%1,%2,%3};\n"
        : "+f"(d[0]), "+f"(d[1]), "+f"(d[2]), "+f"(d[3])
        : "r"(a[0]), "r"(a[1]), "r"(a[2]), "r"(a[3]), "r"(b[0]), "r"(b[1]));
}
__device__ __forceinline__ void mma_f16(float* d, const u32* a, const u32* b) {
    asm volatile(
        "mma.sync.aligned.m16n8k16.row.col.f32.f16.f16.f32 "
        "{%0,%1,%2,%3}, {%4,%5,%6,%7}, {%8,%9}, {%0,%1,%2,%3};\n"
        : "+f"(d[0]), "+f"(d[1]), "+f"(d[2]), "+f"(d[3])
        : "r"(a[0]), "r"(a[1]), "r"(a[2]), "r"(a[3]), "r"(b[0]), "r"(b[1]));
}
__device__ __forceinline__ void ldsm_x4(u32& r0, u32& r1, u32& r2, u32& r3, u32 addr) {
    asm volatile("ldmatrix.sync.aligned.m8n8.x4.shared.b16 {%0,%1,%2,%3}, [%4];"
                 : "=r"(r0), "=r"(r1), "=r"(r2), "=r"(r3) : "r"(addr));
}

#define BM 128
#define BN 128
#define KP 16            // k-pairs per tile (32 elements)
#define STR 20           // smem row stride in u32 (16 used + 4 pad)
#define ABUF (128*STR)   // 2560 u32 per array per buffer
#define GEMM_SMEM_BYTES  (8*ABUF*4 + BM*4)
#define GEMMH_SMEM_BYTES (4*ABUF*4 + BM*4)

// ---------------- bf16x2 3-pass GEMM (delta projection) ----------
__global__ __launch_bounds__(256, 1)
void gemm_bf(const u32* __restrict__ Ahi, const u32* __restrict__ Alo,
             const u32* __restrict__ Bhi, const u32* __restrict__ Blo,
             float* __restrict__ C1, const float* __restrict__ bias,
             int M, int Ncols, int K)
{
    extern __shared__ u32 sm[];

    int mblk = blockIdx.y;
    int nblk = blockIdx.x;
    int n0 = nblk * BN;
    int K2 = K / 2;
    int tid = threadIdx.x;

    int crow = tid >> 1;
    int cseg = (tid & 1) * 8;
    size_t abase = (size_t)(mblk * BM + crow) * K2 + cseg;
    size_t bbase = (size_t)(n0 + crow) * K2 + cseg;

    int wid = tid >> 5, lane = tid & 31;
    int g = lane >> 2, tig = lane & 3;
    int wm = wid >> 2, wn = wid & 3;

    u32 aoffL = (u32)((wm * 64 + (lane & 15)) * STR + (lane >> 4) * 4);
    u32 boffL = (u32)((wn * 32 + ((lane >> 4) << 3) + (lane & 7)) * STR + ((lane >> 3) & 1) * 4);

    float acc[4][4][4];
#pragma unroll
    for (int i = 0; i < 4; i++)
#pragma unroll
        for (int j = 0; j < 4; j++)
#pragma unroll
            for (int k = 0; k < 4; k++) acc[i][j][k] = 0.f;

    int KT = K2 / KP;
    int buf = 0;
    u32 sdst = crow * STR + cseg;

    {
        u32* s0 = sm;
        cp_async16z(s0 + 0*ABUF + sdst,     Ahi + abase,     16);
        cp_async16z(s0 + 0*ABUF + sdst + 4, Ahi + abase + 4, 16);
        cp_async16z(s0 + 1*ABUF + sdst,     Alo + abase,     16);
        cp_async16z(s0 + 1*ABUF + sdst + 4, Alo + abase + 4, 16);
        cp_async16z(s0 + 2*ABUF + sdst,     Bhi + bbase,     16);
        cp_async16z(s0 + 2*ABUF + sdst + 4, Bhi + bbase + 4, 16);
        cp_async16z(s0 + 3*ABUF + sdst,     Blo + bbase,     16);
        cp_async16z(s0 + 3*ABUF + sdst + 4, Blo + bbase + 4, 16);
        cp_commit();
    }

    for (int kt = 0; kt < KT; kt++) {
        if (kt + 1 < KT) {
            u32* s1 = sm + (buf ^ 1) * 4 * ABUF;
            size_t ao = abase + (size_t)(kt + 1) * KP;
            size_t bo = bbase + (size_t)(kt + 1) * KP;
            cp_async16z(s1 + 0*ABUF + sdst,     Ahi + ao,     16);
            cp_async16z(s1 + 0*ABUF + sdst + 4, Ahi + ao + 4, 16);
            cp_async16z(s1 + 1*ABUF + sdst,     Alo + ao,     16);
            cp_async16z(s1 + 1*ABUF + sdst + 4, Alo + ao + 4, 16);
            cp_async16z(s1 + 2*ABUF + sdst,     Bhi + bo,     16);
            cp_async16z(s1 + 2*ABUF + sdst + 4, Bhi + bo + 4, 16);
            cp_async16z(s1 + 3*ABUF + sdst,     Blo + bo,     16);
            cp_async16z(s1 + 3*ABUF + sdst + 4, Blo + bo + 4, 16);
            cp_commit();
            cp_wait<1>();
        } else {
            cp_wait<0>();
        }
        __syncthreads();

        u32 aAh = (u32)__cvta_generic_to_shared(sm + buf * 4 * ABUF);
        u32 aAl = aAh + ABUF * 4;
        u32 aBh = aAh + 2 * ABUF * 4;
        u32 aBl = aAh + 3 * ABUF * 4;

#pragma unroll
        for (int ks = 0; ks < 2; ks++) {
            int kb = ks * 8;
            u32 ah[4][4], al[4][4];
#pragma unroll
            for (int mt = 0; mt < 4; mt++) {
                u32 off = (aoffL + mt * 16 * STR + kb) * 4;
                ldsm_x4(ah[mt][0], ah[mt][1], ah[mt][2], ah[mt][3], aAh + off);
                ldsm_x4(al[mt][0], al[mt][1], al[mt][2], al[mt][3], aAl + off);
            }
            u32 bh[4][2], bl[4][2];
#pragma unroll
            for (int np = 0; np < 2; np++) {
                u32 off = (boffL + np * 16 * STR + kb) * 4;
                ldsm_x4(bh[2*np][0], bh[2*np][1], bh[2*np+1][0], bh[2*np+1][1], aBh + off);
                ldsm_x4(bl[2*np][0], bl[2*np][1], bl[2*np+1][0], bl[2*np+1][1], aBl + off);
            }
#pragma unroll
            for (int mt = 0; mt < 4; mt++)
#pragma unroll
                for (int nt = 0; nt < 4; nt++) {
                    mma_bf16(acc[mt][nt], ah[mt], bh[nt]);
                    mma_bf16(acc[mt][nt], ah[mt], bl[nt]);
                    mma_bf16(acc[mt][nt], al[mt], bh[nt]);
                }
        }
        __syncthreads();
        buf ^= 1;
    }

#pragma unroll
    for (int mt = 0; mt < 4; mt++) {
#pragma unroll
        for (int half = 0; half < 2; half++) {
            int gr = mblk * BM + wm * 64 + mt * 16 + g + half * 8;
            float* orow = C1 + (size_t)gr * Ncols;
#pragma unroll
            for (int nt = 0; nt < 4; nt++) {
                int col = n0 + wn * 32 + nt * 8 + tig * 2;
                float v0 = softplusf(acc[mt][nt][half*2+0] + bias[col]);
                float v1 = softplusf(acc[mt][nt][half*2+1] + bias[col+1]);
                *(float2*)(orow + col) = make_float2(v0, v1);
            }
        }
    }
}

// ---------------- fp16 single-pass GEMM (MoE up/down), expert-batched ----------
// blockIdx.z = expert.
// MODE 1: A (g_sF) gathered via g_list; nblk<16 -> g_Gh, else g_Uh (fp16 pair stores)
// MODE 2: A compact per-expert rows; Cf[(e*NN+gr),:] = g_rs[row] * acc (float store)
template<int MODE>
__global__ __launch_bounds__(256, 2)
void gemm_hf(const u32* __restrict__ A,
             const u32* __restrict__ B1, const u32* __restrict__ B2,
             float* __restrict__ Cf, u32* __restrict__ Ch1, u32* __restrict__ Ch2,
             int Ncols, int K)
{
    extern __shared__ u32 sm[];
    int* sidx = (int*)(sm + 4 * ABUF);

    int e = blockIdx.z;
    int M = g_cnt[e];
    int mblk = blockIdx.y;
    if (mblk * BM >= M) return;
    int nblk = blockIdx.x;
    int K2 = K / 2;

    const u32* Bp = B1 + (size_t)e * Ncols * K2;
    u32* Chout = Ch1;
    int nb = nblk;
    if (MODE == 1 && nblk >= 16) {
        Bp = B2 + (size_t)e * Ncols * K2;
        Chout = Ch2; nb = nblk - 16;
    }
    int n0 = nb * BN;
    int tid = threadIdx.x;

    if (MODE == 1) {
        const int* rowidx = g_list + (size_t)e * NN;
        for (int i = tid; i < BM; i += 256) {
            int gr = mblk * BM + i;
            sidx[i] = (gr < M) ? rowidx[gr] : -1;
        }
        __syncthreads();
    }

    int crow = tid >> 1;
    int cseg = (tid & 1) * 8;
    int asz;
    size_t abase;
    if (MODE == 1) {
        int s = sidx[crow];
        asz = (s >= 0) ? 16 : 0;
        abase = (size_t)(s >= 0 ? s : 0) * K2 + cseg;
    } else {
        int gr = mblk * BM + crow;
        asz = (gr < M) ? 16 : 0;
        abase = ((size_t)e * NN + (gr < M ? gr : 0)) * K2 + cseg;
    }
    size_t bbase = (size_t)(n0 + crow) * K2 + cseg;

    int wid = tid >> 5, lane = tid & 31;
    int g = lane >> 2, tig = lane & 3;
    int wm = wid >> 2, wn = wid & 3;

    u32 aoffL = (u32)((wm * 64 + (lane & 15)) * STR + (lane >> 4) * 4);
    u32 boffL = (u32)((wn * 32 + ((lane >> 4) << 3) + (lane & 7)) * STR + ((lane >> 3) & 1) * 4);

    float acc[4][4][4];
#pragma unroll
    for (int i = 0; i < 4; i++)
#pragma unroll
        for (int j = 0; j < 4; j++)
#pragma unroll
            for (int k = 0; k < 4; k++) acc[i][j][k] = 0.f;

    int KT = K2 / KP;
    int buf = 0;
    u32 sdst = crow * STR + cseg;

    {
        u32* s0 = sm;
        cp_async16z(s0 + 0*ABUF + sdst,     A + abase,      asz);
        cp_async16z(s0 + 0*ABUF + sdst + 4, A + abase + 4,  asz);
        cp_async16z(s0 + 1*ABUF + sdst,     Bp + bbase,     16);
        cp_async16z(s0 + 1*ABUF + sdst + 4, Bp + bbase + 4, 16);
        cp_commit();
    }

    for (int kt = 0; kt < KT; kt++) {
        if (kt + 1 < KT) {
            u32* s1 = sm + (buf ^ 1) * 2 * ABUF;
            size_t ao = abase + (size_t)(kt + 1) * KP;
            size_t bo = bbase + (size_t)(kt + 1) * KP;
            cp_async16z(s1 + 0*ABUF + sdst,     A + ao,      asz);
            cp_async16z(s1 + 0*ABUF + sdst + 4, A + ao + 4,  asz);
            cp_async16z(s1 + 1*ABUF + sdst,     Bp + bo,     16);
            cp_async16z(s1 + 1*ABUF + sdst + 4, Bp + bo + 4, 16);
            cp_commit();
            cp_wait<1>();
        } else {
            cp_wait<0>();
        }
        __syncthreads();

        u32 aA = (u32)__cvta_generic_to_shared(sm + buf * 2 * ABUF);
        u32 aB = aA + ABUF * 4;

#pragma unroll
        for (int ks = 0; ks < 2; ks++) {
            int kb = ks * 8;
            u32 ah[4][4];
#pragma unroll
            for (int mt = 0; mt < 4; mt++) {
                u32 off = (aoffL + mt * 16 * STR + kb) * 4;
                ldsm_x4(ah[mt][0], ah[mt][1], ah[mt][2], ah[mt][3], aA + off);
            }
            u32 bh[4][2];
#pragma unroll
            for (int np = 0; np < 2; np++) {
                u32 off = (boffL + np * 16 * STR + kb) * 4;
                ldsm_x4(bh[2*np][0], bh[2*np][1], bh[2*np+1][0], bh[2*np+1][1], aB + off);
            }
#pragma unroll
            for (int mt = 0; mt < 4; mt++)
#pragma unroll
                for (int nt = 0; nt < 4; nt++)
                    mma_f16(acc[mt][nt], ah[mt], bh[nt]);
        }
        __syncthreads();
        buf ^= 1;
    }

#pragma unroll
    for (int mt = 0; mt < 4; mt++) {
#pragma unroll
        for (int half = 0; half < 2; half++) {
            int lr = wm * 64 + mt * 16 + g + half * 8;
            int gr = mblk * BM + lr;
            if (gr >= M) continue;
            if (MODE == 1) {
                u32* orow = Chout + ((size_t)e * NN + gr) * (Ncols / 2);
#pragma unroll
                for (int nt = 0; nt < 4; nt++) {
                    int col = n0 + wn * 32 + nt * 8 + tig * 2;
                    orow[col >> 1] = pack_h2(acc[mt][nt][half*2+0], acc[mt][nt][half*2+1]);
                }
            } else {
                float rs = g_rs[(size_t)e * NN + gr];
                float* orow = Cf + ((size_t)e * NN + gr) * Ncols;
#pragma unroll
                for (int nt = 0; nt < 4; nt++) {
                    int col = n0 + wn * 32 + nt * 8 + tig * 2;
                    *(float2*)(orow + col) =
                        make_float2(rs * acc[mt][nt][half*2+0], rs * acc[mt][nt][half*2+1]);
                }
            }
        }
    }
}

// ---------------- small projections: Bm, Cm (from x) ----------------
__global__ __launch_bounds__(128)
void proj_small(const float* __restrict__ x, const float* __restrict__ WB,
                const float* __restrict__ WC)
{
    int n = blockIdx.x;
    __shared__ float xs[DD];
    const float* xr = x + (size_t)n * DD;
    for (int i = threadIdx.x; i < DD; i += 128) xs[i] = xr[i];
    __syncthreads();
    int warp = threadIdx.x >> 5, lane = threadIdx.x & 31;
    for (int c = warp; c < 32; c += 4) {
        const float* W; int col; float* out;
        if (c < 16) { W = WB; col = c;      out = g_Bm + (size_t)n * SS + col; }
        else        { W = WC; col = c - 16; out = g_Cm + (size_t)n * SS + col; }
        float s = 0.f;
        for (int k = lane; k < DD; k += 32)
            s = fmaf(xs[k], W[(size_t)k * SS + col], s);
        s += __shfl_xor_sync(~0u, s, 16);
        s += __shfl_xor_sync(~0u, s, 8);
        s += __shfl_xor_sync(~0u, s, 4);
        s += __shfl_xor_sync(~0u, s, 2);
        s += __shfl_xor_sync(~0u, s, 1);
        if (lane == 0) *out = s;
    }
}

// ---------------- selective scan: hoisted coefficients, short chain ------------
#define SPQ 168   // q-stride in sp (== 8 mod 32 for conflict-free reads)
__global__ __launch_bounds__(128)
void scan_kernel(const float* __restrict__ x, const float* __restrict__ A_log,
                 const float* __restrict__ D_param)
{
    int b = blockIdx.x >> 7;
    int dchunk = blockIdx.x & 127;    // 8 d's per chunk
    int dl = threadIdx.x >> 4;        // 0..7
    int s  = threadIdx.x & 15;        // state
    int d = dchunk * 8 + dl;

    float A_ds = -__expf(A_log[d * SS + s]);

    __shared__ float sx[16][8], sd[16][8];
    __shared__ float sB[16][17], sC[16][17];
    __shared__ float sp[16 * SPQ];    // [q][s*10 + dl]
    __shared__ float sDp[8];

    int tt = threadIdx.x >> 3;        // 0..15
    int cc = threadIdx.x & 7;         // 0..7
    int t2 = threadIdx.x >> 4;        // 0..7
    int c16 = threadIdx.x & 15;
    const int base_bt = b * LL;

    if (threadIdx.x < 8) sDp[threadIdx.x] = D_param[dchunk * 8 + threadIdx.x];

    size_t xoff = ((size_t)(base_bt + tt)) * DD + dchunk * 8 + cc;
    float rx = x[xoff];
    float rd = g_delta[xoff];
    size_t boff0 = ((size_t)(base_bt + t2)) * SS + c16;
    size_t boff1 = ((size_t)(base_bt + t2 + 8)) * SS + c16;
    float rB0 = g_Bm[boff0], rB1 = g_Bm[boff1];
    float rC0 = g_Cm[boff0], rC1 = g_Cm[boff1];

    float h = 0.f;
    for (int t0 = 0; t0 < LL; t0 += 16) {
        __syncthreads();
        sx[tt][cc] = rx; sd[tt][cc] = rd;
        sB[t2][c16] = rB0; sB[t2 + 8][c16] = rB1;
        sC[t2][c16] = rC0; sC[t2 + 8][c16] = rC1;
        __syncthreads();
        if (t0 + 16 < LL) {
            size_t xo = ((size_t)(base_bt + t0 + 16 + tt)) * DD + dchunk * 8 + cc;
            rx = x[xo]; rd = g_delta[xo];
            size_t bo0 = ((size_t)(base_bt + t0 + 16 + t2)) * SS + c16;
            size_t bo1 = ((size_t)(base_bt + t0 + 24 + t2)) * SS + c16;
            rB0 = g_Bm[bo0]; rB1 = g_Bm[bo1];
            rC0 = g_Cm[bo0]; rC1 = g_Cm[bo1];
        }
        float av[16], bx[16];
#pragma unroll
        for (int q = 0; q < 16; q++) {
            float dv = sd[q][dl];
            av[q] = __expf(fminf(dv * A_ds, 10.f));
            bx[q] = fminf(fmaxf(dv * sB[q][s], -10.f), 10.f) * sx[q][dl];
        }
        float p[16];
#pragma unroll
        for (int q = 0; q < 16; q++) {
            h = fminf(fmaxf(fmaf(av[q], h, bx[q]), -10000.f), 10000.f);
            p[q] = h * sC[q][s];
        }
#pragma unroll
        for (int q = 0; q < 16; q++)
            sp[q * SPQ + s * 10 + dl] = p[q];
        __syncthreads();
        int q2 = tt, d2 = cc;
        float ysum = 0.f;
#pragma unroll
        for (int s2 = 0; s2 < 16; s2++)
            ysum += sp[q2 * SPQ + s2 * 10 + d2];
        float y = fmaf(sx[q2][d2], sDp[d2], ysum);
        size_t yo = ((size_t)(base_bt + t0 + q2)) * DD + dchunk * 8 + d2;
        g_ssm[yo] = y;
        float yn = __shfl_down_sync(~0u, y, 1);
        if (!(d2 & 1)) {
            float ya = fminf(fmaxf(y,  -60000.f), 60000.f);
            float yb = fminf(fmaxf(yn, -60000.f), 60000.f);
            size_t po = ((size_t)(base_bt + t0 + q2)) * (DD/2) + dchunk * 4 + (d2 >> 1);
            g_sF[po] = pack_h2(ya, yb);
        }
    }
}

// ---------------- router on SSM output: softmax, top-2, expert lists ----------
__global__ __launch_bounds__(128)
void router_kernel(const float* __restrict__ WR)
{
    int n = blockIdx.x;
    __shared__ float xs[DD];
    __shared__ float logits[EE];
    const float* xr = g_ssm + (size_t)n * DD;
    for (int i = threadIdx.x; i < DD; i += 128) xs[i] = xr[i];
    __syncthreads();
    int warp = threadIdx.x >> 5, lane = threadIdx.x & 31;
    {
        float s = 0.f;
        for (int k = lane; k < DD; k += 32)
            s = fmaf(xs[k], WR[(size_t)k * EE + warp], s);
        s += __shfl_xor_sync(~0u, s, 16);
        s += __shfl_xor_sync(~0u, s, 8);
        s += __shfl_xor_sync(~0u, s, 4);
        s += __shfl_xor_sync(~0u, s, 2);
        s += __shfl_xor_sync(~0u, s, 1);
        if (lane == 0) logits[warp] = s;
    }
    __syncthreads();
    if (threadIdx.x == 0) {
        float l[4] = {logits[0], logits[1], logits[2], logits[3]};
        float m = fmaxf(fmaxf(l[0], l[1]), fmaxf(l[2], l[3]));
        float e[4], sum = 0.f;
#pragma unroll
        for (int i = 0; i < 4; i++) { e[i] = __expf(l[i] - m); sum += e[i]; }
        float p[4];
#pragma unroll
        for (int i = 0; i < 4; i++) p[i] = e[i] / sum;
        int i0 = 0;
#pragma unroll
        for (int i = 1; i < 4; i++) if (p[i] > p[i0]) i0 = i;
        int i1 = -1;
#pragma unroll
        for (int i = 0; i < 4; i++) {
            if (i == i0) continue;
            if (i1 < 0 || p[i] > p[i1]) i1 = i;
        }
        float w0 = p[i0], w1 = p[i1];
        float sw = w0 + w1 + 1e-9f;
        w0 /= sw; w1 /= sw;
        int pos = atomicAdd(&g_cnt[i0], 1);
        g_list[i0*NN + pos] = n; g_cw[i0*NN + pos] = w0;
        g_loc[n] = i0 * NN + pos;
        pos = atomicAdd(&g_cnt[i1], 1);
        g_list[i1*NN + pos] = n; g_cw[i1*NN + pos] = w1;
        g_loc[NN + n] = i1 * NN + pos;
    }
}

// ---------------- v = silu(G)*U (fp16 out, single pass) + row scale -----------
__global__ __launch_bounds__(256)
void act_norm()
{
    int i = blockIdx.x;
    int e = blockIdx.y;
    if (i >= g_cnt[e]) return;
    size_t row = (size_t)e * NN + i;
    __shared__ float red[8];
    float ss = 0.f;
#pragma unroll
    for (int it = 0; it < 4; it++) {
        int j2 = threadIdx.x + it * 256;
        float2 gg = __half22float2(*(const __half2*)&g_Gh[row * (HH/2) + j2]);
        float2 uu = __half22float2(*(const __half2*)&g_Uh[row * (HH/2) + j2]);
        float v0 = fsilu(gg.x) * uu.x;
        float v1 = fsilu(gg.y) * uu.y;
        g_aF[row * (HH/2) + j2] = pack_h2(v0, v1);
        ss = fmaf(v0, v0, fmaf(v1, v1, ss));
    }
    ss += __shfl_xor_sync(~0u, ss, 16);
    ss += __shfl_xor_sync(~0u, ss, 8);
    ss += __shfl_xor_sync(~0u, ss, 4);
    ss += __shfl_xor_sync(~0u, ss, 2);
    ss += __shfl_xor_sync(~0u, ss, 1);
    if ((threadIdx.x & 31) == 0) red[threadIdx.x >> 5] = ss;
    __syncthreads();
    if (threadIdx.x == 0) {
        float v = red[0] + red[1] + red[2] + red[3]
                + red[4] + red[5] + red[6] + red[7];
        g_rs[row] = g_cw[row] * rsqrtf(v / (float)HH + 1e-6f);
    }
}

// ---------------- final rmsnorm over (ssm + Dn[loc0] + Dn[loc1]) --------------
__global__ __launch_bounds__(256)
void final_norm(const float* __restrict__ norm_w, float* __restrict__ out)
{
    int n = blockIdx.x;
    __shared__ float red[8];
    __shared__ float buf[DD];
    int l0 = g_loc[n], l1 = g_loc[NN + n];
    const float* r0 = g_Dn + (size_t)l0 * DD;
    const float* r1 = g_Dn + (size_t)l1 * DD;
    const float* rs = g_ssm + (size_t)n * DD;
    float ss = 0.f;
    for (int j = threadIdx.x; j < DD; j += 256) {
        float v = rs[j] + r0[j] + r1[j];
        buf[j] = v;
        ss = fmaf(v, v, ss);
    }
    ss += __shfl_xor_sync(~0u, ss, 16);
    ss += __shfl_xor_sync(~0u, ss, 8);
    ss += __shfl_xor_sync(~0u, ss, 4);
    ss += __shfl_xor_sync(~0u, ss, 2);
    ss += __shfl_xor_sync(~0u, ss, 1);
    if ((threadIdx.x & 31) == 0) red[threadIdx.x >> 5] = ss;
    __syncthreads();
    if (threadIdx.x < 32) {
        float v = (threadIdx.x < 8) ? red[threadIdx.x] : 0.f;
        v += __shfl_xor_sync(~0u, v, 4);
        v += __shfl_xor_sync(~0u, v, 2);
        v += __shfl_xor_sync(~0u, v, 1);
        if (threadIdx.x == 0) red[0] = v;
    }
    __syncthreads();
    float inv = rsqrtf(red[0] / (float)DD + 1e-6f);
    for (int j = threadIdx.x; j < DD; j += 256)
        out[(size_t)n * DD + j] = norm_w[j] * buf[j] * inv;
}

// ---------------- launch ----------------
extern "C" void kernel_launch(void* const* d_in, const int* in_sizes, int n_in,
                              void* d_out, int out_size)
{
    const float* x        = (const float*)d_in[0];
    const float* A_log    = (const float*)d_in[1];
    const float* D_param  = (const float*)d_in[2];
    const float* W_delta  = (const float*)d_in[3];
    const float* b_delta  = (const float*)d_in[4];
    const float* W_B      = (const float*)d_in[5];
    const float* W_C      = (const float*)d_in[6];
    const float* W_router = (const float*)d_in[7];
    const float* Wg       = (const float*)d_in[8];
    const float* Wu       = (const float*)d_in[9];
    const float* Wd       = (const float*)d_in[10];
    const float* wn_exp   = (const float*)d_in[11];
    const float* norm_w   = (const float*)d_in[12];
    float* out = (float*)d_out;

    float *p_delta, *p_Dn;
    u32 *p_xHi, *p_xLo, *p_sF, *p_aF, *p_Gh, *p_Uh;
    u32 *p_WdHi, *p_WdLo, *p_WgF, *p_WuF, *p_WnF;
    cudaGetSymbolAddress((void**)&p_delta, g_delta);
    cudaGetSymbolAddress((void**)&p_Gh,    g_Gh);
    cudaGetSymbolAddress((void**)&p_Uh,    g_Uh);
    cudaGetSymbolAddress((void**)&p_Dn,    g_Dn);
    cudaGetSymbolAddress((void**)&p_xHi,   g_xHi);
    cudaGetSymbolAddress((void**)&p_xLo,   g_xLo);
    cudaGetSymbolAddress((void**)&p_sF,    g_sF);
    cudaGetSymbolAddress((void**)&p_aF,    g_aF);
    cudaGetSymbolAddress((void**)&p_WdHi,  g_WdHi);
    cudaGetSymbolAddress((void**)&p_WdLo,  g_WdLo);
    cudaGetSymbolAddress((void**)&p_WgF,   g_WgF);
    cudaGetSymbolAddress((void**)&p_WuF,   g_WuF);
    cudaGetSymbolAddress((void**)&p_WnF,   g_WnF);

    cudaFuncSetAttribute(gemm_bf,    cudaFuncAttributeMaxDynamicSharedMemorySize, GEMM_SMEM_BYTES);
    cudaFuncSetAttribute(gemm_hf<1>, cudaFuncAttributeMaxDynamicSharedMemorySize, GEMMH_SMEM_BYTES);
    cudaFuncSetAttribute(gemm_hf<2>, cudaFuncAttributeMaxDynamicSharedMemorySize, GEMMH_SMEM_BYTES);

    zero_counts<<<1, 32>>>();

    // operand pre-conversion
    {
        int n2 = NN * DD / 2;
        split_x_kernel<<<(n2 + 255) / 256, 256>>>(x, p_xHi, p_xLo, n2);
    }
    {
        dim3 blk(32, 8);
        dim3 gWdel(DD/2/32, DD/32, 1);
        split_w_kernel<<<gWdel, blk>>>(W_delta, p_WdHi, p_WdLo, DD, DD);
        dim3 gUp(DD/2/32, HH/32, EE);
        split_w_h_kernel<<<gUp, blk>>>(Wg, p_WgF, DD, HH, nullptr);
        split_w_h_kernel<<<gUp, blk>>>(Wu, p_WuF, DD, HH, nullptr);
        dim3 gDn(HH/2/32, DD/32, EE);
        split_w_h_kernel<<<gDn, blk>>>(Wd, p_WnF, HH, DD, wn_exp);  // folds wn
    }

    // delta = softplus(x @ W_delta + b)   [bf16x2 3-pass]
    {
        dim3 grid(DD / BN, NN / BM);
        gemm_bf<<<grid, 256, GEMM_SMEM_BYTES>>>(
            p_xHi, p_xLo, p_WdHi, p_WdLo, p_delta, b_delta, NN, DD, DD);
    }

    // Bm, Cm from x
    proj_small<<<NN, 128>>>(x, W_B, W_C);

    // selective scan -> g_ssm / fp16 ssm
    scan_kernel<<<BB * (DD / 8), 128>>>(x, A_log, D_param);

    // router on SSM output
    router_kernel<<<NN, 128>>>(W_router);

    // MoE, all experts batched:
    gemm_hf<1><<<dim3(2 * HH / BN, NN / BM, EE), 256, GEMMH_SMEM_BYTES>>>(
        p_sF, p_WgF, p_WuF, nullptr, p_Gh, p_Uh, HH, DD);
    act_norm<<<dim3(NN, EE), 256>>>();
    gemm_hf<2><<<dim3(DD / BN, NN / BM, EE), 256, GEMMH_SMEM_BYTES>>>(
        p_aF, p_WnF, nullptr, p_Dn, nullptr, nullptr, DD, HH);

    // out = rmsnorm(ssm + Dn[loc0] + Dn[loc1], norm_w)
    final_norm<<<NN, 256>>>(norm_w, out);
}

// round 14
// speedup vs baseline: 1.0821x; 1.0199x over previous
#include <cuda_runtime.h>
#include <cuda_bf16.h>
#include <cuda_fp16.h>
#include <math.h>
#include <stdint.h>

// Problem dims (fixed)
#define BB 2
#define LL 2048
#define DD 1024
#define SS 16
#define EE 4
#define HH 2048
#define NN (BB*LL)   // 4096

typedef uint32_t u32;

// ---------------- scratch (device globals; no allocation allowed) ----------------
__device__ float g_delta[NN*DD];
__device__ float g_Bm[NN*SS];
__device__ float g_Cm[NN*SS];
__device__ float g_ssm[NN*DD];
__device__ int   g_cnt[EE];
__device__ int   g_list[EE*NN];
__device__ float g_cw[EE*NN];
__device__ float g_rs[EE*NN];            // per compact row: cw * rsqrt(mean(v^2)+eps)
__device__ int   g_loc[2*NN];            // token -> (e*NN + pos), two entries
__device__ u32   g_Gh[(size_t)EE*NN*HH/2];  // per-expert compact G (fp16 pairs)
__device__ u32   g_Uh[(size_t)EE*NN*HH/2];  // per-expert compact U (fp16 pairs)
__device__ float g_Dn[(size_t)EE*NN*DD]; // per-expert compact down output

// bf16x2 split operands for delta GEMM (packed: low16 = even k, high16 = odd k)
__device__ u32 g_xHi[NN*DD/2],   g_xLo[NN*DD/2];      // x           [NN][512]
__device__ u32 g_WdHi[DD*DD/2],  g_WdLo[DD*DD/2];     // W_delta^T   [D][512]
// fp16 single-precision MoE operands (pair-packed)
__device__ u32 g_sF[NN*DD/2];                         // ssm  (fp16 pairs)
__device__ u32 g_aF[(size_t)EE*NN*HH/2];              // act v (fp16 pairs, per-expert)
__device__ u32 g_WgF[EE*HH*DD/2];                     // Wg^T  [e][H][512]
__device__ u32 g_WuF[EE*HH*DD/2];                     // Wu^T  [e][H][512]
__device__ u32 g_WnF[EE*DD*HH/2];                     // (wn*Wd)^T  [e][D][1024]

// ---------------- FMA-only helpers ----------------
__device__ __forceinline__ float fexpf(float x) {
    x = fmaxf(x, -87.3f);
    float t = fmaf(x, 1.4426950408889634f, 12582912.f);
    float n = t - 12582912.f;
    float r = fmaf(n, -0.693359375f, x);
    r = fmaf(n, 2.12194440e-4f, r);
    float z = r * r;
    float p =          1.9875691500E-4f;
    p = fmaf(p, r,     1.3981999507E-3f);
    p = fmaf(p, r,     8.3334519073E-3f);
    p = fmaf(p, r,     4.1665795894E-2f);
    p = fmaf(p, r,     1.6666665459E-1f);
    p = fmaf(p, r,     5.0000001201E-1f);
    float res = fmaf(p, z, r) + 1.f;
    int e = (int)n;
    return __int_as_float(__float_as_int(res) + (e << 23));
}

__device__ __forceinline__ float flogf(float u) {   // u >= 1
    int iu = __float_as_int(u);
    int e = ((iu >> 23) & 255) - 127;
    float m = __int_as_float((iu & 0x007FFFFF) | 0x3F800000);
    if (m > 1.41421356f) { m *= 0.5f; e += 1; }
    float f = m - 1.f;
    float z = f * f;
    float p =          7.0376836292E-2f;
    p = fmaf(p, f,    -1.1514610310E-1f);
    p = fmaf(p, f,     1.1676998740E-1f);
    p = fmaf(p, f,    -1.2420140846E-1f);
    p = fmaf(p, f,     1.4249322787E-1f);
    p = fmaf(p, f,    -1.6668057665E-1f);
    p = fmaf(p, f,     2.0000714765E-1f);
    p = fmaf(p, f,    -2.4999993993E-1f);
    p = fmaf(p, f,     3.3333331174E-1f);
    float y = fmaf(z * f, p, -0.5f * z);
    float res = f + y;
    return fmaf((float)e, 0.69314718056f, res);
}

__device__ __forceinline__ float softplusf(float z) {
    if (z > 20.f) return z;
    return flogf(1.f + fexpf(z));
}

__device__ __forceinline__ float frecip12(float d) {  // d in (1, 2]
    float r = __int_as_float(0x7EF311C3 - __float_as_int(d));
    r = r * fmaf(-d, r, 2.f);
    r = r * fmaf(-d, r, 2.f);
    return r;
}

__device__ __forceinline__ float fsilu(float g) {   // g * sigmoid(g)
    float e = fexpf(-fabsf(g));
    float r = frecip12(1.f + e);
    float num = (g >= 0.f) ? 1.f : e;
    return g * num * r;
}

__device__ __forceinline__ void split2(float a, float b, u32& hi, u32& lo) {
    __nv_bfloat16 ah = __float2bfloat16(a);
    __nv_bfloat16 bh = __float2bfloat16(b);
    float ra = a - __bfloat162float(ah);
    float rb = b - __bfloat162float(bh);
    __nv_bfloat16 al = __float2bfloat16(ra);
    __nv_bfloat16 bl = __float2bfloat16(rb);
    hi = ((u32)__bfloat16_as_ushort(bh) << 16) | __bfloat16_as_ushort(ah);
    lo = ((u32)__bfloat16_as_ushort(bl) << 16) | __bfloat16_as_ushort(al);
}

__device__ __forceinline__ u32 pack_h2(float a, float b) {
    __half2 h = __floats2half2_rn(a, b);
    return *reinterpret_cast<u32*>(&h);
}

// ---------------- zero counts ----------------
__global__ void zero_counts() {
    if (threadIdx.x < EE) g_cnt[threadIdx.x] = 0;
}

// ---------------- split x (bf16 pairs, row-major) ----------------
__global__ __launch_bounds__(256)
void split_x_kernel(const float* __restrict__ in, u32* __restrict__ oh,
                    u32* __restrict__ ol, int n2) {
    int i = blockIdx.x * blockDim.x + threadIdx.x;
    if (i < n2) {
        float2 v = ((const float2*)in)[i];
        u32 hi, lo; split2(v.x, v.y, hi, lo);
        oh[i] = hi; ol[i] = lo;
    }
}

// ---------------- split + transpose W_delta (bf16 pairs) ----------------
__global__ __launch_bounds__(256)
void split_w_kernel(const float* __restrict__ W, u32* __restrict__ oh,
                    u32* __restrict__ ol, int K, int N) {
    int K2 = K / 2;
    __shared__ u32 th[32][33], tl[32][33];
    int kp0 = blockIdx.x * 32, n0 = blockIdx.y * 32;
    int tx = threadIdx.x, ty = threadIdx.y;
#pragma unroll
    for (int r = 0; r < 4; r++) {
        int kp = kp0 + ty + r * 8;
        int n  = n0 + tx;
        float w0 = W[(size_t)(2 * kp) * N + n];
        float w1 = W[(size_t)(2 * kp + 1) * N + n];
        u32 hi, lo; split2(w0, w1, hi, lo);
        th[ty + r * 8][tx] = hi;
        tl[ty + r * 8][tx] = lo;
    }
    __syncthreads();
#pragma unroll
    for (int r = 0; r < 4; r++) {
        int n  = n0 + ty + r * 8;
        int kp = kp0 + tx;
        oh[(size_t)n * K2 + kp] = th[tx][ty + r * 8];
        ol[(size_t)n * K2 + kp] = tl[tx][ty + r * 8];
    }
}

// ---------------- convert + transpose MoE weight (single fp16 pairs) ----------
// wn != nullptr: multiply row k by wn[e][k] (folds rmsnorm weight into W_down)
__global__ __launch_bounds__(256)
void split_w_h_kernel(const float* __restrict__ W, u32* __restrict__ o,
                      int K, int N, const float* __restrict__ wn) {
    int K2 = K / 2;
    size_t eoffW = (size_t)blockIdx.z * K * N;
    size_t eoffO = (size_t)blockIdx.z * N * K2;
    const float* wne = wn ? (wn + (size_t)blockIdx.z * K) : nullptr;
    __shared__ u32 th[32][33];
    int kp0 = blockIdx.x * 32, n0 = blockIdx.y * 32;
    int tx = threadIdx.x, ty = threadIdx.y;
#pragma unroll
    for (int r = 0; r < 4; r++) {
        int kp = kp0 + ty + r * 8;
        int n  = n0 + tx;
        float w0 = W[eoffW + (size_t)(2 * kp) * N + n];
        float w1 = W[eoffW + (size_t)(2 * kp + 1) * N + n];
        if (wne) { w0 *= wne[2 * kp]; w1 *= wne[2 * kp + 1]; }
        th[ty + r * 8][tx] = pack_h2(w0, w1);
    }
    __syncthreads();
#pragma unroll
    for (int r = 0; r < 4; r++) {
        int n  = n0 + ty + r * 8;
        int kp = kp0 + tx;
        o[eoffO + (size_t)n * K2 + kp] = th[tx][ty + r * 8];
    }
}

// ---------------- cp.async helpers ----------------
__device__ __forceinline__ void cp_async16z(void* dst, const void* src, int sz) {
    u32 d = (u32)__cvta_generic_to_shared(dst);
    asm volatile("cp.async.ca.shared.global [%0], [%1], 16, %2;\n"
                 :: "r"(d), "l"(src), "r"(sz) : "memory");
}
__device__ __forceinline__ void cp_commit() {
    asm volatile("cp.async.commit_group;\n" ::: "memory");
}
template<int N> __device__ __forceinline__ void cp_wait() {
    asm volatile("cp.async.wait_group %0;\n" :: "n"(N) : "memory");
}

// ---------------- mma / ldmatrix ----------------
__device__ __forceinline__ void mma_bf16(float* d, const u32* a, const u32* b) {
    asm volatile(
        "mma.sync.aligned.m16n8k16.row.col.f32.bf16.bf16.f32 "
        "{%0,%1,%2,%3}, {%4,%5,%6,%7}, {%8,%9}, {%0,%1,%2,%3};\n"
        : "+f"(d[0]), "+f"(d[1]), "+f"(d[2]), "+f"(d[3])
        : "r"(a[0]), "r"(a[1]), "r"(a[2]), "r"(a[3]), "r"(b[0]), "r"(b[1]));
}
__device__ __forceinline__ void mma_f16(float* d, const u32* a, const u32* b) {
    asm volatile(
        "mma.sync.aligned.m16n8k16.row.col.f32.f16.f16.f32 "
        "{%0,%1,%2,%3}, {%4,%5,%6,%7}, {%8,%9}, {%0,%1,%2,%3};\n"
        : "+f"(d[0]), "+f"(d[1]), "+f"(d[2]), "+f"(d[3])
        : "r"(a[0]), "r"(a[1]), "r"(a[2]), "r"(a[3]), "r"(b[0]), "r"(b[1]));
}
__device__ __forceinline__ void ldsm_x4(u32& r0, u32& r1, u32& r2, u32& r3, u32 addr) {
    asm volatile("ldmatrix.sync.aligned.m8n8.x4.shared.b16 {%0,%1,%2,%3}, [%4];"
                 : "=r"(r0), "=r"(r1), "=r"(r2), "=r"(r3) : "r"(addr));
}

#define BM 128
#define BN 128
#define KP 16            // k-pairs per tile (32 elements)
#define STR 20           // smem row stride in u32 (16 used + 4 pad)
#define ABUF (128*STR)   // 2560 u32 per array per buffer
#define GEMM_SMEM_BYTES  (12*ABUF*4 + BM*4)   // 3 stages x 4 arrays
#define GEMMH_SMEM_BYTES (6*ABUF*4 + BM*4)    // 3 stages x 2 arrays

// ---------------- bf16x2 3-pass GEMM (delta projection), 3-stage pipe ----------
__global__ __launch_bounds__(256, 1)
void gemm_bf(const u32* __restrict__ Ahi, const u32* __restrict__ Alo,
             const u32* __restrict__ Bhi, const u32* __restrict__ Blo,
             float* __restrict__ C1, const float* __restrict__ bias,
             int M, int Ncols, int K)
{
    extern __shared__ u32 sm[];

    int mblk = blockIdx.y;
    int nblk = blockIdx.x;
    int n0 = nblk * BN;
    int K2 = K / 2;
    int tid = threadIdx.x;

    int crow = tid >> 1;
    int cseg = (tid & 1) * 8;
    size_t abase = (size_t)(mblk * BM + crow) * K2 + cseg;
    size_t bbase = (size_t)(n0 + crow) * K2 + cseg;

    int wid = tid >> 5, lane = tid & 31;
    int g = lane >> 2, tig = lane & 3;
    int wm = wid >> 2, wn = wid & 3;

    u32 aoffL = (u32)((wm * 64 + (lane & 15)) * STR + (lane >> 4) * 4);
    u32 boffL = (u32)((wn * 32 + ((lane >> 4) << 3) + (lane & 7)) * STR + ((lane >> 3) & 1) * 4);

    float acc[4][4][4];
#pragma unroll
    for (int i = 0; i < 4; i++)
#pragma unroll
        for (int j = 0; j < 4; j++)
#pragma unroll
            for (int k = 0; k < 4; k++) acc[i][j][k] = 0.f;

    int KT = K2 / KP;
    u32 sdst = crow * STR + cseg;

    auto load_stage = [&](int kt, int st) {
        u32* s = sm + st * 4 * ABUF;
        size_t ao = abase + (size_t)kt * KP;
        size_t bo = bbase + (size_t)kt * KP;
        cp_async16z(s + 0*ABUF + sdst,     Ahi + ao,     16);
        cp_async16z(s + 0*ABUF + sdst + 4, Ahi + ao + 4, 16);
        cp_async16z(s + 1*ABUF + sdst,     Alo + ao,     16);
        cp_async16z(s + 1*ABUF + sdst + 4, Alo + ao + 4, 16);
        cp_async16z(s + 2*ABUF + sdst,     Bhi + bo,     16);
        cp_async16z(s + 2*ABUF + sdst + 4, Bhi + bo + 4, 16);
        cp_async16z(s + 3*ABUF + sdst,     Blo + bo,     16);
        cp_async16z(s + 3*ABUF + sdst + 4, Blo + bo + 4, 16);
        cp_commit();
    };

    load_stage(0, 0);
    load_stage(1, 1);

    for (int kt = 0; kt < KT; kt++) {
        if (kt == KT - 1) cp_wait<0>(); else cp_wait<1>();
        __syncthreads();
        if (kt + 2 < KT) load_stage(kt + 2, (kt + 2) % 3);

        int buf = kt % 3;
        u32 aAh = (u32)__cvta_generic_to_shared(sm + buf * 4 * ABUF);
        u32 aAl = aAh + ABUF * 4;
        u32 aBh = aAh + 2 * ABUF * 4;
        u32 aBl = aAh + 3 * ABUF * 4;

#pragma unroll
        for (int ks = 0; ks < 2; ks++) {
            int kb = ks * 8;
            u32 ah[4][4], al[4][4];
#pragma unroll
            for (int mt = 0; mt < 4; mt++) {
                u32 off = (aoffL + mt * 16 * STR + kb) * 4;
                ldsm_x4(ah[mt][0], ah[mt][1], ah[mt][2], ah[mt][3], aAh + off);
                ldsm_x4(al[mt][0], al[mt][1], al[mt][2], al[mt][3], aAl + off);
            }
            u32 bh[4][2], bl[4][2];
#pragma unroll
            for (int np = 0; np < 2; np++) {
                u32 off = (boffL + np * 16 * STR + kb) * 4;
                ldsm_x4(bh[2*np][0], bh[2*np][1], bh[2*np+1][0], bh[2*np+1][1], aBh + off);
                ldsm_x4(bl[2*np][0], bl[2*np][1], bl[2*np+1][0], bl[2*np+1][1], aBl + off);
            }
#pragma unroll
            for (int mt = 0; mt < 4; mt++)
#pragma unroll
                for (int nt = 0; nt < 4; nt++) {
                    mma_bf16(acc[mt][nt], ah[mt], bh[nt]);
                    mma_bf16(acc[mt][nt], ah[mt], bl[nt]);
                    mma_bf16(acc[mt][nt], al[mt], bh[nt]);
                }
        }
    }

#pragma unroll
    for (int mt = 0; mt < 4; mt++) {
#pragma unroll
        for (int half = 0; half < 2; half++) {
            int gr = mblk * BM + wm * 64 + mt * 16 + g + half * 8;
            float* orow = C1 + (size_t)gr * Ncols;
#pragma unroll
            for (int nt = 0; nt < 4; nt++) {
                int col = n0 + wn * 32 + nt * 8 + tig * 2;
                float v0 = softplusf(acc[mt][nt][half*2+0] + bias[col]);
                float v1 = softplusf(acc[mt][nt][half*2+1] + bias[col+1]);
                *(float2*)(orow + col) = make_float2(v0, v1);
            }
        }
    }
}

// ---------------- fp16 single-pass GEMM (MoE up/down), 3-stage, expert-batched --
// blockIdx.z = expert.
// MODE 1: A (g_sF) gathered via g_list; nblk<16 -> g_Gh, else g_Uh (fp16 pair stores)
// MODE 2: A compact per-expert rows; Cf[(e*NN+gr),:] = g_rs[row] * acc (float store)
template<int MODE>
__global__ __launch_bounds__(256, 2)
void gemm_hf(const u32* __restrict__ A,
             const u32* __restrict__ B1, const u32* __restrict__ B2,
             float* __restrict__ Cf, u32* __restrict__ Ch1, u32* __restrict__ Ch2,
             int Ncols, int K)
{
    extern __shared__ u32 sm[];
    int* sidx = (int*)(sm + 6 * ABUF);

    int e = blockIdx.z;
    int M = g_cnt[e];
    int mblk = blockIdx.y;
    if (mblk * BM >= M) return;
    int nblk = blockIdx.x;
    int K2 = K / 2;

    const u32* Bp = B1 + (size_t)e * Ncols * K2;
    u32* Chout = Ch1;
    int nb = nblk;
    if (MODE == 1 && nblk >= 16) {
        Bp = B2 + (size_t)e * Ncols * K2;
        Chout = Ch2; nb = nblk - 16;
    }
    int n0 = nb * BN;
    int tid = threadIdx.x;

    if (MODE == 1) {
        const int* rowidx = g_list + (size_t)e * NN;
        for (int i = tid; i < BM; i += 256) {
            int gr = mblk * BM + i;
            sidx[i] = (gr < M) ? rowidx[gr] : -1;
        }
        __syncthreads();
    }

    int crow = tid >> 1;
    int cseg = (tid & 1) * 8;
    int asz;
    size_t abase;
    if (MODE == 1) {
        int s = sidx[crow];
        asz = (s >= 0) ? 16 : 0;
        abase = (size_t)(s >= 0 ? s : 0) * K2 + cseg;
    } else {
        int gr = mblk * BM + crow;
        asz = (gr < M) ? 16 : 0;
        abase = ((size_t)e * NN + (gr < M ? gr : 0)) * K2 + cseg;
    }
    size_t bbase = (size_t)(n0 + crow) * K2 + cseg;

    int wid = tid >> 5, lane = tid & 31;
    int g = lane >> 2, tig = lane & 3;
    int wm = wid >> 2, wn = wid & 3;

    u32 aoffL = (u32)((wm * 64 + (lane & 15)) * STR + (lane >> 4) * 4);
    u32 boffL = (u32)((wn * 32 + ((lane >> 4) << 3) + (lane & 7)) * STR + ((lane >> 3) & 1) * 4);

    float acc[4][4][4];
#pragma unroll
    for (int i = 0; i < 4; i++)
#pragma unroll
        for (int j = 0; j < 4; j++)
#pragma unroll
            for (int k = 0; k < 4; k++) acc[i][j][k] = 0.f;

    int KT = K2 / KP;
    u32 sdst = crow * STR + cseg;

    auto load_stage = [&](int kt, int st) {
        u32* s = sm + st * 2 * ABUF;
        size_t ao = abase + (size_t)kt * KP;
        size_t bo = bbase + (size_t)kt * KP;
        cp_async16z(s + 0*ABUF + sdst,     A + ao,      asz);
        cp_async16z(s + 0*ABUF + sdst + 4, A + ao + 4,  asz);
        cp_async16z(s + 1*ABUF + sdst,     Bp + bo,     16);
        cp_async16z(s + 1*ABUF + sdst + 4, Bp + bo + 4, 16);
        cp_commit();
    };

    load_stage(0, 0);
    load_stage(1, 1);

    for (int kt = 0; kt < KT; kt++) {
        if (kt == KT - 1) cp_wait<0>(); else cp_wait<1>();
        __syncthreads();
        if (kt + 2 < KT) load_stage(kt + 2, (kt + 2) % 3);

        int buf = kt % 3;
        u32 aA = (u32)__cvta_generic_to_shared(sm + buf * 2 * ABUF);
        u32 aB = aA + ABUF * 4;

#pragma unroll
        for (int ks = 0; ks < 2; ks++) {
            int kb = ks * 8;
            u32 ah[4][4];
#pragma unroll
            for (int mt = 0; mt < 4; mt++) {
                u32 off = (aoffL + mt * 16 * STR + kb) * 4;
                ldsm_x4(ah[mt][0], ah[mt][1], ah[mt][2], ah[mt][3], aA + off);
            }
            u32 bh[4][2];
#pragma unroll
            for (int np = 0; np < 2; np++) {
                u32 off = (boffL + np * 16 * STR + kb) * 4;
                ldsm_x4(bh[2*np][0], bh[2*np][1], bh[2*np+1][0], bh[2*np+1][1], aB + off);
            }
#pragma unroll
            for (int mt = 0; mt < 4; mt++)
#pragma unroll
                for (int nt = 0; nt < 4; nt++)
                    mma_f16(acc[mt][nt], ah[mt], bh[nt]);
        }
    }

#pragma unroll
    for (int mt = 0; mt < 4; mt++) {
#pragma unroll
        for (int half = 0; half < 2; half++) {
            int lr = wm * 64 + mt * 16 + g + half * 8;
            int gr = mblk * BM + lr;
            if (gr >= M) continue;
            if (MODE == 1) {
                u32* orow = Chout + ((size_t)e * NN + gr) * (Ncols / 2);
#pragma unroll
                for (int nt = 0; nt < 4; nt++) {
                    int col = n0 + wn * 32 + nt * 8 + tig * 2;
                    orow[col >> 1] = pack_h2(acc[mt][nt][half*2+0], acc[mt][nt][half*2+1]);
                }
            } else {
                float rs = g_rs[(size_t)e * NN + gr];
                float* orow = Cf + ((size_t)e * NN + gr) * Ncols;
#pragma unroll
                for (int nt = 0; nt < 4; nt++) {
                    int col = n0 + wn * 32 + nt * 8 + tig * 2;
                    *(float2*)(orow + col) =
                        make_float2(rs * acc[mt][nt][half*2+0], rs * acc[mt][nt][half*2+1]);
                }
            }
        }
    }
}

// ---------------- small projections: Bm, Cm (from x) ----------------
__global__ __launch_bounds__(128)
void proj_small(const float* __restrict__ x, const float* __restrict__ WB,
                const float* __restrict__ WC)
{
    int n = blockIdx.x;
    __shared__ float xs[DD];
    const float* xr = x + (size_t)n * DD;
    for (int i = threadIdx.x; i < DD; i += 128) xs[i] = xr[i];
    __syncthreads();
    int warp = threadIdx.x >> 5, lane = threadIdx.x & 31;
    for (int c = warp; c < 32; c += 4) {
        const float* W; int col; float* out;
        if (c < 16) { W = WB; col = c;      out = g_Bm + (size_t)n * SS + col; }
        else        { W = WC; col = c - 16; out = g_Cm + (size_t)n * SS + col; }
        float s = 0.f;
        for (int k = lane; k < DD; k += 32)
            s = fmaf(xs[k], W[(size_t)k * SS + col], s);
        s += __shfl_xor_sync(~0u, s, 16);
        s += __shfl_xor_sync(~0u, s, 8);
        s += __shfl_xor_sync(~0u, s, 4);
        s += __shfl_xor_sync(~0u, s, 2);
        s += __shfl_xor_sync(~0u, s, 1);
        if (lane == 0) *out = s;
    }
}

// ---------------- selective scan: hoisted coefficients, short chain ------------
#define SPQ 168   // q-stride in sp (== 8 mod 32 for conflict-free reads)
__global__ __launch_bounds__(128)
void scan_kernel(const float* __restrict__ x, const float* __restrict__ A_log,
                 const float* __restrict__ D_param)
{
    int b = blockIdx.x >> 7;
    int dchunk = blockIdx.x & 127;    // 8 d's per chunk
    int dl = threadIdx.x >> 4;        // 0..7
    int s  = threadIdx.x & 15;        // state
    int d = dchunk * 8 + dl;

    float A_ds = -__expf(A_log[d * SS + s]);

    __shared__ float sx[16][8], sd[16][8];
    __shared__ float sB[16][17], sC[16][17];
    __shared__ float sp[16 * SPQ];    // [q][s*10 + dl]
    __shared__ float sDp[8];

    int tt = threadIdx.x >> 3;        // 0..15
    int cc = threadIdx.x & 7;         // 0..7
    int t2 = threadIdx.x >> 4;        // 0..7
    int c16 = threadIdx.x & 15;
    const int base_bt = b * LL;

    if (threadIdx.x < 8) sDp[threadIdx.x] = D_param[dchunk * 8 + threadIdx.x];

    size_t xoff = ((size_t)(base_bt + tt)) * DD + dchunk * 8 + cc;
    float rx = x[xoff];
    float rd = g_delta[xoff];
    size_t boff0 = ((size_t)(base_bt + t2)) * SS + c16;
    size_t boff1 = ((size_t)(base_bt + t2 + 8)) * SS + c16;
    float rB0 = g_Bm[boff0], rB1 = g_Bm[boff1];
    float rC0 = g_Cm[boff0], rC1 = g_Cm[boff1];

    float h = 0.f;
    for (int t0 = 0; t0 < LL; t0 += 16) {
        __syncthreads();
        sx[tt][cc] = rx; sd[tt][cc] = rd;
        sB[t2][c16] = rB0; sB[t2 + 8][c16] = rB1;
        sC[t2][c16] = rC0; sC[t2 + 8][c16] = rC1;
        __syncthreads();
        if (t0 + 16 < LL) {
            size_t xo = ((size_t)(base_bt + t0 + 16 + tt)) * DD + dchunk * 8 + cc;
            rx = x[xo]; rd = g_delta[xo];
            size_t bo0 = ((size_t)(base_bt + t0 + 16 + t2)) * SS + c16;
            size_t bo1 = ((size_t)(base_bt + t0 + 24 + t2)) * SS + c16;
            rB0 = g_Bm[bo0]; rB1 = g_Bm[bo1];
            rC0 = g_Cm[bo0]; rC1 = g_Cm[bo1];
        }
        float av[16], bx[16];
#pragma unroll
        for (int q = 0; q < 16; q++) {
            float dv = sd[q][dl];
            av[q] = __expf(fminf(dv * A_ds, 10.f));
            bx[q] = fminf(fmaxf(dv * sB[q][s], -10.f), 10.f) * sx[q][dl];
        }
        float p[16];
#pragma unroll
        for (int q = 0; q < 16; q++) {
            h = fminf(fmaxf(fmaf(av[q], h, bx[q]), -10000.f), 10000.f);
            p[q] = h * sC[q][s];
        }
#pragma unroll
        for (int q = 0; q < 16; q++)
            sp[q * SPQ + s * 10 + dl] = p[q];
        __syncthreads();
        int q2 = tt, d2 = cc;
        float ysum = 0.f;
#pragma unroll
        for (int s2 = 0; s2 < 16; s2++)
            ysum += sp[q2 * SPQ + s2 * 10 + d2];
        float y = fmaf(sx[q2][d2], sDp[d2], ysum);
        size_t yo = ((size_t)(base_bt + t0 + q2)) * DD + dchunk * 8 + d2;
        g_ssm[yo] = y;
        float yn = __shfl_down_sync(~0u, y, 1);
        if (!(d2 & 1)) {
            float ya = fminf(fmaxf(y,  -60000.f), 60000.f);
            float yb = fminf(fmaxf(yn, -60000.f), 60000.f);
            size_t po = ((size_t)(base_bt + t0 + q2)) * (DD/2) + dchunk * 4 + (d2 >> 1);
            g_sF[po] = pack_h2(ya, yb);
        }
    }
}

// ---------------- router on SSM output: softmax, top-2, expert lists ----------
__global__ __launch_bounds__(128)
void router_kernel(const float* __restrict__ WR)
{
    int n = blockIdx.x;
    __shared__ float xs[DD];
    __shared__ float logits[EE];
    const float* xr = g_ssm + (size_t)n * DD;
    for (int i = threadIdx.x; i < DD; i += 128) xs[i] = xr[i];
    __syncthreads();
    int warp = threadIdx.x >> 5, lane = threadIdx.x & 31;
    {
        float s = 0.f;
        for (int k = lane; k < DD; k += 32)
            s = fmaf(xs[k], WR[(size_t)k * EE + warp], s);
        s += __shfl_xor_sync(~0u, s, 16);
        s += __shfl_xor_sync(~0u, s, 8);
        s += __shfl_xor_sync(~0u, s, 4);
        s += __shfl_xor_sync(~0u, s, 2);
        s += __shfl_xor_sync(~0u, s, 1);
        if (lane == 0) logits[warp] = s;
    }
    __syncthreads();
    if (threadIdx.x == 0) {
        float l[4] = {logits[0], logits[1], logits[2], logits[3]};
        float m = fmaxf(fmaxf(l[0], l[1]), fmaxf(l[2], l[3]));
        float e[4], sum = 0.f;
#pragma unroll
        for (int i = 0; i < 4; i++) { e[i] = __expf(l[i] - m); sum += e[i]; }
        float p[4];
#pragma unroll
        for (int i = 0; i < 4; i++) p[i] = e[i] / sum;
        int i0 = 0;
#pragma unroll
        for (int i = 1; i < 4; i++) if (p[i] > p[i0]) i0 = i;
        int i1 = -1;
#pragma unroll
        for (int i = 0; i < 4; i++) {
            if (i == i0) continue;
            if (i1 < 0 || p[i] > p[i1]) i1 = i;
        }
        float w0 = p[i0], w1 = p[i1];
        float sw = w0 + w1 + 1e-9f;
        w0 /= sw; w1 /= sw;
        int pos = atomicAdd(&g_cnt[i0], 1);
        g_list[i0*NN + pos] = n; g_cw[i0*NN + pos] = w0;
        g_loc[n] = i0 * NN + pos;
        pos = atomicAdd(&g_cnt[i1], 1);
        g_list[i1*NN + pos] = n; g_cw[i1*NN + pos] = w1;
        g_loc[NN + n] = i1 * NN + pos;
    }
}

// ---------------- v = silu(G)*U (fp16 out, single pass) + row scale -----------
__global__ __launch_bounds__(256)
void act_norm()
{
    int i = blockIdx.x;
    int e = blockIdx.y;
    if (i >= g_cnt[e]) return;
    size_t row = (size_t)e * NN + i;
    __shared__ float red[8];
    float ss = 0.f;
#pragma unroll
    for (int it = 0; it < 4; it++) {
        int j2 = threadIdx.x + it * 256;
        float2 gg = __half22float2(*(const __half2*)&g_Gh[row * (HH/2) + j2]);
        float2 uu = __half22float2(*(const __half2*)&g_Uh[row * (HH/2) + j2]);
        float v0 = fsilu(gg.x) * uu.x;
        float v1 = fsilu(gg.y) * uu.y;
        g_aF[row * (HH/2) + j2] = pack_h2(v0, v1);
        ss = fmaf(v0, v0, fmaf(v1, v1, ss));
    }
    ss += __shfl_xor_sync(~0u, ss, 16);
    ss += __shfl_xor_sync(~0u, ss, 8);
    ss += __shfl_xor_sync(~0u, ss, 4);
    ss += __shfl_xor_sync(~0u, ss, 2);
    ss += __shfl_xor_sync(~0u, ss, 1);
    if ((threadIdx.x & 31) == 0) red[threadIdx.x >> 5] = ss;
    __syncthreads();
    if (threadIdx.x == 0) {
        float v = red[0] + red[1] + red[2] + red[3]
                + red[4] + red[5] + red[6] + red[7];
        g_rs[row] = g_cw[row] * rsqrtf(v / (float)HH + 1e-6f);
    }
}

// ---------------- final rmsnorm over (ssm + Dn[loc0] + Dn[loc1]) --------------
__global__ __launch_bounds__(256)
void final_norm(const float* __restrict__ norm_w, float* __restrict__ out)
{
    int n = blockIdx.x;
    __shared__ float red[8];
    __shared__ float buf[DD];
    int l0 = g_loc[n], l1 = g_loc[NN + n];
    const float* r0 = g_Dn + (size_t)l0 * DD;
    const float* r1 = g_Dn + (size_t)l1 * DD;
    const float* rs = g_ssm + (size_t)n * DD;
    float ss = 0.f;
    for (int j = threadIdx.x; j < DD; j += 256) {
        float v = rs[j] + r0[j] + r1[j];
        buf[j] = v;
        ss = fmaf(v, v, ss);
    }
    ss += __shfl_xor_sync(~0u, ss, 16);
    ss += __shfl_xor_sync(~0u, ss, 8);
    ss += __shfl_xor_sync(~0u, ss, 4);
    ss += __shfl_xor_sync(~0u, ss, 2);
    ss += __shfl_xor_sync(~0u, ss, 1);
    if ((threadIdx.x & 31) == 0) red[threadIdx.x >> 5] = ss;
    __syncthreads();
    if (threadIdx.x < 32) {
        float v = (threadIdx.x < 8) ? red[threadIdx.x] : 0.f;
        v += __shfl_xor_sync(~0u, v, 4);
        v += __shfl_xor_sync(~0u, v, 2);
        v += __shfl_xor_sync(~0u, v, 1);
        if (threadIdx.x == 0) red[0] = v;
    }
    __syncthreads();
    float inv = rsqrtf(red[0] / (float)DD + 1e-6f);
    for (int j = threadIdx.x; j < DD; j += 256)
        out[(size_t)n * DD + j] = norm_w[j] * buf[j] * inv;
}

// ---------------- launch ----------------
extern "C" void kernel_launch(void* const* d_in, const int* in_sizes, int n_in,
                              void* d_out, int out_size)
{
    const float* x        = (const float*)d_in[0];
    const float* A_log    = (const float*)d_in[1];
    const float* D_param  = (const float*)d_in[2];
    const float* W_delta  = (const float*)d_in[3];
    const float* b_delta  = (const float*)d_in[4];
    const float* W_B      = (const float*)d_in[5];
    const float* W_C      = (const float*)d_in[6];
    const float* W_router = (const float*)d_in[7];
    const float* Wg       = (const float*)d_in[8];
    const float* Wu       = (const float*)d_in[9];
    const float* Wd       = (const float*)d_in[10];
    const float* wn_exp   = (const float*)d_in[11];
    const float* norm_w   = (const float*)d_in[12];
    float* out = (float*)d_out;

    float *p_delta, *p_Dn;
    u32 *p_xHi, *p_xLo, *p_sF, *p_aF, *p_Gh, *p_Uh;
    u32 *p_WdHi, *p_WdLo, *p_WgF, *p_WuF, *p_WnF;
    cudaGetSymbolAddress((void**)&p_delta, g_delta);
    cudaGetSymbolAddress((void**)&p_Gh,    g_Gh);
    cudaGetSymbolAddress((void**)&p_Uh,    g_Uh);
    cudaGetSymbolAddress((void**)&p_Dn,    g_Dn);
    cudaGetSymbolAddress((void**)&p_xHi,   g_xHi);
    cudaGetSymbolAddress((void**)&p_xLo,   g_xLo);
    cudaGetSymbolAddress((void**)&p_sF,    g_sF);
    cudaGetSymbolAddress((void**)&p_aF,    g_aF);
    cudaGetSymbolAddress((void**)&p_WdHi,  g_WdHi);
    cudaGetSymbolAddress((void**)&p_WdLo,  g_WdLo);
    cudaGetSymbolAddress((void**)&p_WgF,   g_WgF);
    cudaGetSymbolAddress((void**)&p_WuF,   g_WuF);
    cudaGetSymbolAddress((void**)&p_WnF,   g_WnF);

    cudaFuncSetAttribute(gemm_bf,    cudaFuncAttributeMaxDynamicSharedMemorySize, GEMM_SMEM_BYTES);
    cudaFuncSetAttribute(gemm_hf<1>, cudaFuncAttributeMaxDynamicSharedMemorySize, GEMMH_SMEM_BYTES);
    cudaFuncSetAttribute(gemm_hf<2>, cudaFuncAttributeMaxDynamicSharedMemorySize, GEMMH_SMEM_BYTES);

    zero_counts<<<1, 32>>>();

    // operand pre-conversion
    {
        int n2 = NN * DD / 2;
        split_x_kernel<<<(n2 + 255) / 256, 256>>>(x, p_xHi, p_xLo, n2);
    }
    {
        dim3 blk(32, 8);
        dim3 gWdel(DD/2/32, DD/32, 1);
        split_w_kernel<<<gWdel, blk>>>(W_delta, p_WdHi, p_WdLo, DD, DD);
        dim3 gUp(DD/2/32, HH/32, EE);
        split_w_h_kernel<<<gUp, blk>>>(Wg, p_WgF, DD, HH, nullptr);
        split_w_h_kernel<<<gUp, blk>>>(Wu, p_WuF, DD, HH, nullptr);
        dim3 gDn(HH/2/32, DD/32, EE);
        split_w_h_kernel<<<gDn, blk>>>(Wd, p_WnF, HH, DD, wn_exp);  // folds wn
    }

    // delta = softplus(x @ W_delta + b)   [bf16x2 3-pass, 3-stage]
    {
        dim3 grid(DD / BN, NN / BM);
        gemm_bf<<<grid, 256, GEMM_SMEM_BYTES>>>(
            p_xHi, p_xLo, p_WdHi, p_WdLo, p_delta, b_delta, NN, DD, DD);
    }

    // Bm, Cm from x
    proj_small<<<NN, 128>>>(x, W_B, W_C);

    // selective scan -> g_ssm / fp16 ssm
    scan_kernel<<<BB * (DD / 8), 128>>>(x, A_log, D_param);

    // router on SSM output
    router_kernel<<<NN, 128>>>(W_router);

    // MoE, all experts batched:
    gemm_hf<1><<<dim3(2 * HH / BN, NN / BM, EE), 256, GEMMH_SMEM_BYTES>>>(
        p_sF, p_WgF, p_WuF, nullptr, p_Gh, p_Uh, HH, DD);
    act_norm<<<dim3(NN, EE), 256>>>();
    gemm_hf<2><<<dim3(DD / BN, NN / BM, EE), 256, GEMMH_SMEM_BYTES>>>(
        p_aF, p_WnF, nullptr, p_Dn, nullptr, nullptr, DD, HH);

    // out = rmsnorm(ssm + Dn[loc0] + Dn[loc1], norm_w)
    final_norm<<<NN, 256>>>(norm_w, out);
}

// round 15
// speedup vs baseline: 1.0839x; 1.0017x over previous
#include <cuda_runtime.h>
#include <cuda_bf16.h>
#include <cuda_fp16.h>
#include <math.h>
#include <stdint.h>

// Problem dims (fixed)
#define BB 2
#define LL 2048
#define DD 1024
#define SS 16
#define EE 4
#define HH 2048
#define NN (BB*LL)   // 4096

typedef uint32_t u32;

// ---------------- scratch (device globals; no allocation allowed) ----------------
__device__ float g_delta[NN*DD];
__device__ float g_Bm[NN*SS];
__device__ float g_Cm[NN*SS];
__device__ float g_ssm[NN*DD];
__device__ int   g_cnt[EE];
__device__ int   g_list[EE*NN];
__device__ float g_cw[EE*NN];
__device__ float g_rs[EE*NN];            // per compact row: cw * rsqrt(mean(v^2)+eps)
__device__ int   g_loc[2*NN];            // token -> (e*NN + pos), two entries
__device__ u32   g_Gh[(size_t)EE*NN*HH/2];  // per-expert compact G (fp16 pairs)
__device__ u32   g_Uh[(size_t)EE*NN*HH/2];  // per-expert compact U (fp16 pairs)
__device__ float g_Dn[(size_t)EE*NN*DD]; // per-expert compact down output

// bf16x2 split operands for delta GEMM (packed: low16 = even k, high16 = odd k)
__device__ u32 g_xHi[NN*DD/2],   g_xLo[NN*DD/2];      // x           [NN][512]
__device__ u32 g_WdHi[DD*DD/2],  g_WdLo[DD*DD/2];     // W_delta^T   [D][512]
// fp16 single-precision MoE operands (pair-packed)
__device__ u32 g_sF[NN*DD/2];                         // ssm  (fp16 pairs)
__device__ u32 g_aF[(size_t)EE*NN*HH/2];              // act v (fp16 pairs, per-expert)
__device__ u32 g_WgF[EE*HH*DD/2];                     // Wg^T  [e][H][512]
__device__ u32 g_WuF[EE*HH*DD/2];                     // Wu^T  [e][H][512]
__device__ u32 g_WnF[EE*DD*HH/2];                     // (wn*Wd)^T  [e][D][1024]

// ---------------- FMA-only helpers ----------------
__device__ __forceinline__ float fexpf(float x) {
    x = fmaxf(x, -87.3f);
    float t = fmaf(x, 1.4426950408889634f, 12582912.f);
    float n = t - 12582912.f;
    float r = fmaf(n, -0.693359375f, x);
    r = fmaf(n, 2.12194440e-4f, r);
    float z = r * r;
    float p =          1.9875691500E-4f;
    p = fmaf(p, r,     1.3981999507E-3f);
    p = fmaf(p, r,     8.3334519073E-3f);
    p = fmaf(p, r,     4.1665795894E-2f);
    p = fmaf(p, r,     1.6666665459E-1f);
    p = fmaf(p, r,     5.0000001201E-1f);
    float res = fmaf(p, z, r) + 1.f;
    int e = (int)n;
    return __int_as_float(__float_as_int(res) + (e << 23));
}

__device__ __forceinline__ float flogf(float u) {   // u >= 1
    int iu = __float_as_int(u);
    int e = ((iu >> 23) & 255) - 127;
    float m = __int_as_float((iu & 0x007FFFFF) | 0x3F800000);
    if (m > 1.41421356f) { m *= 0.5f; e += 1; }
    float f = m - 1.f;
    float z = f * f;
    float p =          7.0376836292E-2f;
    p = fmaf(p, f,    -1.1514610310E-1f);
    p = fmaf(p, f,     1.1676998740E-1f);
    p = fmaf(p, f,    -1.2420140846E-1f);
    p = fmaf(p, f,     1.4249322787E-1f);
    p = fmaf(p, f,    -1.6668057665E-1f);
    p = fmaf(p, f,     2.0000714765E-1f);
    p = fmaf(p, f,    -2.4999993993E-1f);
    p = fmaf(p, f,     3.3333331174E-1f);
    float y = fmaf(z * f, p, -0.5f * z);
    float res = f + y;
    return fmaf((float)e, 0.69314718056f, res);
}

__device__ __forceinline__ float softplusf(float z) {
    if (z > 20.f) return z;
    return flogf(1.f + fexpf(z));
}

__device__ __forceinline__ float frecip12(float d) {  // d in (1, 2]
    float r = __int_as_float(0x7EF311C3 - __float_as_int(d));
    r = r * fmaf(-d, r, 2.f);
    r = r * fmaf(-d, r, 2.f);
    return r;
}

__device__ __forceinline__ float fsilu(float g) {   // g * sigmoid(g)
    float e = fexpf(-fabsf(g));
    float r = frecip12(1.f + e);
    float num = (g >= 0.f) ? 1.f : e;
    return g * num * r;
}

__device__ __forceinline__ void split2(float a, float b, u32& hi, u32& lo) {
    __nv_bfloat16 ah = __float2bfloat16(a);
    __nv_bfloat16 bh = __float2bfloat16(b);
    float ra = a - __bfloat162float(ah);
    float rb = b - __bfloat162float(bh);
    __nv_bfloat16 al = __float2bfloat16(ra);
    __nv_bfloat16 bl = __float2bfloat16(rb);
    hi = ((u32)__bfloat16_as_ushort(bh) << 16) | __bfloat16_as_ushort(ah);
    lo = ((u32)__bfloat16_as_ushort(bl) << 16) | __bfloat16_as_ushort(al);
}

__device__ __forceinline__ u32 pack_h2(float a, float b) {
    __half2 h = __floats2half2_rn(a, b);
    return *reinterpret_cast<u32*>(&h);
}

// ---------------- zero counts ----------------
__global__ void zero_counts() {
    if (threadIdx.x < EE) g_cnt[threadIdx.x] = 0;
}

// ---------------- split x (bf16 pairs, row-major) ----------------
__global__ __launch_bounds__(256)
void split_x_kernel(const float* __restrict__ in, u32* __restrict__ oh,
                    u32* __restrict__ ol, int n2) {
    int i = blockIdx.x * blockDim.x + threadIdx.x;
    if (i < n2) {
        float2 v = ((const float2*)in)[i];
        u32 hi, lo; split2(v.x, v.y, hi, lo);
        oh[i] = hi; ol[i] = lo;
    }
}

// ---------------- split + transpose W_delta (bf16 pairs) ----------------
__global__ __launch_bounds__(256)
void split_w_kernel(const float* __restrict__ W, u32* __restrict__ oh,
                    u32* __restrict__ ol, int K, int N) {
    int K2 = K / 2;
    __shared__ u32 th[32][33], tl[32][33];
    int kp0 = blockIdx.x * 32, n0 = blockIdx.y * 32;
    int tx = threadIdx.x, ty = threadIdx.y;
#pragma unroll
    for (int r = 0; r < 4; r++) {
        int kp = kp0 + ty + r * 8;
        int n  = n0 + tx;
        float w0 = W[(size_t)(2 * kp) * N + n];
        float w1 = W[(size_t)(2 * kp + 1) * N + n];
        u32 hi, lo; split2(w0, w1, hi, lo);
        th[ty + r * 8][tx] = hi;
        tl[ty + r * 8][tx] = lo;
    }
    __syncthreads();
#pragma unroll
    for (int r = 0; r < 4; r++) {
        int n  = n0 + ty + r * 8;
        int kp = kp0 + tx;
        oh[(size_t)n * K2 + kp] = th[tx][ty + r * 8];
        ol[(size_t)n * K2 + kp] = tl[tx][ty + r * 8];
    }
}

// ---------------- convert + transpose MoE weight (single fp16 pairs) ----------
// wn != nullptr: multiply row k by wn[e][k] (folds rmsnorm weight into W_down)
__global__ __launch_bounds__(256)
void split_w_h_kernel(const float* __restrict__ W, u32* __restrict__ o,
                      int K, int N, const float* __restrict__ wn) {
    int K2 = K / 2;
    size_t eoffW = (size_t)blockIdx.z * K * N;
    size_t eoffO = (size_t)blockIdx.z * N * K2;
    const float* wne = wn ? (wn + (size_t)blockIdx.z * K) : nullptr;
    __shared__ u32 th[32][33];
    int kp0 = blockIdx.x * 32, n0 = blockIdx.y * 32;
    int tx = threadIdx.x, ty = threadIdx.y;
#pragma unroll
    for (int r = 0; r < 4; r++) {
        int kp = kp0 + ty + r * 8;
        int n  = n0 + tx;
        float w0 = W[eoffW + (size_t)(2 * kp) * N + n];
        float w1 = W[eoffW + (size_t)(2 * kp + 1) * N + n];
        if (wne) { w0 *= wne[2 * kp]; w1 *= wne[2 * kp + 1]; }
        th[ty + r * 8][tx] = pack_h2(w0, w1);
    }
    __syncthreads();
#pragma unroll
    for (int r = 0; r < 4; r++) {
        int n  = n0 + ty + r * 8;
        int kp = kp0 + tx;
        o[eoffO + (size_t)n * K2 + kp] = th[tx][ty + r * 8];
    }
}

// ---------------- cp.async helpers ----------------
__device__ __forceinline__ void cp_async16z(void* dst, const void* src, int sz) {
    u32 d = (u32)__cvta_generic_to_shared(dst);
    asm volatile("cp.async.ca.shared.global [%0], [%1], 16, %2;\n"
                 :: "r"(d), "l"(src), "r"(sz) : "memory");
}
__device__ __forceinline__ void cp_commit() {
    asm volatile("cp.async.commit_group;\n" ::: "memory");
}
template<int N> __device__ __forceinline__ void cp_wait() {
    asm volatile("cp.async.wait_group %0;\n" :: "n"(N) : "memory");
}

// ---------------- mma / ldmatrix ----------------
__device__ __forceinline__ void mma_bf16(float* d, const u32* a, const u32* b) {
    asm volatile(
        "mma.sync.aligned.m16n8k16.row.col.f32.bf16.bf16.f32 "
        "{%0,%1,%2,%3}, {%4,%5,%6,%7}, {%8,%9}, {%0,%1,%2,%3};\n"
        : "+f"(d[0]), "+f"(d[1]), "+f"(d[2]), "+f"(d[3])
        : "r"(a[0]), "r"(a[1]), "r"(a[2]), "r"(a[3]), "r"(b[0]), "r"(b[1]));
}
__device__ __forceinline__ void mma_f16(float* d, const u32* a, const u32* b) {
    asm volatile(
        "mma.sync.aligned.m16n8k16.row.col.f32.f16.f16.f32 "
        "{%0,%1,%2,%3}, {%4,%5,%6,%7}, {%8,%9}, {%0,%1,%2,%3};\n"
        : "+f"(d[0]), "+f"(d[1]), "+f"(d[2]), "+f"(d[3])
        : "r"(a[0]), "r"(a[1]), "r"(a[2]), "r"(a[3]), "r"(b[0]), "r"(b[1]));
}
__device__ __forceinline__ void ldsm_x4(u32& r0, u32& r1, u32& r2, u32& r3, u32 addr) {
    asm volatile("ldmatrix.sync.aligned.m8n8.x4.shared.b16 {%0,%1,%2,%3}, [%4];"
                 : "=r"(r0), "=r"(r1), "=r"(r2), "=r"(r3) : "r"(addr));
}

#define BM 128
#define BN 128
#define KP 16            // k-pairs per tile (32 elements)
#define STR 20           // smem row stride in u32 (16 used + 4 pad)
#define ABUF (128*STR)   // 2560 u32 per array per buffer
#define GEMM_SMEM_BYTES  (12*ABUF*4 + BM*4)   // 3 stages x 4 arrays
#define GEMMH_SMEM_BYTES (6*ABUF*4 + BM*4)    // 3 stages x 2 arrays

// ---------------- bf16x2 3-pass GEMM (delta projection), 3-stage pipe ----------
__global__ __launch_bounds__(256, 1)
void gemm_bf(const u32* __restrict__ Ahi, const u32* __restrict__ Alo,
             const u32* __restrict__ Bhi, const u32* __restrict__ Blo,
             float* __restrict__ C1, const float* __restrict__ bias,
             int M, int Ncols, int K)
{
    extern __shared__ u32 sm[];

    int mblk = blockIdx.y;
    int nblk = blockIdx.x;
    int n0 = nblk * BN;
    int K2 = K / 2;
    int tid = threadIdx.x;

    int crow = tid >> 1;
    int cseg = (tid & 1) * 8;
    size_t abase = (size_t)(mblk * BM + crow) * K2 + cseg;
    size_t bbase = (size_t)(n0 + crow) * K2 + cseg;

    int wid = tid >> 5, lane = tid & 31;
    int g = lane >> 2, tig = lane & 3;
    int wm = wid >> 2, wn = wid & 3;

    u32 aoffL = (u32)((wm * 64 + (lane & 15)) * STR + (lane >> 4) * 4);
    u32 boffL = (u32)((wn * 32 + ((lane >> 4) << 3) + (lane & 7)) * STR + ((lane >> 3) & 1) * 4);

    float acc[4][4][4];
#pragma unroll
    for (int i = 0; i < 4; i++)
#pragma unroll
        for (int j = 0; j < 4; j++)
#pragma unroll
            for (int k = 0; k < 4; k++) acc[i][j][k] = 0.f;

    int KT = K2 / KP;
    u32 sdst = crow * STR + cseg;

    auto load_stage = [&](int kt, int st) {
        u32* s = sm + st * 4 * ABUF;
        size_t ao = abase + (size_t)kt * KP;
        size_t bo = bbase + (size_t)kt * KP;
        cp_async16z(s + 0*ABUF + sdst,     Ahi + ao,     16);
        cp_async16z(s + 0*ABUF + sdst + 4, Ahi + ao + 4, 16);
        cp_async16z(s + 1*ABUF + sdst,     Alo + ao,     16);
        cp_async16z(s + 1*ABUF + sdst + 4, Alo + ao + 4, 16);
        cp_async16z(s + 2*ABUF + sdst,     Bhi + bo,     16);
        cp_async16z(s + 2*ABUF + sdst + 4, Bhi + bo + 4, 16);
        cp_async16z(s + 3*ABUF + sdst,     Blo + bo,     16);
        cp_async16z(s + 3*ABUF + sdst + 4, Blo + bo + 4, 16);
        cp_commit();
    };

    load_stage(0, 0);
    load_stage(1, 1);

    for (int kt = 0; kt < KT; kt++) {
        if (kt == KT - 1) cp_wait<0>(); else cp_wait<1>();
        __syncthreads();
        if (kt + 2 < KT) load_stage(kt + 2, (kt + 2) % 3);

        int buf = kt % 3;
        u32 aAh = (u32)__cvta_generic_to_shared(sm + buf * 4 * ABUF);
        u32 aAl = aAh + ABUF * 4;
        u32 aBh = aAh + 2 * ABUF * 4;
        u32 aBl = aAh + 3 * ABUF * 4;

#pragma unroll
        for (int ks = 0; ks < 2; ks++) {
            int kb = ks * 8;
            u32 ah[4][4], al[4][4];
#pragma unroll
            for (int mt = 0; mt < 4; mt++) {
                u32 off = (aoffL + mt * 16 * STR + kb) * 4;
                ldsm_x4(ah[mt][0], ah[mt][1], ah[mt][2], ah[mt][3], aAh + off);
                ldsm_x4(al[mt][0], al[mt][1], al[mt][2], al[mt][3], aAl + off);
            }
            u32 bh[4][2], bl[4][2];
#pragma unroll
            for (int np = 0; np < 2; np++) {
                u32 off = (boffL + np * 16 * STR + kb) * 4;
                ldsm_x4(bh[2*np][0], bh[2*np][1], bh[2*np+1][0], bh[2*np+1][1], aBh + off);
                ldsm_x4(bl[2*np][0], bl[2*np][1], bl[2*np+1][0], bl[2*np+1][1], aBl + off);
            }
#pragma unroll
            for (int mt = 0; mt < 4; mt++)
#pragma unroll
                for (int nt = 0; nt < 4; nt++) {
                    mma_bf16(acc[mt][nt], ah[mt], bh[nt]);
                    mma_bf16(acc[mt][nt], ah[mt], bl[nt]);
                    mma_bf16(acc[mt][nt], al[mt], bh[nt]);
                }
        }
    }

#pragma unroll
    for (int mt = 0; mt < 4; mt++) {
#pragma unroll
        for (int half = 0; half < 2; half++) {
            int gr = mblk * BM + wm * 64 + mt * 16 + g + half * 8;
            float* orow = C1 + (size_t)gr * Ncols;
#pragma unroll
            for (int nt = 0; nt < 4; nt++) {
                int col = n0 + wn * 32 + nt * 8 + tig * 2;
                float v0 = softplusf(acc[mt][nt][half*2+0] + bias[col]);
                float v1 = softplusf(acc[mt][nt][half*2+1] + bias[col+1]);
                *(float2*)(orow + col) = make_float2(v0, v1);
            }
        }
    }
}

// ---------------- fp16 single-pass GEMM (MoE up/down), 3-stage, expert-batched --
// blockIdx.z = expert.
// MODE 1: A (g_sF) gathered via g_list; nblk<16 -> g_Gh, else g_Uh (fp16 pair stores)
// MODE 2: A compact per-expert rows; Cf[(e*NN+gr),:] = g_rs[row] * acc (float store)
template<int MODE>
__global__ __launch_bounds__(256, 2)
void gemm_hf(const u32* __restrict__ A,
             const u32* __restrict__ B1, const u32* __restrict__ B2,
             float* __restrict__ Cf, u32* __restrict__ Ch1, u32* __restrict__ Ch2,
             int Ncols, int K)
{
    extern __shared__ u32 sm[];
    int* sidx = (int*)(sm + 6 * ABUF);

    int e = blockIdx.z;
    int M = g_cnt[e];
    int mblk = blockIdx.y;
    if (mblk * BM >= M) return;
    int nblk = blockIdx.x;
    int K2 = K / 2;

    const u32* Bp = B1 + (size_t)e * Ncols * K2;
    u32* Chout = Ch1;
    int nb = nblk;
    if (MODE == 1 && nblk >= 16) {
        Bp = B2 + (size_t)e * Ncols * K2;
        Chout = Ch2; nb = nblk - 16;
    }
    int n0 = nb * BN;
    int tid = threadIdx.x;

    if (MODE == 1) {
        const int* rowidx = g_list + (size_t)e * NN;
        for (int i = tid; i < BM; i += 256) {
            int gr = mblk * BM + i;
            sidx[i] = (gr < M) ? rowidx[gr] : -1;
        }
        __syncthreads();
    }

    int crow = tid >> 1;
    int cseg = (tid & 1) * 8;
    int asz;
    size_t abase;
    if (MODE == 1) {
        int s = sidx[crow];
        asz = (s >= 0) ? 16 : 0;
        abase = (size_t)(s >= 0 ? s : 0) * K2 + cseg;
    } else {
        int gr = mblk * BM + crow;
        asz = (gr < M) ? 16 : 0;
        abase = ((size_t)e * NN + (gr < M ? gr : 0)) * K2 + cseg;
    }
    size_t bbase = (size_t)(n0 + crow) * K2 + cseg;

    int wid = tid >> 5, lane = tid & 31;
    int g = lane >> 2, tig = lane & 3;
    int wm = wid >> 2, wn = wid & 3;

    u32 aoffL = (u32)((wm * 64 + (lane & 15)) * STR + (lane >> 4) * 4);
    u32 boffL = (u32)((wn * 32 + ((lane >> 4) << 3) + (lane & 7)) * STR + ((lane >> 3) & 1) * 4);

    float acc[4][4][4];
#pragma unroll
    for (int i = 0; i < 4; i++)
#pragma unroll
        for (int j = 0; j < 4; j++)
#pragma unroll
            for (int k = 0; k < 4; k++) acc[i][j][k] = 0.f;

    int KT = K2 / KP;
    u32 sdst = crow * STR + cseg;

    auto load_stage = [&](int kt, int st) {
        u32* s = sm + st * 2 * ABUF;
        size_t ao = abase + (size_t)kt * KP;
        size_t bo = bbase + (size_t)kt * KP;
        cp_async16z(s + 0*ABUF + sdst,     A + ao,      asz);
        cp_async16z(s + 0*ABUF + sdst + 4, A + ao + 4,  asz);
        cp_async16z(s + 1*ABUF + sdst,     Bp + bo,     16);
        cp_async16z(s + 1*ABUF + sdst + 4, Bp + bo + 4, 16);
        cp_commit();
    };

    load_stage(0, 0);
    load_stage(1, 1);

    for (int kt = 0; kt < KT; kt++) {
        if (kt == KT - 1) cp_wait<0>(); else cp_wait<1>();
        __syncthreads();
        if (kt + 2 < KT) load_stage(kt + 2, (kt + 2) % 3);

        int buf = kt % 3;
        u32 aA = (u32)__cvta_generic_to_shared(sm + buf * 2 * ABUF);
        u32 aB = aA + ABUF * 4;

#pragma unroll
        for (int ks = 0; ks < 2; ks++) {
            int kb = ks * 8;
            u32 ah[4][4];
#pragma unroll
            for (int mt = 0; mt < 4; mt++) {
                u32 off = (aoffL + mt * 16 * STR + kb) * 4;
                ldsm_x4(ah[mt][0], ah[mt][1], ah[mt][2], ah[mt][3], aA + off);
            }
            u32 bh[4][2];
#pragma unroll
            for (int np = 0; np < 2; np++) {
                u32 off = (boffL + np * 16 * STR + kb) * 4;
                ldsm_x4(bh[2*np][0], bh[2*np][1], bh[2*np+1][0], bh[2*np+1][1], aB + off);
            }
#pragma unroll
            for (int mt = 0; mt < 4; mt++)
#pragma unroll
                for (int nt = 0; nt < 4; nt++)
                    mma_f16(acc[mt][nt], ah[mt], bh[nt]);
        }
    }

#pragma unroll
    for (int mt = 0; mt < 4; mt++) {
#pragma unroll
        for (int half = 0; half < 2; half++) {
            int lr = wm * 64 + mt * 16 + g + half * 8;
            int gr = mblk * BM + lr;
            if (gr >= M) continue;
            if (MODE == 1) {
                u32* orow = Chout + ((size_t)e * NN + gr) * (Ncols / 2);
#pragma unroll
                for (int nt = 0; nt < 4; nt++) {
                    int col = n0 + wn * 32 + nt * 8 + tig * 2;
                    orow[col >> 1] = pack_h2(acc[mt][nt][half*2+0], acc[mt][nt][half*2+1]);
                }
            } else {
                float rs = g_rs[(size_t)e * NN + gr];
                float* orow = Cf + ((size_t)e * NN + gr) * Ncols;
#pragma unroll
                for (int nt = 0; nt < 4; nt++) {
                    int col = n0 + wn * 32 + nt * 8 + tig * 2;
                    *(float2*)(orow + col) =
                        make_float2(rs * acc[mt][nt][half*2+0], rs * acc[mt][nt][half*2+1]);
                }
            }
        }
    }
}

// ---------------- small projections: Bm, Cm (from x) ----------------
__global__ __launch_bounds__(128)
void proj_small(const float* __restrict__ x, const float* __restrict__ WB,
                const float* __restrict__ WC)
{
    int n = blockIdx.x;
    __shared__ float xs[DD];
    const float* xr = x + (size_t)n * DD;
    for (int i = threadIdx.x; i < DD; i += 128) xs[i] = xr[i];
    __syncthreads();
    int warp = threadIdx.x >> 5, lane = threadIdx.x & 31;
    for (int c = warp; c < 32; c += 4) {
        const float* W; int col; float* out;
        if (c < 16) { W = WB; col = c;      out = g_Bm + (size_t)n * SS + col; }
        else        { W = WC; col = c - 16; out = g_Cm + (size_t)n * SS + col; }
        float s = 0.f;
        for (int k = lane; k < DD; k += 32)
            s = fmaf(xs[k], W[(size_t)k * SS + col], s);
        s += __shfl_xor_sync(~0u, s, 16);
        s += __shfl_xor_sync(~0u, s, 8);
        s += __shfl_xor_sync(~0u, s, 4);
        s += __shfl_xor_sync(~0u, s, 2);
        s += __shfl_xor_sync(~0u, s, 1);
        if (lane == 0) *out = s;
    }
}

// ---------------- selective scan: hoisted coefficients, single wave ------------
// block 256 = (16 d) x (16 s); grid = BB * DD/16 = 128 (one wave on 148 SMs)
__global__ __launch_bounds__(256)
void scan_kernel(const float* __restrict__ x, const float* __restrict__ A_log,
                 const float* __restrict__ D_param)
{
    int b = blockIdx.x >> 6;
    int dchunk = blockIdx.x & 63;
    int dl = threadIdx.x >> 4;      // d-local 0..15
    int s  = threadIdx.x & 15;      // state index
    int d = dchunk * 16 + dl;

    float A_ds = -__expf(A_log[d * SS + s]);

    __shared__ float sx[16][16], sd[16][16];
    __shared__ float sB[16][17], sC[16][17];
    __shared__ float sp[16 * 272];  // [q][s*17 + dl]
    __shared__ float sDp[16];

    int tt = threadIdx.x >> 4;
    int cc = threadIdx.x & 15;
    const int base_bt = b * LL;

    if (threadIdx.x < 16) sDp[threadIdx.x] = D_param[dchunk * 16 + threadIdx.x];

    size_t xoff = ((size_t)(base_bt + tt)) * DD + dchunk * 16 + cc;
    float rx = x[xoff];
    float rd = g_delta[xoff];
    size_t boff = ((size_t)(base_bt + tt)) * SS + cc;
    float rB = g_Bm[boff];
    float rC = g_Cm[boff];

    float h = 0.f;
    for (int t0 = 0; t0 < LL; t0 += 16) {
        __syncthreads();
        sx[tt][cc] = rx; sd[tt][cc] = rd; sB[tt][cc] = rB; sC[tt][cc] = rC;
        __syncthreads();
        if (t0 + 16 < LL) {
            size_t xo = ((size_t)(base_bt + t0 + 16 + tt)) * DD + dchunk * 16 + cc;
            rx = x[xo]; rd = g_delta[xo];
            size_t bo = ((size_t)(base_bt + t0 + 16 + tt)) * SS + cc;
            rB = g_Bm[bo]; rC = g_Cm[bo];
        }
        // hoisted, h-independent coefficients (ILP-rich)
        float av[16], bx[16];
#pragma unroll
        for (int q = 0; q < 16; q++) {
            float dv = sd[q][dl];
            av[q] = __expf(fminf(dv * A_ds, 10.f));
            bx[q] = fminf(fmaxf(dv * sB[q][s], -10.f), 10.f) * sx[q][dl];
        }
        // short serial chain: fma + clamp only
        float p[16];
#pragma unroll
        for (int q = 0; q < 16; q++) {
            h = fminf(fmaxf(fmaf(av[q], h, bx[q]), -10000.f), 10000.f);
            p[q] = h * sC[q][s];
        }
#pragma unroll
        for (int q = 0; q < 16; q++)
            sp[q * 272 + s * 17 + dl] = p[q];
        __syncthreads();
        // reduction role: (q2 = tt, d2 = cc)
        float ysum = 0.f;
#pragma unroll
        for (int s2 = 0; s2 < 16; s2++)
            ysum += sp[tt * 272 + s2 * 17 + cc];
        float y = fmaf(sx[tt][cc], sDp[cc], ysum);
        size_t yo = ((size_t)(base_bt + t0 + tt)) * DD + dchunk * 16 + cc;
        g_ssm[yo] = y;
        float yn = __shfl_down_sync(~0u, y, 1);
        if (!(cc & 1)) {
            float ya = fminf(fmaxf(y,  -60000.f), 60000.f);
            float yb = fminf(fmaxf(yn, -60000.f), 60000.f);
            size_t po = ((size_t)(base_bt + t0 + tt)) * (DD/2) + dchunk * 8 + (cc >> 1);
            g_sF[po] = pack_h2(ya, yb);
        }
    }
}

// ---------------- router on SSM output: softmax, top-2, expert lists ----------
__global__ __launch_bounds__(128)
void router_kernel(const float* __restrict__ WR)
{
    int n = blockIdx.x;
    __shared__ float xs[DD];
    __shared__ float logits[EE];
    const float* xr = g_ssm + (size_t)n * DD;
    for (int i = threadIdx.x; i < DD; i += 128) xs[i] = xr[i];
    __syncthreads();
    int warp = threadIdx.x >> 5, lane = threadIdx.x & 31;
    {
        float s = 0.f;
        for (int k = lane; k < DD; k += 32)
            s = fmaf(xs[k], WR[(size_t)k * EE + warp], s);
        s += __shfl_xor_sync(~0u, s, 16);
        s += __shfl_xor_sync(~0u, s, 8);
        s += __shfl_xor_sync(~0u, s, 4);
        s += __shfl_xor_sync(~0u, s, 2);
        s += __shfl_xor_sync(~0u, s, 1);
        if (lane == 0) logits[warp] = s;
    }
    __syncthreads();
    if (threadIdx.x == 0) {
        float l[4] = {logits[0], logits[1], logits[2], logits[3]};
        float m = fmaxf(fmaxf(l[0], l[1]), fmaxf(l[2], l[3]));
        float e[4], sum = 0.f;
#pragma unroll
        for (int i = 0; i < 4; i++) { e[i] = __expf(l[i] - m); sum += e[i]; }
        float p[4];
#pragma unroll
        for (int i = 0; i < 4; i++) p[i] = e[i] / sum;
        int i0 = 0;
#pragma unroll
        for (int i = 1; i < 4; i++) if (p[i] > p[i0]) i0 = i;
        int i1 = -1;
#pragma unroll
        for (int i = 0; i < 4; i++) {
            if (i == i0) continue;
            if (i1 < 0 || p[i] > p[i1]) i1 = i;
        }
        float w0 = p[i0], w1 = p[i1];
        float sw = w0 + w1 + 1e-9f;
        w0 /= sw; w1 /= sw;
        int pos = atomicAdd(&g_cnt[i0], 1);
        g_list[i0*NN + pos] = n; g_cw[i0*NN + pos] = w0;
        g_loc[n] = i0 * NN + pos;
        pos = atomicAdd(&g_cnt[i1], 1);
        g_list[i1*NN + pos] = n; g_cw[i1*NN + pos] = w1;
        g_loc[NN + n] = i1 * NN + pos;
    }
}

// ---------------- v = silu(G)*U (fp16 out, single pass) + row scale -----------
__global__ __launch_bounds__(256)
void act_norm()
{
    int i = blockIdx.x;
    int e = blockIdx.y;
    if (i >= g_cnt[e]) return;
    size_t row = (size_t)e * NN + i;
    __shared__ float red[8];
    float ss = 0.f;
#pragma unroll
    for (int it = 0; it < 4; it++) {
        int j2 = threadIdx.x + it * 256;
        float2 gg = __half22float2(*(const __half2*)&g_Gh[row * (HH/2) + j2]);
        float2 uu = __half22float2(*(const __half2*)&g_Uh[row * (HH/2) + j2]);
        float v0 = fsilu(gg.x) * uu.x;
        float v1 = fsilu(gg.y) * uu.y;
        g_aF[row * (HH/2) + j2] = pack_h2(v0, v1);
        ss = fmaf(v0, v0, fmaf(v1, v1, ss));
    }
    ss += __shfl_xor_sync(~0u, ss, 16);
    ss += __shfl_xor_sync(~0u, ss, 8);
    ss += __shfl_xor_sync(~0u, ss, 4);
    ss += __shfl_xor_sync(~0u, ss, 2);
    ss += __shfl_xor_sync(~0u, ss, 1);
    if ((threadIdx.x & 31) == 0) red[threadIdx.x >> 5] = ss;
    __syncthreads();
    if (threadIdx.x == 0) {
        float v = red[0] + red[1] + red[2] + red[3]
                + red[4] + red[5] + red[6] + red[7];
        g_rs[row] = g_cw[row] * rsqrtf(v / (float)HH + 1e-6f);
    }
}

// ---------------- final rmsnorm over (ssm + Dn[loc0] + Dn[loc1]) --------------
__global__ __launch_bounds__(256)
void final_norm(const float* __restrict__ norm_w, float* __restrict__ out)
{
    int n = blockIdx.x;
    __shared__ float red[8];
    __shared__ float buf[DD];
    int l0 = g_loc[n], l1 = g_loc[NN + n];
    const float* r0 = g_Dn + (size_t)l0 * DD;
    const float* r1 = g_Dn + (size_t)l1 * DD;
    const float* rs = g_ssm + (size_t)n * DD;
    float ss = 0.f;
    for (int j = threadIdx.x; j < DD; j += 256) {
        float v = rs[j] + r0[j] + r1[j];
        buf[j] = v;
        ss = fmaf(v, v, ss);
    }
    ss += __shfl_xor_sync(~0u, ss, 16);
    ss += __shfl_xor_sync(~0u, ss, 8);
    ss += __shfl_xor_sync(~0u, ss, 4);
    ss += __shfl_xor_sync(~0u, ss, 2);
    ss += __shfl_xor_sync(~0u, ss, 1);
    if ((threadIdx.x & 31) == 0) red[threadIdx.x >> 5] = ss;
    __syncthreads();
    if (threadIdx.x < 32) {
        float v = (threadIdx.x < 8) ? red[threadIdx.x] : 0.f;
        v += __shfl_xor_sync(~0u, v, 4);
        v += __shfl_xor_sync(~0u, v, 2);
        v += __shfl_xor_sync(~0u, v, 1);
        if (threadIdx.x == 0) red[0] = v;
    }
    __syncthreads();
    float inv = rsqrtf(red[0] / (float)DD + 1e-6f);
    for (int j = threadIdx.x; j < DD; j += 256)
        out[(size_t)n * DD + j] = norm_w[j] * buf[j] * inv;
}

// ---------------- launch ----------------
extern "C" void kernel_launch(void* const* d_in, const int* in_sizes, int n_in,
                              void* d_out, int out_size)
{
    const float* x        = (const float*)d_in[0];
    const float* A_log    = (const float*)d_in[1];
    const float* D_param  = (const float*)d_in[2];
    const float* W_delta  = (const float*)d_in[3];
    const float* b_delta  = (const float*)d_in[4];
    const float* W_B      = (const float*)d_in[5];
    const float* W_C      = (const float*)d_in[6];
    const float* W_router = (const float*)d_in[7];
    const float* Wg       = (const float*)d_in[8];
    const float* Wu       = (const float*)d_in[9];
    const float* Wd       = (const float*)d_in[10];
    const float* wn_exp   = (const float*)d_in[11];
    const float* norm_w   = (const float*)d_in[12];
    float* out = (float*)d_out;

    float *p_delta, *p_Dn;
    u32 *p_xHi, *p_xLo, *p_sF, *p_aF, *p_Gh, *p_Uh;
    u32 *p_WdHi, *p_WdLo, *p_WgF, *p_WuF, *p_WnF;
    cudaGetSymbolAddress((void**)&p_delta, g_delta);
    cudaGetSymbolAddress((void**)&p_Gh,    g_Gh);
    cudaGetSymbolAddress((void**)&p_Uh,    g_Uh);
    cudaGetSymbolAddress((void**)&p_Dn,    g_Dn);
    cudaGetSymbolAddress((void**)&p_xHi,   g_xHi);
    cudaGetSymbolAddress((void**)&p_xLo,   g_xLo);
    cudaGetSymbolAddress((void**)&p_sF,    g_sF);
    cudaGetSymbolAddress((void**)&p_aF,    g_aF);
    cudaGetSymbolAddress((void**)&p_WdHi,  g_WdHi);
    cudaGetSymbolAddress((void**)&p_WdLo,  g_WdLo);
    cudaGetSymbolAddress((void**)&p_WgF,   g_WgF);
    cudaGetSymbolAddress((void**)&p_WuF,   g_WuF);
    cudaGetSymbolAddress((void**)&p_WnF,   g_WnF);

    cudaFuncSetAttribute(gemm_bf,    cudaFuncAttributeMaxDynamicSharedMemorySize, GEMM_SMEM_BYTES);
    cudaFuncSetAttribute(gemm_hf<1>, cudaFuncAttributeMaxDynamicSharedMemorySize, GEMMH_SMEM_BYTES);
    cudaFuncSetAttribute(gemm_hf<2>, cudaFuncAttributeMaxDynamicSharedMemorySize, GEMMH_SMEM_BYTES);

    zero_counts<<<1, 32>>>();

    // operand pre-conversion
    {
        int n2 = NN * DD / 2;
        split_x_kernel<<<(n2 + 255) / 256, 256>>>(x, p_xHi, p_xLo, n2);
    }
    {
        dim3 blk(32, 8);
        dim3 gWdel(DD/2/32, DD/32, 1);
        split_w_kernel<<<gWdel, blk>>>(W_delta, p_WdHi, p_WdLo, DD, DD);
        dim3 gUp(DD/2/32, HH/32, EE);
        split_w_h_kernel<<<gUp, blk>>>(Wg, p_WgF, DD, HH, nullptr);
        split_w_h_kernel<<<gUp, blk>>>(Wu, p_WuF, DD, HH, nullptr);
        dim3 gDn(HH/2/32, DD/32, EE);
        split_w_h_kernel<<<gDn, blk>>>(Wd, p_WnF, HH, DD, wn_exp);  // folds wn
    }

    // delta = softplus(x @ W_delta + b)   [bf16x2 3-pass, 3-stage]
    {
        dim3 grid(DD / BN, NN / BM);
        gemm_bf<<<grid, 256, GEMM_SMEM_BYTES>>>(
            p_xHi, p_xLo, p_WdHi, p_WdLo, p_delta, b_delta, NN, DD, DD);
    }

    // Bm, Cm from x
    proj_small<<<NN, 128>>>(x, W_B, W_C);

    // selective scan -> g_ssm / fp16 ssm   [single wave: 128 blocks]
    scan_kernel<<<BB * (DD / 16), 256>>>(x, A_log, D_param);

    // router on SSM output
    router_kernel<<<NN, 128>>>(W_router);

    // MoE, all experts batched:
    gemm_hf<1><<<dim3(2 * HH / BN, NN / BM, EE), 256, GEMMH_SMEM_BYTES>>>(
        p_sF, p_WgF, p_WuF, nullptr, p_Gh, p_Uh, HH, DD);
    act_norm<<<dim3(NN, EE), 256>>>();
    gemm_hf<2><<<dim3(DD / BN, NN / BM, EE), 256, GEMMH_SMEM_BYTES>>>(
        p_aF, p_WnF, nullptr, p_Dn, nullptr, nullptr, DD, HH);

    // out = rmsnorm(ssm + Dn[loc0] + Dn[loc1], norm_w)
    final_norm<<<NN, 256>>>(norm_w, out);
}

// round 16
// speedup vs baseline: 1.1124x; 1.0263x over previous
#include <cuda_runtime.h>
#include <cuda_bf16.h>
#include <cuda_fp16.h>
#include <math.h>
#include <stdint.h>

// Problem dims (fixed)
#define BB 2
#define LL 2048
#define DD 1024
#define SS 16
#define EE 4
#define HH 2048
#define NN (BB*LL)   // 4096

typedef uint32_t u32;

// ---------------- scratch (device globals; no allocation allowed) ----------------
__device__ float g_delta[NN*DD];
__device__ float g_Bm[NN*SS];
__device__ float g_Cm[NN*SS];
__device__ float g_ssm[NN*DD];
__device__ int   g_cnt[EE];
__device__ int   g_list[EE*NN];
__device__ float g_cw[EE*NN];
__device__ float g_ssq[EE*NN];           // per compact row: sum of v^2 (atomic)
__device__ int   g_loc[2*NN];            // token -> (e*NN + pos), two entries
__device__ float g_Dn[(size_t)EE*NN*DD]; // per-expert compact down output

// bf16x2 split operands for delta GEMM (packed: low16 = even k, high16 = odd k)
__device__ u32 g_xHi[NN*DD/2],   g_xLo[NN*DD/2];      // x           [NN][512]
__device__ u32 g_WdHi[DD*DD/2],  g_WdLo[DD*DD/2];     // W_delta^T   [D][512]
// fp16 single-precision MoE operands (pair-packed)
__device__ u32 g_sF[NN*DD/2];                         // ssm  (fp16 pairs)
__device__ u32 g_aF[(size_t)EE*NN*HH/2];              // act v (fp16 pairs, per-expert)
__device__ u32 g_WgF[EE*HH*DD/2];                     // Wg^T  [e][H][512]
__device__ u32 g_WuF[EE*HH*DD/2];                     // Wu^T  [e][H][512]
__device__ u32 g_WnF[EE*DD*HH/2];                     // (wn*Wd)^T  [e][D][1024]

// ---------------- FMA-only helpers ----------------
__device__ __forceinline__ float fexpf(float x) {
    x = fmaxf(x, -87.3f);
    float t = fmaf(x, 1.4426950408889634f, 12582912.f);
    float n = t - 12582912.f;
    float r = fmaf(n, -0.693359375f, x);
    r = fmaf(n, 2.12194440e-4f, r);
    float z = r * r;
    float p =          1.9875691500E-4f;
    p = fmaf(p, r,     1.3981999507E-3f);
    p = fmaf(p, r,     8.3334519073E-3f);
    p = fmaf(p, r,     4.1665795894E-2f);
    p = fmaf(p, r,     1.6666665459E-1f);
    p = fmaf(p, r,     5.0000001201E-1f);
    float res = fmaf(p, z, r) + 1.f;
    int e = (int)n;
    return __int_as_float(__float_as_int(res) + (e << 23));
}

__device__ __forceinline__ float flogf(float u) {   // u >= 1
    int iu = __float_as_int(u);
    int e = ((iu >> 23) & 255) - 127;
    float m = __int_as_float((iu & 0x007FFFFF) | 0x3F800000);
    if (m > 1.41421356f) { m *= 0.5f; e += 1; }
    float f = m - 1.f;
    float z = f * f;
    float p =          7.0376836292E-2f;
    p = fmaf(p, f,    -1.1514610310E-1f);
    p = fmaf(p, f,     1.1676998740E-1f);
    p = fmaf(p, f,    -1.2420140846E-1f);
    p = fmaf(p, f,     1.4249322787E-1f);
    p = fmaf(p, f,    -1.6668057665E-1f);
    p = fmaf(p, f,     2.0000714765E-1f);
    p = fmaf(p, f,    -2.4999993993E-1f);
    p = fmaf(p, f,     3.3333331174E-1f);
    float y = fmaf(z * f, p, -0.5f * z);
    float res = f + y;
    return fmaf((float)e, 0.69314718056f, res);
}

__device__ __forceinline__ float softplusf(float z) {
    if (z > 20.f) return z;
    return flogf(1.f + fexpf(z));
}

__device__ __forceinline__ float frecip12(float d) {  // d in (1, 2]
    float r = __int_as_float(0x7EF311C3 - __float_as_int(d));
    r = r * fmaf(-d, r, 2.f);
    r = r * fmaf(-d, r, 2.f);
    return r;
}

__device__ __forceinline__ float fsilu(float g) {   // g * sigmoid(g)
    float e = fexpf(-fabsf(g));
    float r = frecip12(1.f + e);
    float num = (g >= 0.f) ? 1.f : e;
    return g * num * r;
}

__device__ __forceinline__ void split2(float a, float b, u32& hi, u32& lo) {
    __nv_bfloat16 ah = __float2bfloat16(a);
    __nv_bfloat16 bh = __float2bfloat16(b);
    float ra = a - __bfloat162float(ah);
    float rb = b - __bfloat162float(bh);
    __nv_bfloat16 al = __float2bfloat16(ra);
    __nv_bfloat16 bl = __float2bfloat16(rb);
    hi = ((u32)__bfloat16_as_ushort(bh) << 16) | __bfloat16_as_ushort(ah);
    lo = ((u32)__bfloat16_as_ushort(bl) << 16) | __bfloat16_as_ushort(al);
}

__device__ __forceinline__ u32 pack_h2(float a, float b) {
    __half2 h = __floats2half2_rn(a, b);
    return *reinterpret_cast<u32*>(&h);
}

// ---------------- zero counts + ssq ----------------
__global__ __launch_bounds__(256)
void zero_init() {
    int i = blockIdx.x * blockDim.x + threadIdx.x;
    if (i < EE) g_cnt[i] = 0;
    if (i < EE * NN) g_ssq[i] = 0.f;
}

// ---------------- split x (bf16 pairs, row-major) ----------------
__global__ __launch_bounds__(256)
void split_x_kernel(const float* __restrict__ in, u32* __restrict__ oh,
                    u32* __restrict__ ol, int n2) {
    int i = blockIdx.x * blockDim.x + threadIdx.x;
    if (i < n2) {
        float2 v = ((const float2*)in)[i];
        u32 hi, lo; split2(v.x, v.y, hi, lo);
        oh[i] = hi; ol[i] = lo;
    }
}

// ---------------- split + transpose W_delta (bf16 pairs) ----------------
__global__ __launch_bounds__(256)
void split_w_kernel(const float* __restrict__ W, u32* __restrict__ oh,
                    u32* __restrict__ ol, int K, int N) {
    int K2 = K / 2;
    __shared__ u32 th[32][33], tl[32][33];
    int kp0 = blockIdx.x * 32, n0 = blockIdx.y * 32;
    int tx = threadIdx.x, ty = threadIdx.y;
#pragma unroll
    for (int r = 0; r < 4; r++) {
        int kp = kp0 + ty + r * 8;
        int n  = n0 + tx;
        float w0 = W[(size_t)(2 * kp) * N + n];
        float w1 = W[(size_t)(2 * kp + 1) * N + n];
        u32 hi, lo; split2(w0, w1, hi, lo);
        th[ty + r * 8][tx] = hi;
        tl[ty + r * 8][tx] = lo;
    }
    __syncthreads();
#pragma unroll
    for (int r = 0; r < 4; r++) {
        int n  = n0 + ty + r * 8;
        int kp = kp0 + tx;
        oh[(size_t)n * K2 + kp] = th[tx][ty + r * 8];
        ol[(size_t)n * K2 + kp] = tl[tx][ty + r * 8];
    }
}

// ---------------- convert + transpose MoE weight (single fp16 pairs) ----------
__global__ __launch_bounds__(256)
void split_w_h_kernel(const float* __restrict__ W, u32* __restrict__ o,
                      int K, int N, const float* __restrict__ wn) {
    int K2 = K / 2;
    size_t eoffW = (size_t)blockIdx.z * K * N;
    size_t eoffO = (size_t)blockIdx.z * N * K2;
    const float* wne = wn ? (wn + (size_t)blockIdx.z * K) : nullptr;
    __shared__ u32 th[32][33];
    int kp0 = blockIdx.x * 32, n0 = blockIdx.y * 32;
    int tx = threadIdx.x, ty = threadIdx.y;
#pragma unroll
    for (int r = 0; r < 4; r++) {
        int kp = kp0 + ty + r * 8;
        int n  = n0 + tx;
        float w0 = W[eoffW + (size_t)(2 * kp) * N + n];
        float w1 = W[eoffW + (size_t)(2 * kp + 1) * N + n];
        if (wne) { w0 *= wne[2 * kp]; w1 *= wne[2 * kp + 1]; }
        th[ty + r * 8][tx] = pack_h2(w0, w1);
    }
    __syncthreads();
#pragma unroll
    for (int r = 0; r < 4; r++) {
        int n  = n0 + ty + r * 8;
        int kp = kp0 + tx;
        o[eoffO + (size_t)n * K2 + kp] = th[tx][ty + r * 8];
    }
}

// ---------------- cp.async helpers ----------------
__device__ __forceinline__ void cp_async16z(void* dst, const void* src, int sz) {
    u32 d = (u32)__cvta_generic_to_shared(dst);
    asm volatile("cp.async.ca.shared.global [%0], [%1], 16, %2;\n"
                 :: "r"(d), "l"(src), "r"(sz) : "memory");
}
__device__ __forceinline__ void cp_commit() {
    asm volatile("cp.async.commit_group;\n" ::: "memory");
}
template<int N> __device__ __forceinline__ void cp_wait() {
    asm volatile("cp.async.wait_group %0;\n" :: "n"(N) : "memory");
}

// ---------------- mma / ldmatrix ----------------
__device__ __forceinline__ void mma_bf16(float* d, const u32* a, const u32* b) {
    asm volatile(
        "mma.sync.aligned.m16n8k16.row.col.f32.bf16.bf16.f32 "
        "{%0,%1,%2,%3}, {%4,%5,%6,%7}, {%8,%9}, {%0,%1,%2,%3};\n"
        : "+f"(d[0]), "+f"(d[1]), "+f"(d[2]), "+f"(d[3])
        : "r"(a[0]), "r"(a[1]), "r"(a[2]), "r"(a[3]), "r"(b[0]), "r"(b[1]));
}
__device__ __forceinline__ void mma_f16(float* d, const u32* a, const u32* b) {
    asm volatile(
        "mma.sync.aligned.m16n8k16.row.col.f32.f16.f16.f32 "
        "{%0,%1,%2,%3}, {%4,%5,%6,%7}, {%8,%9}, {%0,%1,%2,%3};\n"
        : "+f"(d[0]), "+f"(d[1]), "+f"(d[2]), "+f"(d[3])
        : "r"(a[0]), "r"(a[1]), "r"(a[2]), "r"(a[3]), "r"(b[0]), "r"(b[1]));
}
__device__ __forceinline__ void ldsm_x4(u32& r0, u32& r1, u32& r2, u32& r3, u32 addr) {
    asm volatile("ldmatrix.sync.aligned.m8n8.x4.shared.b16 {%0,%1,%2,%3}, [%4];"
                 : "=r"(r0), "=r"(r1), "=r"(r2), "=r"(r3) : "r"(addr));
}

#define BM 128
#define BN 128
#define KP 16            // k-pairs per tile (32 elements)
#define STR 20           // smem row stride in u32 (16 used + 4 pad)
#define ABUF (128*STR)   // 2560 u32 per array per buffer
#define GEMM_SMEM_BYTES  (12*ABUF*4 + BM*4)   // 3 stages x 4 arrays
#define GEMMH_SMEM_BYTES (6*ABUF*4 + BM*4)    // 3 stages x 2 arrays

// ---------------- bf16x2 3-pass GEMM (delta projection), 3-stage pipe ----------
__global__ __launch_bounds__(256, 1)
void gemm_bf(const u32* __restrict__ Ahi, const u32* __restrict__ Alo,
             const u32* __restrict__ Bhi, const u32* __restrict__ Blo,
             float* __restrict__ C1, const float* __restrict__ bias,
             int M, int Ncols, int K)
{
    extern __shared__ u32 sm[];

    int mblk = blockIdx.y;
    int nblk = blockIdx.x;
    int n0 = nblk * BN;
    int K2 = K / 2;
    int tid = threadIdx.x;

    int crow = tid >> 1;
    int cseg = (tid & 1) * 8;
    size_t abase = (size_t)(mblk * BM + crow) * K2 + cseg;
    size_t bbase = (size_t)(n0 + crow) * K2 + cseg;

    int wid = tid >> 5, lane = tid & 31;
    int g = lane >> 2, tig = lane & 3;
    int wm = wid >> 2, wn = wid & 3;

    u32 aoffL = (u32)((wm * 64 + (lane & 15)) * STR + (lane >> 4) * 4);
    u32 boffL = (u32)((wn * 32 + ((lane >> 4) << 3) + (lane & 7)) * STR + ((lane >> 3) & 1) * 4);

    float acc[4][4][4];
#pragma unroll
    for (int i = 0; i < 4; i++)
#pragma unroll
        for (int j = 0; j < 4; j++)
#pragma unroll
            for (int k = 0; k < 4; k++) acc[i][j][k] = 0.f;

    int KT = K2 / KP;
    u32 sdst = crow * STR + cseg;

    auto load_stage = [&](int kt, int st) {
        u32* s = sm + st * 4 * ABUF;
        size_t ao = abase + (size_t)kt * KP;
        size_t bo = bbase + (size_t)kt * KP;
        cp_async16z(s + 0*ABUF + sdst,     Ahi + ao,     16);
        cp_async16z(s + 0*ABUF + sdst + 4, Ahi + ao + 4, 16);
        cp_async16z(s + 1*ABUF + sdst,     Alo + ao,     16);
        cp_async16z(s + 1*ABUF + sdst + 4, Alo + ao + 4, 16);
        cp_async16z(s + 2*ABUF + sdst,     Bhi + bo,     16);
        cp_async16z(s + 2*ABUF + sdst + 4, Bhi + bo + 4, 16);
        cp_async16z(s + 3*ABUF + sdst,     Blo + bo,     16);
        cp_async16z(s + 3*ABUF + sdst + 4, Blo + bo + 4, 16);
        cp_commit();
    };

    load_stage(0, 0);
    load_stage(1, 1);

    for (int kt = 0; kt < KT; kt++) {
        if (kt == KT - 1) cp_wait<0>(); else cp_wait<1>();
        __syncthreads();
        if (kt + 2 < KT) load_stage(kt + 2, (kt + 2) % 3);

        int buf = kt % 3;
        u32 aAh = (u32)__cvta_generic_to_shared(sm + buf * 4 * ABUF);
        u32 aAl = aAh + ABUF * 4;
        u32 aBh = aAh + 2 * ABUF * 4;
        u32 aBl = aAh + 3 * ABUF * 4;

#pragma unroll
        for (int ks = 0; ks < 2; ks++) {
            int kb = ks * 8;
            u32 ah[4][4], al[4][4];
#pragma unroll
            for (int mt = 0; mt < 4; mt++) {
                u32 off = (aoffL + mt * 16 * STR + kb) * 4;
                ldsm_x4(ah[mt][0], ah[mt][1], ah[mt][2], ah[mt][3], aAh + off);
                ldsm_x4(al[mt][0], al[mt][1], al[mt][2], al[mt][3], aAl + off);
            }
            u32 bh[4][2], bl[4][2];
#pragma unroll
            for (int np = 0; np < 2; np++) {
                u32 off = (boffL + np * 16 * STR + kb) * 4;
                ldsm_x4(bh[2*np][0], bh[2*np][1], bh[2*np+1][0], bh[2*np+1][1], aBh + off);
                ldsm_x4(bl[2*np][0], bl[2*np][1], bl[2*np+1][0], bl[2*np+1][1], aBl + off);
            }
#pragma unroll
            for (int mt = 0; mt < 4; mt++)
#pragma unroll
                for (int nt = 0; nt < 4; nt++) {
                    mma_bf16(acc[mt][nt], ah[mt], bh[nt]);
                    mma_bf16(acc[mt][nt], ah[mt], bl[nt]);
                    mma_bf16(acc[mt][nt], al[mt], bh[nt]);
                }
        }
    }

#pragma unroll
    for (int mt = 0; mt < 4; mt++) {
#pragma unroll
        for (int half = 0; half < 2; half++) {
            int gr = mblk * BM + wm * 64 + mt * 16 + g + half * 8;
            float* orow = C1 + (size_t)gr * Ncols;
#pragma unroll
            for (int nt = 0; nt < 4; nt++) {
                int col = n0 + wn * 32 + nt * 8 + tig * 2;
                float v0 = softplusf(acc[mt][nt][half*2+0] + bias[col]);
                float v1 = softplusf(acc[mt][nt][half*2+1] + bias[col+1]);
                *(float2*)(orow + col) = make_float2(v0, v1);
            }
        }
    }
}

// ---------------- fused MoE up-GEMM: v = silu(ssm@Wg) * (ssm@Wu), fp16 out ------
// grid (HH/64, NN/128, EE). Each CTA: 128 gathered rows x 64 cols of BOTH G and U.
// Epilogue writes v to g_aF and atomically accumulates sum(v^2) into g_ssq[row].
__global__ __launch_bounds__(256, 2)
void gemm_up(const u32* __restrict__ A,
             const u32* __restrict__ Bg, const u32* __restrict__ Bu)
{
    extern __shared__ u32 sm[];
    int* sidx = (int*)(sm + 6 * ABUF);

    int e = blockIdx.z;
    int M = g_cnt[e];
    int mblk = blockIdx.y;
    if (mblk * BM >= M) return;
    int nblk = blockIdx.x;
    int n0 = nblk * 64;
    int K2 = DD / 2;
    int tid = threadIdx.x;

    const int* rowidx = g_list + (size_t)e * NN;
    for (int i = tid; i < BM; i += 256) {
        int gr = mblk * BM + i;
        sidx[i] = (gr < M) ? rowidx[gr] : -1;
    }
    __syncthreads();

    int crow = tid >> 1;                 // 0..127
    int cseg = (tid & 1) * 8;
    int s0i = sidx[crow];
    int asz = (s0i >= 0) ? 16 : 0;
    size_t abase = (size_t)(s0i >= 0 ? s0i : 0) * K2 + cseg;
    // B loader: crow<64 -> Wg row n0+crow ; crow>=64 -> Wu row n0+crow-64
    const u32* Bsrc = (crow < 64) ? Bg : Bu;
    size_t bbase = ((size_t)e * HH + n0 + (crow & 63)) * K2 + cseg;

    int wid = tid >> 5, lane = tid & 31;
    int g = lane >> 2, tig = lane & 3;
    int wm = wid >> 1, wn = wid & 1;     // 4 x 2 warps; warp = 32 rows x 32 cols (G+U)

    u32 aoffL = (u32)((wm * 32 + (lane & 15)) * STR + (lane >> 4) * 4);
    u32 boffL = (u32)((wn * 32 + ((lane >> 4) << 3) + (lane & 7)) * STR + ((lane >> 3) & 1) * 4);

    float accg[2][4][4], accu[2][4][4];
#pragma unroll
    for (int i = 0; i < 2; i++)
#pragma unroll
        for (int j = 0; j < 4; j++)
#pragma unroll
            for (int k = 0; k < 4; k++) { accg[i][j][k] = 0.f; accu[i][j][k] = 0.f; }

    int KT = K2 / KP;
    u32 sdst = crow * STR + cseg;

    auto load_stage = [&](int kt, int st) {
        u32* s = sm + st * 2 * ABUF;
        size_t ao = abase + (size_t)kt * KP;
        size_t bo = bbase + (size_t)kt * KP;
        cp_async16z(s + 0*ABUF + sdst,     A + ao,        asz);
        cp_async16z(s + 0*ABUF + sdst + 4, A + ao + 4,    asz);
        cp_async16z(s + 1*ABUF + sdst,     Bsrc + bo,     16);
        cp_async16z(s + 1*ABUF + sdst + 4, Bsrc + bo + 4, 16);
        cp_commit();
    };

    load_stage(0, 0);
    load_stage(1, 1);

    for (int kt = 0; kt < KT; kt++) {
        if (kt == KT - 1) cp_wait<0>(); else cp_wait<1>();
        __syncthreads();
        if (kt + 2 < KT) load_stage(kt + 2, (kt + 2) % 3);

        int buf = kt % 3;
        u32 aA = (u32)__cvta_generic_to_shared(sm + buf * 2 * ABUF);
        u32 aB = aA + ABUF * 4;

#pragma unroll
        for (int ks = 0; ks < 2; ks++) {
            int kb = ks * 8;
            u32 ah[2][4];
#pragma unroll
            for (int mt = 0; mt < 2; mt++) {
                u32 off = (aoffL + mt * 16 * STR + kb) * 4;
                ldsm_x4(ah[mt][0], ah[mt][1], ah[mt][2], ah[mt][3], aA + off);
            }
            u32 bg[4][2], bu[4][2];
#pragma unroll
            for (int np = 0; np < 2; np++) {
                u32 offg = (boffL + np * 16 * STR + kb) * 4;
                ldsm_x4(bg[2*np][0], bg[2*np][1], bg[2*np+1][0], bg[2*np+1][1], aB + offg);
                u32 offu = offg + 64 * STR * 4;
                ldsm_x4(bu[2*np][0], bu[2*np][1], bu[2*np+1][0], bu[2*np+1][1], aB + offu);
            }
#pragma unroll
            for (int mt = 0; mt < 2; mt++)
#pragma unroll
                for (int nt = 0; nt < 4; nt++) {
                    mma_f16(accg[mt][nt], ah[mt], bg[nt]);
                    mma_f16(accu[mt][nt], ah[mt], bu[nt]);
                }
        }
    }

    // epilogue: v = fsilu(G)*U, write fp16, accumulate row ssq via atomics
#pragma unroll
    for (int mt = 0; mt < 2; mt++) {
#pragma unroll
        for (int half = 0; half < 2; half++) {
            int lr = wm * 32 + mt * 16 + g + half * 8;
            int gr = mblk * BM + lr;
            bool valid = (gr < M);
            size_t row = (size_t)e * NN + gr;
            float ssq = 0.f;
#pragma unroll
            for (int nt = 0; nt < 4; nt++) {
                int col = n0 + wn * 32 + nt * 8 + tig * 2;
                float v0 = fsilu(accg[mt][nt][half*2+0]) * accu[mt][nt][half*2+0];
                float v1 = fsilu(accg[mt][nt][half*2+1]) * accu[mt][nt][half*2+1];
                ssq = fmaf(v0, v0, fmaf(v1, v1, ssq));
                if (valid)
                    g_aF[row * (HH/2) + (col >> 1)] = pack_h2(v0, v1);
            }
            // reduce over tig (lanes g*4+{0..3} share the same row)
            ssq += __shfl_xor_sync(~0u, ssq, 1);
            ssq += __shfl_xor_sync(~0u, ssq, 2);
            if (valid && tig == 0)
                atomicAdd(&g_ssq[row], ssq);
        }
    }
}

// ---------------- MoE down-GEMM, 3-stage: Dn = rs * (v @ Wd') ----------
__global__ __launch_bounds__(256, 2)
void gemm_dn(const u32* __restrict__ A, const u32* __restrict__ B1,
             float* __restrict__ Cf, int Ncols, int K)
{
    extern __shared__ u32 sm[];

    int e = blockIdx.z;
    int M = g_cnt[e];
    int mblk = blockIdx.y;
    if (mblk * BM >= M) return;
    int nblk = blockIdx.x;
    int K2 = K / 2;

    const u32* Bp = B1 + (size_t)e * Ncols * K2;
    int n0 = nblk * BN;
    int tid = threadIdx.x;

    int crow = tid >> 1;
    int cseg = (tid & 1) * 8;
    int gr0 = mblk * BM + crow;
    int asz = (gr0 < M) ? 16 : 0;
    size_t abase = ((size_t)e * NN + (gr0 < M ? gr0 : 0)) * K2 + cseg;
    size_t bbase = (size_t)(n0 + crow) * K2 + cseg;

    int wid = tid >> 5, lane = tid & 31;
    int g = lane >> 2, tig = lane & 3;
    int wm = wid >> 2, wn = wid & 3;

    u32 aoffL = (u32)((wm * 64 + (lane & 15)) * STR + (lane >> 4) * 4);
    u32 boffL = (u32)((wn * 32 + ((lane >> 4) << 3) + (lane & 7)) * STR + ((lane >> 3) & 1) * 4);

    float acc[4][4][4];
#pragma unroll
    for (int i = 0; i < 4; i++)
#pragma unroll
        for (int j = 0; j < 4; j++)
#pragma unroll
            for (int k = 0; k < 4; k++) acc[i][j][k] = 0.f;

    int KT = K2 / KP;
    u32 sdst = crow * STR + cseg;

    auto load_stage = [&](int kt, int st) {
        u32* s = sm + st * 2 * ABUF;
        size_t ao = abase + (size_t)kt * KP;
        size_t bo = bbase + (size_t)kt * KP;
        cp_async16z(s + 0*ABUF + sdst,     A + ao,      asz);
        cp_async16z(s + 0*ABUF + sdst + 4, A + ao + 4,  asz);
        cp_async16z(s + 1*ABUF + sdst,     Bp + bo,     16);
        cp_async16z(s + 1*ABUF + sdst + 4, Bp + bo + 4, 16);
        cp_commit();
    };

    load_stage(0, 0);
    load_stage(1, 1);

    for (int kt = 0; kt < KT; kt++) {
        if (kt == KT - 1) cp_wait<0>(); else cp_wait<1>();
        __syncthreads();
        if (kt + 2 < KT) load_stage(kt + 2, (kt + 2) % 3);

        int buf = kt % 3;
        u32 aA = (u32)__cvta_generic_to_shared(sm + buf * 2 * ABUF);
        u32 aB = aA + ABUF * 4;

#pragma unroll
        for (int ks = 0; ks < 2; ks++) {
            int kb = ks * 8;
            u32 ah[4][4];
#pragma unroll
            for (int mt = 0; mt < 4; mt++) {
                u32 off = (aoffL + mt * 16 * STR + kb) * 4;
                ldsm_x4(ah[mt][0], ah[mt][1], ah[mt][2], ah[mt][3], aA + off);
            }
            u32 bh[4][2];
#pragma unroll
            for (int np = 0; np < 2; np++) {
                u32 off = (boffL + np * 16 * STR + kb) * 4;
                ldsm_x4(bh[2*np][0], bh[2*np][1], bh[2*np+1][0], bh[2*np+1][1], aB + off);
            }
#pragma unroll
            for (int mt = 0; mt < 4; mt++)
#pragma unroll
                for (int nt = 0; nt < 4; nt++)
                    mma_f16(acc[mt][nt], ah[mt], bh[nt]);
        }
    }

#pragma unroll
    for (int mt = 0; mt < 4; mt++) {
#pragma unroll
        for (int half = 0; half < 2; half++) {
            int lr = wm * 64 + mt * 16 + g + half * 8;
            int gr = mblk * BM + lr;
            if (gr >= M) continue;
            size_t row = (size_t)e * NN + gr;
            float rs = g_cw[row] * rsqrtf(g_ssq[row] / (float)HH + 1e-6f);
            float* orow = Cf + row * Ncols;
#pragma unroll
            for (int nt = 0; nt < 4; nt++) {
                int col = n0 + wn * 32 + nt * 8 + tig * 2;
                *(float2*)(orow + col) =
                    make_float2(rs * acc[mt][nt][half*2+0], rs * acc[mt][nt][half*2+1]);
            }
        }
    }
}

// ---------------- small projections: Bm, Cm (from x) ----------------
__global__ __launch_bounds__(128)
void proj_small(const float* __restrict__ x, const float* __restrict__ WB,
                const float* __restrict__ WC)
{
    int n = blockIdx.x;
    __shared__ float xs[DD];
    const float* xr = x + (size_t)n * DD;
    for (int i = threadIdx.x; i < DD; i += 128) xs[i] = xr[i];
    __syncthreads();
    int warp = threadIdx.x >> 5, lane = threadIdx.x & 31;
    for (int c = warp; c < 32; c += 4) {
        const float* W; int col; float* out;
        if (c < 16) { W = WB; col = c;      out = g_Bm + (size_t)n * SS + col; }
        else        { W = WC; col = c - 16; out = g_Cm + (size_t)n * SS + col; }
        float s = 0.f;
        for (int k = lane; k < DD; k += 32)
            s = fmaf(xs[k], W[(size_t)k * SS + col], s);
        s += __shfl_xor_sync(~0u, s, 16);
        s += __shfl_xor_sync(~0u, s, 8);
        s += __shfl_xor_sync(~0u, s, 4);
        s += __shfl_xor_sync(~0u, s, 2);
        s += __shfl_xor_sync(~0u, s, 1);
        if (lane == 0) *out = s;
    }
}

// ---------------- selective scan: hoisted coefficients, single wave ------------
__global__ __launch_bounds__(256)
void scan_kernel(const float* __restrict__ x, const float* __restrict__ A_log,
                 const float* __restrict__ D_param)
{
    int b = blockIdx.x >> 6;
    int dchunk = blockIdx.x & 63;
    int dl = threadIdx.x >> 4;      // d-local 0..15
    int s  = threadIdx.x & 15;      // state index
    int d = dchunk * 16 + dl;

    float A_ds = -__expf(A_log[d * SS + s]);

    __shared__ float sx[16][16], sd[16][16];
    __shared__ float sB[16][17], sC[16][17];
    __shared__ float sp[16 * 272];  // [q][s*17 + dl]
    __shared__ float sDp[16];

    int tt = threadIdx.x >> 4;
    int cc = threadIdx.x & 15;
    const int base_bt = b * LL;

    if (threadIdx.x < 16) sDp[threadIdx.x] = D_param[dchunk * 16 + threadIdx.x];

    size_t xoff = ((size_t)(base_bt + tt)) * DD + dchunk * 16 + cc;
    float rx = x[xoff];
    float rd = g_delta[xoff];
    size_t boff = ((size_t)(base_bt + tt)) * SS + cc;
    float rB = g_Bm[boff];
    float rC = g_Cm[boff];

    float h = 0.f;
    for (int t0 = 0; t0 < LL; t0 += 16) {
        __syncthreads();
        sx[tt][cc] = rx; sd[tt][cc] = rd; sB[tt][cc] = rB; sC[tt][cc] = rC;
        __syncthreads();
        if (t0 + 16 < LL) {
            size_t xo = ((size_t)(base_bt + t0 + 16 + tt)) * DD + dchunk * 16 + cc;
            rx = x[xo]; rd = g_delta[xo];
            size_t bo = ((size_t)(base_bt + t0 + 16 + tt)) * SS + cc;
            rB = g_Bm[bo]; rC = g_Cm[bo];
        }
        float av[16], bx[16];
#pragma unroll
        for (int q = 0; q < 16; q++) {
            float dv = sd[q][dl];
            av[q] = __expf(fminf(dv * A_ds, 10.f));
            bx[q] = fminf(fmaxf(dv * sB[q][s], -10.f), 10.f) * sx[q][dl];
        }
        float p[16];
#pragma unroll
        for (int q = 0; q < 16; q++) {
            h = fminf(fmaxf(fmaf(av[q], h, bx[q]), -10000.f), 10000.f);
            p[q] = h * sC[q][s];
        }
#pragma unroll
        for (int q = 0; q < 16; q++)
            sp[q * 272 + s * 17 + dl] = p[q];
        __syncthreads();
        float ysum = 0.f;
#pragma unroll
        for (int s2 = 0; s2 < 16; s2++)
            ysum += sp[tt * 272 + s2 * 17 + cc];
        float y = fmaf(sx[tt][cc], sDp[cc], ysum);
        size_t yo = ((size_t)(base_bt + t0 + tt)) * DD + dchunk * 16 + cc;
        g_ssm[yo] = y;
        float yn = __shfl_down_sync(~0u, y, 1);
        if (!(cc & 1)) {
            float ya = fminf(fmaxf(y,  -60000.f), 60000.f);
            float yb = fminf(fmaxf(yn, -60000.f), 60000.f);
            size_t po = ((size_t)(base_bt + t0 + tt)) * (DD/2) + dchunk * 8 + (cc >> 1);
            g_sF[po] = pack_h2(ya, yb);
        }
    }
}

// ---------------- router on SSM output: softmax, top-2, expert lists ----------
__global__ __launch_bounds__(128)
void router_kernel(const float* __restrict__ WR)
{
    int n = blockIdx.x;
    __shared__ float xs[DD];
    __shared__ float logits[EE];
    const float* xr = g_ssm + (size_t)n * DD;
    for (int i = threadIdx.x; i < DD; i += 128) xs[i] = xr[i];
    __syncthreads();
    int warp = threadIdx.x >> 5, lane = threadIdx.x & 31;
    {
        float s = 0.f;
        for (int k = lane; k < DD; k += 32)
            s = fmaf(xs[k], WR[(size_t)k * EE + warp], s);
        s += __shfl_xor_sync(~0u, s, 16);
        s += __shfl_xor_sync(~0u, s, 8);
        s += __shfl_xor_sync(~0u, s, 4);
        s += __shfl_xor_sync(~0u, s, 2);
        s += __shfl_xor_sync(~0u, s, 1);
        if (lane == 0) logits[warp] = s;
    }
    __syncthreads();
    if (threadIdx.x == 0) {
        float l[4] = {logits[0], logits[1], logits[2], logits[3]};
        float m = fmaxf(fmaxf(l[0], l[1]), fmaxf(l[2], l[3]));
        float e[4], sum = 0.f;
#pragma unroll
        for (int i = 0; i < 4; i++) { e[i] = __expf(l[i] - m); sum += e[i]; }
        float p[4];
#pragma unroll
        for (int i = 0; i < 4; i++) p[i] = e[i] / sum;
        int i0 = 0;
#pragma unroll
        for (int i = 1; i < 4; i++) if (p[i] > p[i0]) i0 = i;
        int i1 = -1;
#pragma unroll
        for (int i = 0; i < 4; i++) {
            if (i == i0) continue;
            if (i1 < 0 || p[i] > p[i1]) i1 = i;
        }
        float w0 = p[i0], w1 = p[i1];
        float sw = w0 + w1 + 1e-9f;
        w0 /= sw; w1 /= sw;
        int pos = atomicAdd(&g_cnt[i0], 1);
        g_list[i0*NN + pos] = n; g_cw[i0*NN + pos] = w0;
        g_loc[n] = i0 * NN + pos;
        pos = atomicAdd(&g_cnt[i1], 1);
        g_list[i1*NN + pos] = n; g_cw[i1*NN + pos] = w1;
        g_loc[NN + n] = i1 * NN + pos;
    }
}

// ---------------- final rmsnorm over (ssm + Dn[loc0] + Dn[loc1]) --------------
__global__ __launch_bounds__(256)
void final_norm(const float* __restrict__ norm_w, float* __restrict__ out)
{
    int n = blockIdx.x;
    __shared__ float red[8];
    __shared__ float buf[DD];
    int l0 = g_loc[n], l1 = g_loc[NN + n];
    const float* r0 = g_Dn + (size_t)l0 * DD;
    const float* r1 = g_Dn + (size_t)l1 * DD;
    const float* rs = g_ssm + (size_t)n * DD;
    float ss = 0.f;
    for (int j = threadIdx.x; j < DD; j += 256) {
        float v = rs[j] + r0[j] + r1[j];
        buf[j] = v;
        ss = fmaf(v, v, ss);
    }
    ss += __shfl_xor_sync(~0u, ss, 16);
    ss += __shfl_xor_sync(~0u, ss, 8);
    ss += __shfl_xor_sync(~0u, ss, 4);
    ss += __shfl_xor_sync(~0u, ss, 2);
    ss += __shfl_xor_sync(~0u, ss, 1);
    if ((threadIdx.x & 31) == 0) red[threadIdx.x >> 5] = ss;
    __syncthreads();
    if (threadIdx.x < 32) {
        float v = (threadIdx.x < 8) ? red[threadIdx.x] : 0.f;
        v += __shfl_xor_sync(~0u, v, 4);
        v += __shfl_xor_sync(~0u, v, 2);
        v += __shfl_xor_sync(~0u, v, 1);
        if (threadIdx.x == 0) red[0] = v;
    }
    __syncthreads();
    float inv = rsqrtf(red[0] / (float)DD + 1e-6f);
    for (int j = threadIdx.x; j < DD; j += 256)
        out[(size_t)n * DD + j] = norm_w[j] * buf[j] * inv;
}

// ---------------- launch ----------------
extern "C" void kernel_launch(void* const* d_in, const int* in_sizes, int n_in,
                              void* d_out, int out_size)
{
    const float* x        = (const float*)d_in[0];
    const float* A_log    = (const float*)d_in[1];
    const float* D_param  = (const float*)d_in[2];
    const float* W_delta  = (const float*)d_in[3];
    const float* b_delta  = (const float*)d_in[4];
    const float* W_B      = (const float*)d_in[5];
    const float* W_C      = (const float*)d_in[6];
    const float* W_router = (const float*)d_in[7];
    const float* Wg       = (const float*)d_in[8];
    const float* Wu       = (const float*)d_in[9];
    const float* Wd       = (const float*)d_in[10];
    const float* wn_exp   = (const float*)d_in[11];
    const float* norm_w   = (const float*)d_in[12];
    float* out = (float*)d_out;

    float *p_delta, *p_Dn;
    u32 *p_xHi, *p_xLo, *p_sF, *p_aF;
    u32 *p_WdHi, *p_WdLo, *p_WgF, *p_WuF, *p_WnF;
    cudaGetSymbolAddress((void**)&p_delta, g_delta);
    cudaGetSymbolAddress((void**)&p_Dn,    g_Dn);
    cudaGetSymbolAddress((void**)&p_xHi,   g_xHi);
    cudaGetSymbolAddress((void**)&p_xLo,   g_xLo);
    cudaGetSymbolAddress((void**)&p_sF,    g_sF);
    cudaGetSymbolAddress((void**)&p_aF,    g_aF);
    cudaGetSymbolAddress((void**)&p_WdHi,  g_WdHi);
    cudaGetSymbolAddress((void**)&p_WdLo,  g_WdLo);
    cudaGetSymbolAddress((void**)&p_WgF,   g_WgF);
    cudaGetSymbolAddress((void**)&p_WuF,   g_WuF);
    cudaGetSymbolAddress((void**)&p_WnF,   g_WnF);

    cudaFuncSetAttribute(gemm_bf, cudaFuncAttributeMaxDynamicSharedMemorySize, GEMM_SMEM_BYTES);
    cudaFuncSetAttribute(gemm_up, cudaFuncAttributeMaxDynamicSharedMemorySize, GEMMH_SMEM_BYTES);
    cudaFuncSetAttribute(gemm_dn, cudaFuncAttributeMaxDynamicSharedMemorySize, GEMMH_SMEM_BYTES);

    zero_init<<<(EE * NN + 255) / 256, 256>>>();

    // operand pre-conversion
    {
        int n2 = NN * DD / 2;
        split_x_kernel<<<(n2 + 255) / 256, 256>>>(x, p_xHi, p_xLo, n2);
    }
    {
        dim3 blk(32, 8);
        dim3 gWdel(DD/2/32, DD/32, 1);
        split_w_kernel<<<gWdel, blk>>>(W_delta, p_WdHi, p_WdLo, DD, DD);
        dim3 gUp(DD/2/32, HH/32, EE);
        split_w_h_kernel<<<gUp, blk>>>(Wg, p_WgF, DD, HH, nullptr);
        split_w_h_kernel<<<gUp, blk>>>(Wu, p_WuF, DD, HH, nullptr);
        dim3 gDn(HH/2/32, DD/32, EE);
        split_w_h_kernel<<<gDn, blk>>>(Wd, p_WnF, HH, DD, wn_exp);  // folds wn
    }

    // delta = softplus(x @ W_delta + b)   [bf16x2 3-pass, 3-stage]
    {
        dim3 grid(DD / BN, NN / BM);
        gemm_bf<<<grid, 256, GEMM_SMEM_BYTES>>>(
            p_xHi, p_xLo, p_WdHi, p_WdLo, p_delta, b_delta, NN, DD, DD);
    }

    // Bm, Cm from x
    proj_small<<<NN, 128>>>(x, W_B, W_C);

    // selective scan -> g_ssm / fp16 ssm
    scan_kernel<<<BB * (DD / 16), 256>>>(x, A_log, D_param);

    // router on SSM output
    router_kernel<<<NN, 128>>>(W_router);

    // MoE: fused up-GEMM (v = silu(G)*U directly, + row ssq)
    gemm_up<<<dim3(HH / 64, NN / BM, EE), 256, GEMMH_SMEM_BYTES>>>(
        p_sF, p_WgF, p_WuF);
    // down-GEMM with rs applied in epilogue
    gemm_dn<<<dim3(DD / BN, NN / BM, EE), 256, GEMMH_SMEM_BYTES>>>(
        p_aF, p_WnF, p_Dn, DD, HH);

    // out = rmsnorm(ssm + Dn[loc0] + Dn[loc1], norm_w)
    final_norm<<<NN, 256>>>(norm_w, out);
}